// round 4
// baseline (speedup 1.0000x reference)
#include <cuda_runtime.h>
#include <cuda_bf16.h>
#include <math.h>
#include <stdint.h>

#define NB    8
#define C     192
#define C2    384
#define C4    768
#define HEADS 4
#define HD    48
#define HW    128
#define NPIX  16384
#define GK    192
#define PP    132            // smem row pitch (floats): 16B-aligned, conflict-benign

// ---------------- scratch (static device memory) ----------------
__device__ float g_avg[NB*C];
__device__ float g_mx [NB*C];
__device__ float g_cg [NB*C];
__device__ float g_sp [NB*2*NPIX];
__device__ float g_sg [NB*NPIX];
__device__ float g_qkv [(size_t)NB*C4*NPIX];   // 402 MB
__device__ float g_inq [NB*C];
__device__ float g_ink [NB*C];
__device__ float g_ssqp[(size_t)HW*NB*C2];     // per-row ssq partials
__device__ float g_spart[(size_t)HW*NB*HEADS*HD*HD];  // per-row qk^T partials (37.7MB)
__device__ float g_attn [(size_t)NB*HEADS*HD*HD];
__device__ float g_outg [(size_t)NB*C*NPIX];   // 100 MB

__device__ __forceinline__ float sigmoidf_(float x){ return 1.f/(1.f+expf(-x)); }

// 3x3 depthwise tap (pad 1) for channel image `in` at (y,p)
__device__ __forceinline__ float dw3x3(const float* __restrict__ in,
                                       const float* __restrict__ w, int y, int p){
    float a = 0.f;
    #pragma unroll
    for (int dy=0; dy<3; dy++){
        int yy = y+dy-1;
        if ((unsigned)yy < 128u){
            const float* row = in + yy*HW;
            #pragma unroll
            for (int dx=0; dx<3; dx++){
                int xc = p+dx-1;
                if ((unsigned)xc < 128u) a += row[xc]*w[dy*3+dx];
            }
        }
    }
    return a;
}

// ---------------- K1: per-(b,c) mean & max over pixels ----------------
__global__ void k_chan_pool(const float* __restrict__ x){
    int bc = blockIdx.x;
    const float4* px = (const float4*)(x + (size_t)bc*NPIX);
    int t = threadIdx.x;
    float s = 0.f, m = -1e30f;
    for (int i = t; i < NPIX/4; i += 256){
        float4 v = px[i];
        s += v.x+v.y+v.z+v.w;
        m = fmaxf(m, fmaxf(fmaxf(v.x,v.y), fmaxf(v.z,v.w)));
    }
    __shared__ float ss[256], sm[256];
    ss[t]=s; sm[t]=m; __syncthreads();
    for (int o=128;o>0;o>>=1){
        if (t<o){ ss[t]+=ss[t+o]; sm[t]=fmaxf(sm[t],sm[t+o]); }
        __syncthreads();
    }
    if (t==0){ g_avg[bc]=ss[0]*(1.f/NPIX); g_mx[bc]=sm[0]; }
}

// ---------------- K2: SE channel gate MLP ----------------
__global__ void k_chan_gate(const float* __restrict__ w1, const float* __restrict__ w2){
    int b = blockIdx.x, t = threadIdx.x;     // 192 threads
    __shared__ float pool[C2], sq[48];
    pool[t]     = g_avg[b*C+t];
    pool[C+t]   = g_mx [b*C+t];
    __syncthreads();
    if (t < 48){
        float a = 0.f;
        #pragma unroll 8
        for (int c=0;c<C2;c++) a += w1[t*C2+c]*pool[c];
        sq[t] = fmaxf(a, 0.f);
    }
    __syncthreads();
    float a = 0.f;
    #pragma unroll
    for (int s=0;s<48;s++) a += w2[t*48+s]*sq[s];
    g_cg[b*C+t] = sigmoidf_(a);
}

// ---------------- K3: per-pixel mean & max over channels ----------------
__global__ void k_spatial_stats(const float* __restrict__ x){
    int idx = blockIdx.x*256 + threadIdx.x;
    int b = idx >> 14, p = idx & (NPIX-1);
    const float* px = x + (size_t)b*C*NPIX + p;
    float s = 0.f, m = -1e30f;
    #pragma unroll 4
    for (int c=0;c<C;c++){ float v = px[(size_t)c*NPIX]; s += v; m = fmaxf(m, v); }
    g_sp[(size_t)b*2*NPIX + p]        = s*(1.f/C);
    g_sp[(size_t)b*2*NPIX + NPIX + p] = m;
}

// ---------------- K4: 7x7 spatial conv + sigmoid ----------------
__global__ void k_spatial_conv(const float* __restrict__ ws){
    int idx = blockIdx.x*256 + threadIdx.x;
    int b = idx >> 14, p = idx & (NPIX-1);
    int y = p >> 7, xx = p & 127;
    float acc = 0.f;
    #pragma unroll
    for (int ch=0; ch<2; ch++){
        const float* base = g_sp + (size_t)b*2*NPIX + (size_t)ch*NPIX;
        #pragma unroll
        for (int dy=-3; dy<=3; dy++){
            int yy = y+dy;
            if ((unsigned)yy < 128u){
                const float* row = base + yy*HW;
                #pragma unroll
                for (int dx=-3; dx<=3; dx++){
                    int xc = xx+dx;
                    if ((unsigned)xc < 128u)
                        acc += row[xc]*__ldg(&ws[ch*49 + (dy+3)*7 + (dx+3)]);
                }
            }
        }
    }
    g_sg[(size_t)b*NPIX + p] = sigmoidf_(acc);
}

// ================= split-bf16 HMMA GEMM =================
#define KC     48
#define APITCH 56
#define SM_AH  0
#define SM_AL  14336
#define SM_BH  28672
#define SM_BL  43008
#define SMEM_HMMA 57344

__device__ __forceinline__ void mma16816(float* c, uint32_t a0, uint32_t a1,
                                         uint32_t a2, uint32_t a3,
                                         uint32_t b0, uint32_t b1){
    asm volatile(
      "mma.sync.aligned.m16n8k16.row.col.f32.bf16.bf16.f32 "
      "{%0,%1,%2,%3},{%4,%5,%6,%7},{%8,%9},{%0,%1,%2,%3};"
      : "+f"(c[0]), "+f"(c[1]), "+f"(c[2]), "+f"(c[3])
      : "r"(a0), "r"(a1), "r"(a2), "r"(a3), "r"(b0), "r"(b1));
}
__device__ __forceinline__ uint32_t pack_hi(float v0, float v1){
    __nv_bfloat162 h = __floats2bfloat162_rn(v0, v1);
    return *(uint32_t*)&h;
}

__global__ __launch_bounds__(256)
void k_hmma(const float* __restrict__ A,     // [M,GK] row-major (batch-shared)
            const float* __restrict__ gate,  // per-batch [GK] or null
            const float* __restrict__ B,     // per-batch [GK,NPIX]
            long sB,
            float* __restrict__ Cout, long sC,
            const float* __restrict__ S,     // per-batch [NPIX] or null
            int M){
    extern __shared__ __align__(16) char smem[];
    uint32_t* Ah = (uint32_t*)(smem + SM_AH);
    uint32_t* Al = (uint32_t*)(smem + SM_AL);
    uint32_t* Bh = (uint32_t*)(smem + SM_BH);
    uint32_t* Bl = (uint32_t*)(smem + SM_BL);

    int b  = blockIdx.z;
    int bm = blockIdx.y*128, bn = blockIdx.x*128;
    B    += (size_t)b*sB;
    Cout += (size_t)b*sC;
    const float* gt = gate ? gate + b*C : nullptr;
    const float* Sp = S    ? S + (size_t)b*NPIX : nullptr;

    int tid = threadIdx.x, wid = tid>>5, lid = tid&31;
    int wr = wid>>2, wc = wid&3;
    int gi = lid>>2, li4 = lid&3;

    float acc[4][4][4];
    #pragma unroll
    for (int i=0;i<4;i++)
        #pragma unroll
        for (int j=0;j<4;j++)
            #pragma unroll
            for (int r=0;r<4;r++) acc[i][j][r]=0.f;

    for (int c0=0; c0<GK; c0+=KC){
        for (int q=tid; q<128*(KC/4); q+=256){
            int r  = q/(KC/4);
            int kq = (q - r*(KC/4))*4;
            int m  = bm + r; if (m >= M) m = M-1;
            float4 v = *(const float4*)&A[(size_t)m*GK + c0 + kq];
            if (gt){
                v.x *= gt[c0+kq]; v.y *= gt[c0+kq+1];
                v.z *= gt[c0+kq+2]; v.w *= gt[c0+kq+3];
            }
            uint32_t h0 = pack_hi(v.x, v.y), h1 = pack_hi(v.z, v.w);
            __nv_bfloat162 hh0 = *(__nv_bfloat162*)&h0;
            __nv_bfloat162 hh1 = *(__nv_bfloat162*)&h1;
            uint32_t l0 = pack_hi(v.x - __bfloat162float(hh0.x), v.y - __bfloat162float(hh0.y));
            uint32_t l1 = pack_hi(v.z - __bfloat162float(hh1.x), v.w - __bfloat162float(hh1.y));
            int o = (r*APITCH + kq)>>1;
            Ah[o]=h0; Ah[o+1]=h1; Al[o]=l0; Al[o+1]=l1;
        }
        for (int q=tid; q<128*(KC/4); q+=256){
            int n  = q & 127;
            int kq = (q >> 7)*4;
            const float* bp = B + (size_t)(c0+kq)*NPIX + bn + n;
            float v0 = bp[0], v1 = bp[NPIX], v2 = bp[2*NPIX], v3 = bp[3*NPIX];
            uint32_t h0 = pack_hi(v0, v1), h1 = pack_hi(v2, v3);
            __nv_bfloat162 hh0 = *(__nv_bfloat162*)&h0;
            __nv_bfloat162 hh1 = *(__nv_bfloat162*)&h1;
            uint32_t l0 = pack_hi(v0 - __bfloat162float(hh0.x), v1 - __bfloat162float(hh0.y));
            uint32_t l1 = pack_hi(v2 - __bfloat162float(hh1.x), v3 - __bfloat162float(hh1.y));
            int o = (n*APITCH + kq)>>1;
            Bh[o]=h0; Bh[o+1]=h1; Bl[o]=l0; Bl[o+1]=l1;
        }
        __syncthreads();

        const uint32_t* Ab = Ah + ((wr*64 + gi)*APITCH>>1) + li4;
        const uint32_t* Lb = Al + ((wr*64 + gi)*APITCH>>1) + li4;
        const uint32_t* Bb = Bh + ((wc*32 + gi)*APITCH>>1) + li4;
        const uint32_t* Mb = Bl + ((wc*32 + gi)*APITCH>>1) + li4;

        #pragma unroll
        for (int ks=0; ks<KC/16; ks++){
            int ko = ks*8;
            uint32_t bh[4][2], af[4][4];
            #pragma unroll
            for (int ni=0; ni<4; ni++){
                bh[ni][0] = Bb[ni*8*(APITCH>>1) + ko];
                bh[ni][1] = Bb[ni*8*(APITCH>>1) + ko + 4];
            }
            #pragma unroll
            for (int mi=0; mi<4; mi++){
                const uint32_t* ap = Ab + mi*16*(APITCH>>1) + ko;
                af[mi][0]=ap[0]; af[mi][1]=ap[8*(APITCH>>1)];
                af[mi][2]=ap[4]; af[mi][3]=ap[8*(APITCH>>1)+4];
            }
            #pragma unroll
            for (int mi=0; mi<4; mi++)
                #pragma unroll
                for (int ni=0; ni<4; ni++)
                    mma16816(acc[mi][ni], af[mi][0],af[mi][1],af[mi][2],af[mi][3],
                             bh[ni][0], bh[ni][1]);
            #pragma unroll
            for (int ni=0; ni<4; ni++){
                uint32_t b0 = Mb[ni*8*(APITCH>>1) + ko];
                uint32_t b1 = Mb[ni*8*(APITCH>>1) + ko + 4];
                #pragma unroll
                for (int mi=0; mi<4; mi++)
                    mma16816(acc[mi][ni], af[mi][0],af[mi][1],af[mi][2],af[mi][3], b0, b1);
            }
            #pragma unroll
            for (int mi=0; mi<4; mi++){
                const uint32_t* ap = Lb + mi*16*(APITCH>>1) + ko;
                uint32_t a0=ap[0], a1=ap[8*(APITCH>>1)], a2=ap[4], a3=ap[8*(APITCH>>1)+4];
                #pragma unroll
                for (int ni=0; ni<4; ni++)
                    mma16816(acc[mi][ni], a0,a1,a2,a3, bh[ni][0], bh[ni][1]);
            }
        }
        __syncthreads();
    }

    #pragma unroll
    for (int ni=0; ni<4; ni++){
        int n = bn + wc*32 + ni*8 + li4*2;
        float2 sv = Sp ? *(const float2*)&Sp[n] : make_float2(1.f,1.f);
        #pragma unroll
        for (int mi=0; mi<4; mi++){
            int m0 = bm + wr*64 + mi*16 + gi;
            if (m0 < M){
                float2 p = make_float2(acc[mi][ni][0]*sv.x, acc[mi][ni][1]*sv.y);
                *(float2*)&Cout[(size_t)m0*NPIX + n] = p;
            }
            int m1 = m0 + 8;
            if (m1 < M){
                float2 p = make_float2(acc[mi][ni][2]*sv.x, acc[mi][ni][3]*sv.y);
                *(float2*)&Cout[(size_t)m1*NPIX + n] = p;
            }
        }
    }
}

// ---------------- K5: fused dw(q,k) + ssq partials + qk^T partials ----------------
// block = (y, b). smem: qs[48][PP], ks[48][PP], partial[4*2304]
#define SMEM_DWQK ((2*48*PP + 4*2304)*4)
__global__ __launch_bounds__(256)
void k_dwqk(const float* __restrict__ wd){
    extern __shared__ float sm[];
    float* qs = sm;
    float* ks = sm + 48*PP;
    float* partial = sm + 2*48*PP;
    int y = blockIdx.x, b = blockIdx.y;
    int tid = threadIdx.x;
    int pq = tid>>6, t6 = tid&63, ti = t6>>3, tj = t6&7;

    for (int h=0; h<HEADS; h++){
        int cq0 = h*HD;
        int ck0 = 2*C + h*HD;
        // dw fill
        for (int e=tid; e<48*128; e+=256){
            int c = e>>7, p = e&127;
            const float* inq = g_qkv + ((size_t)b*C4 + cq0 + c)*NPIX;
            const float* ink = g_qkv + ((size_t)b*C4 + ck0 + c)*NPIX;
            qs[c*PP+p] = dw3x3(inq, wd + (cq0+c)*9, y, p);
            ks[c*PP+p] = dw3x3(ink, wd + (ck0+c)*9, y, p);
        }
        __syncthreads();
        // ssq partials (per-row, deterministic)
        if (tid < 96){
            int which = tid>=48 ? 1 : 0, c = tid - which*48;
            const float* src = which ? ks : qs;
            float s = 0.f;
            #pragma unroll 4
            for (int p=0;p<128;p++){ float v = src[c*PP+p]; s += v*v; }
            g_ssqp[(size_t)y*(NB*C2) + b*C2 + which*C + h*HD + c] = s;
        }
        // qk^T partial: 6x6 per thread over a 32-px slice
        {
            float a[6][6];
            #pragma unroll
            for (int r=0;r<6;r++)
                #pragma unroll
                for (int s=0;s<6;s++) a[r][s]=0.f;
            int p0 = pq*32;
            for (int p=0;p<32;p++){
                float qv[6], kv[6];
                #pragma unroll
                for (int r=0;r<6;r++) qv[r] = qs[(ti*6+r)*PP + p0 + p];
                #pragma unroll
                for (int s=0;s<6;s++) kv[s] = ks[(tj*6+s)*PP + p0 + p];
                #pragma unroll
                for (int r=0;r<6;r++)
                    #pragma unroll
                    for (int s=0;s<6;s++) a[r][s] += qv[r]*kv[s];
            }
            float* part = partial + pq*2304;
            #pragma unroll
            for (int r=0;r<6;r++)
                #pragma unroll
                for (int s=0;s<6;s++)
                    part[(ti*6+r)*48 + tj*6+s] = a[r][s];
        }
        __syncthreads();
        // combine 4 slices, write per-row partial
        size_t base = ((size_t)y*(NB*HEADS) + b*HEADS + h)*(HD*HD);
        for (int e=tid; e<2304; e+=256)
            g_spart[base + e] = partial[e] + partial[2304+e] + partial[4608+e] + partial[6912+e];
        __syncthreads();
    }
}

// ---------------- K6: combine ssq partials -> inverse norms ----------------
__global__ void k_cssq(){
    int t = blockIdx.x*256 + threadIdx.x;   // 0..3071
    if (t >= NB*C2) return;
    float s = 0.f;
    for (int y=0;y<HW;y++) s += g_ssqp[(size_t)y*(NB*C2) + t];
    float inv = 1.f/fmaxf(sqrtf(s), 1e-12f);
    int b = t/C2, r = t - b*C2;
    if (r < C) g_inq[b*C + r] = inv;
    else       g_ink[b*C + r - C] = inv;
}

// ---------------- K7: combine qk partials, scale, softmax ----------------
__global__ void k_softmax(const float* __restrict__ temp){
    int row = blockIdx.x;             // NB*HEADS*HD
    int bh = row / HD;
    int i  = row - bh*HD;
    int b = bh >> 2, hh = bh & 3;
    int j = threadIdx.x;              // 64
    float v = -1e30f;
    if (j < HD){
        float s = 0.f;
        for (int y=0; y<HW; y++)
            s += g_spart[((size_t)y*(NB*HEADS) + bh)*(HD*HD) + i*HD + j];
        v = s * __ldg(&temp[hh]) * g_inq[b*C + hh*HD + i] * g_ink[b*C + hh*HD + j];
    }
    __shared__ float sh[64];
    sh[j] = v; __syncthreads();
    for (int o=32;o>0;o>>=1){ if (j<o) sh[j]=fmaxf(sh[j],sh[j+o]); __syncthreads(); }
    float m = sh[0]; __syncthreads();
    float e = (j < HD) ? expf(v - m) : 0.f;
    sh[j] = e; __syncthreads();
    for (int o=32;o>0;o>>=1){ if (j<o) sh[j]+=sh[j+o]; __syncthreads(); }
    if (j < HD) g_attn[(size_t)bh*HD*HD + i*HD + j] = e / sh[0];
}

// ---------------- K8: fused dw(v,gate) + (attn@v)*sigmoid(gate) ----------------
// block = (y, b). smem: vs[48][PP], gs[48][PP], at[2304]
#define SMEM_DWVG ((2*48*PP + 2304)*4)
__global__ __launch_bounds__(256)
void k_dwvg(const float* __restrict__ wd, float* __restrict__ outp){
    extern __shared__ float sm[];
    float* vs = sm;
    float* gs = sm + 48*PP;
    float* at = sm + 2*48*PP;
    int y = blockIdx.x, b = blockIdx.y;
    int tid = threadIdx.x;
    int ig = tid>>5, pg = tid&31;     // 8 i-groups of 6, 32 p-groups of 4

    for (int h=0; h<HEADS; h++){
        int cg0 = C + h*HD;           // gate channels
        int cv0 = 3*C + h*HD;         // v channels
        for (int e=tid; e<2304; e+=256)
            at[e] = g_attn[((size_t)(b*HEADS+h))*(HD*HD) + e];
        for (int e=tid; e<48*128; e+=256){
            int c = e>>7, p = e&127;
            const float* ing = g_qkv + ((size_t)b*C4 + cg0 + c)*NPIX;
            const float* inv = g_qkv + ((size_t)b*C4 + cv0 + c)*NPIX;
            gs[c*PP+p] = dw3x3(ing, wd + (cg0+c)*9, y, p);
            vs[c*PP+p] = dw3x3(inv, wd + (cv0+c)*9, y, p);
        }
        __syncthreads();

        float acc[6][4];
        #pragma unroll
        for (int r=0;r<6;r++)
            #pragma unroll
            for (int q=0;q<4;q++) acc[r][q]=0.f;

        for (int j=0;j<HD;j++){
            float4 v4 = *(float4*)&vs[j*PP + pg*4];
            #pragma unroll
            for (int r=0;r<6;r++){
                float a = at[(ig*6+r)*HD + j];
                acc[r][0] += a*v4.x; acc[r][1] += a*v4.y;
                acc[r][2] += a*v4.z; acc[r][3] += a*v4.w;
            }
        }
        float* orow = outp + ((size_t)b*C + h*HD)*NPIX + y*HW;
        #pragma unroll
        for (int r=0;r<6;r++){
            int i = ig*6 + r;
            float4 g4 = *(float4*)&gs[i*PP + pg*4];
            float4 o;
            o.x = acc[r][0]*sigmoidf_(g4.x);
            o.y = acc[r][1]*sigmoidf_(g4.y);
            o.z = acc[r][2]*sigmoidf_(g4.z);
            o.w = acc[r][3]*sigmoidf_(g4.w);
            *(float4*)&orow[(size_t)i*NPIX + pg*4] = o;
        }
        __syncthreads();
    }
}

// ---------------- host ----------------
extern "C" void kernel_launch(void* const* d_in, const int* in_sizes, int n_in,
                              void* d_out, int out_size){
    const float* x      = (const float*)d_in[0];
    const float* w_fc1  = (const float*)d_in[1];
    const float* w_fc2  = (const float*)d_in[2];
    const float* w_sp   = (const float*)d_in[3];
    const float* w_qkv  = (const float*)d_in[4];
    const float* w_dw   = (const float*)d_in[5];
    const float* w_proj = (const float*)d_in[6];
    const float* temp   = (const float*)d_in[7];
    float* out = (float*)d_out;

    float *qkv, *outg, *cg, *sg;
    cudaGetSymbolAddress((void**)&qkv,  g_qkv);
    cudaGetSymbolAddress((void**)&outg, g_outg);
    cudaGetSymbolAddress((void**)&cg,   g_cg);
    cudaGetSymbolAddress((void**)&sg,   g_sg);

    cudaFuncSetAttribute(k_hmma,  cudaFuncAttributeMaxDynamicSharedMemorySize, SMEM_HMMA);
    cudaFuncSetAttribute(k_dwqk,  cudaFuncAttributeMaxDynamicSharedMemorySize, SMEM_DWQK);
    cudaFuncSetAttribute(k_dwvg,  cudaFuncAttributeMaxDynamicSharedMemorySize, SMEM_DWVG);

    k_chan_pool    <<<NB*C, 256>>>(x);
    k_chan_gate    <<<NB, 192>>>(w_fc1, w_fc2);
    k_spatial_stats<<<NB*NPIX/256, 256>>>(x);
    k_spatial_conv <<<NB*NPIX/256, 256>>>(w_sp);

    // qkv = sg(p) * ((w_qkv * cg) @ x) on tensor cores (split-bf16, 3 passes)
    k_hmma<<<dim3(NPIX/128, 6, NB), 256, SMEM_HMMA>>>(
        w_qkv, cg, x, (long)C*NPIX, qkv, (long)C4*NPIX, sg, C4);

    // fused: dw(q,k) + norms + qk^T partials
    k_dwqk<<<dim3(HW, NB), 256, SMEM_DWQK>>>(w_dw);
    k_cssq<<<(NB*C2+255)/256, 256>>>();
    k_softmax<<<NB*HEADS*HD, 64>>>(temp);

    // fused: dw(v,gate) + (attn@v)*sigmoid(gate) -> g_outg
    k_dwvg<<<dim3(HW, NB), 256, SMEM_DWVG>>>(w_dw, outg);

    // final projection straight into d_out
    k_hmma<<<dim3(NPIX/128, 2, NB), 256, SMEM_HMMA>>>(
        w_proj, nullptr, outg, (long)C*NPIX, out, (long)C*NPIX, nullptr, C);
}

// round 5
// speedup vs baseline: 1.4401x; 1.4401x over previous
#include <cuda_runtime.h>
#include <cuda_bf16.h>
#include <math.h>
#include <stdint.h>

#define NB    8
#define C     192
#define C2    384
#define C4    768
#define HEADS 4
#define HD    48
#define HW    128
#define NPIX  16384
#define GK    192
#define NSEG  16
#define SEGLEN (NPIX/NSEG)
#define NTILE 32              // x-stat tiles of 512 px

// ---------------- scratch (static device memory) ----------------
__device__ float g_cps[NB*NTILE*C];           // channel-sum partials
__device__ float g_cpm[NB*NTILE*C];           // channel-max partials
__device__ float g_cg [NB*C];
__device__ float g_sp [NB*2*NPIX];
__device__ float g_sg [NB*NPIX];
__device__ float g_qkv [(size_t)NB*C4*NPIX];  // 402 MB
__device__ float g_dw  [(size_t)NB*C4*NPIX];  // 402 MB
__device__ float g_ssqp[(size_t)NB*C2*HW];    // per-row ssq partials (q,k)
__device__ float g_inq [NB*C];
__device__ float g_ink [NB*C];
__device__ float g_spart[(size_t)NB*HEADS*NSEG*HD*HD];
__device__ float g_attn [(size_t)NB*HEADS*HD*HD];
__device__ float g_outg [(size_t)NB*C*NPIX];  // 100 MB

__device__ __forceinline__ float sigmoidf_(float x){ return 1.f/(1.f+expf(-x)); }

// ---------------- K1: ONE pass over x -> channel partials + pixel stats ----------------
// grid (NTILE, NB), 256 thr. Warp w handles channels [w*24, w*24+24) over 512 px.
__global__ __launch_bounds__(256)
void k_stats(const float* __restrict__ x){
    __shared__ float sps[8*512], spm[8*512];
    int tile = blockIdx.x, b = blockIdx.y;
    int tid = threadIdx.x, w = tid>>5, lane = tid&31;
    int p0 = tile*512;

    float ps[16], pm[16];
    #pragma unroll
    for (int i=0;i<16;i++){ ps[i]=0.f; pm[i]=-1e30f; }

    for (int ci=0; ci<24; ci++){
        int c = w*24 + ci;
        const float* row = x + ((size_t)b*C + c)*NPIX + p0;
        float cs = 0.f, cm = -1e30f;
        #pragma unroll
        for (int it=0; it<16; it++){
            float v = row[it*32 + lane];
            ps[it] += v; pm[it] = fmaxf(pm[it], v);
            cs += v;     cm = fmaxf(cm, v);
        }
        #pragma unroll
        for (int o=16;o;o>>=1){
            cs += __shfl_xor_sync(~0u, cs, o);
            cm = fmaxf(cm, __shfl_xor_sync(~0u, cm, o));
        }
        if (lane==0){
            g_cps[(b*NTILE + tile)*C + c] = cs;
            g_cpm[(b*NTILE + tile)*C + c] = cm;
        }
    }
    #pragma unroll
    for (int it=0; it<16; it++){
        sps[w*512 + it*32 + lane] = ps[it];
        spm[w*512 + it*32 + lane] = pm[it];
    }
    __syncthreads();
    for (int p=tid; p<512; p+=256){
        float s = 0.f, m = -1e30f;
        #pragma unroll
        for (int ww=0; ww<8; ww++){
            s += sps[ww*512+p];
            m = fmaxf(m, spm[ww*512+p]);
        }
        g_sp[(size_t)b*2*NPIX + p0 + p]        = s*(1.f/C);
        g_sp[(size_t)b*2*NPIX + NPIX + p0 + p] = m;
    }
}

// ---------------- K2: combine channel partials + SE gate MLP ----------------
__global__ void k_chan_gate(const float* __restrict__ w1, const float* __restrict__ w2){
    int b = blockIdx.x, t = threadIdx.x;     // 192 threads
    __shared__ float pool[C2], sq[48];
    {
        float s = 0.f, m = -1e30f;
        for (int tile=0; tile<NTILE; tile++){
            s += g_cps[(b*NTILE + tile)*C + t];
            m = fmaxf(m, g_cpm[(b*NTILE + tile)*C + t]);
        }
        pool[t]   = s*(1.f/NPIX);
        pool[C+t] = m;
    }
    __syncthreads();
    if (t < 48){
        float a = 0.f;
        #pragma unroll 8
        for (int c=0;c<C2;c++) a += w1[t*C2+c]*pool[c];
        sq[t] = fmaxf(a, 0.f);
    }
    __syncthreads();
    float a = 0.f;
    #pragma unroll
    for (int s=0;s<48;s++) a += w2[t*48+s]*sq[s];
    g_cg[b*C+t] = sigmoidf_(a);
}

// ---------------- K3: 7x7 spatial conv + sigmoid ----------------
__global__ void k_spatial_conv(const float* __restrict__ ws){
    int idx = blockIdx.x*256 + threadIdx.x;
    int b = idx >> 14, p = idx & (NPIX-1);
    int y = p >> 7, xx = p & 127;
    float acc = 0.f;
    #pragma unroll
    for (int ch=0; ch<2; ch++){
        const float* base = g_sp + (size_t)b*2*NPIX + (size_t)ch*NPIX;
        #pragma unroll
        for (int dy=-3; dy<=3; dy++){
            int yy = y+dy;
            if ((unsigned)yy < 128u){
                const float* row = base + yy*HW;
                #pragma unroll
                for (int dx=-3; dx<=3; dx++){
                    int xc = xx+dx;
                    if ((unsigned)xc < 128u)
                        acc += row[xc]*__ldg(&ws[ch*49 + (dy+3)*7 + (dx+3)]);
                }
            }
        }
    }
    g_sg[(size_t)b*NPIX + p] = sigmoidf_(acc);
}

// ================= split-bf16 HMMA GEMM =================
#define KC     48
#define APITCH 56
#define SM_AH  0
#define SM_AL  14336
#define SM_BH  28672
#define SM_BL  43008
#define SMEM_HMMA 57344

__device__ __forceinline__ void mma16816(float* c, uint32_t a0, uint32_t a1,
                                         uint32_t a2, uint32_t a3,
                                         uint32_t b0, uint32_t b1){
    asm volatile(
      "mma.sync.aligned.m16n8k16.row.col.f32.bf16.bf16.f32 "
      "{%0,%1,%2,%3},{%4,%5,%6,%7},{%8,%9},{%0,%1,%2,%3};"
      : "+f"(c[0]), "+f"(c[1]), "+f"(c[2]), "+f"(c[3])
      : "r"(a0), "r"(a1), "r"(a2), "r"(a3), "r"(b0), "r"(b1));
}
__device__ __forceinline__ uint32_t pack_hi(float v0, float v1){
    __nv_bfloat162 h = __floats2bfloat162_rn(v0, v1);
    return *(uint32_t*)&h;
}

__global__ __launch_bounds__(256)
void k_hmma(const float* __restrict__ A,     // [M,GK] row-major (batch-shared)
            const float* __restrict__ gate,  // per-batch [GK] or null
            const float* __restrict__ B,     // per-batch [GK,NPIX]
            long sB,
            float* __restrict__ Cout, long sC,
            const float* __restrict__ S,     // per-batch [NPIX] or null
            int M){
    extern __shared__ __align__(16) char smem[];
    uint32_t* Ah = (uint32_t*)(smem + SM_AH);
    uint32_t* Al = (uint32_t*)(smem + SM_AL);
    uint32_t* Bh = (uint32_t*)(smem + SM_BH);
    uint32_t* Bl = (uint32_t*)(smem + SM_BL);

    int b  = blockIdx.z;
    int bm = blockIdx.y*128, bn = blockIdx.x*128;
    B    += (size_t)b*sB;
    Cout += (size_t)b*sC;
    const float* gt = gate ? gate + b*C : nullptr;
    const float* Sp = S    ? S + (size_t)b*NPIX : nullptr;

    int tid = threadIdx.x, wid = tid>>5, lid = tid&31;
    int wr = wid>>2, wc = wid&3;
    int gi = lid>>2, li4 = lid&3;

    float acc[4][4][4];
    #pragma unroll
    for (int i=0;i<4;i++)
        #pragma unroll
        for (int j=0;j<4;j++)
            #pragma unroll
            for (int r=0;r<4;r++) acc[i][j][r]=0.f;

    for (int c0=0; c0<GK; c0+=KC){
        for (int q=tid; q<128*(KC/4); q+=256){
            int r  = q/(KC/4);
            int kq = (q - r*(KC/4))*4;
            int m  = bm + r; if (m >= M) m = M-1;
            float4 v = *(const float4*)&A[(size_t)m*GK + c0 + kq];
            if (gt){
                v.x *= gt[c0+kq]; v.y *= gt[c0+kq+1];
                v.z *= gt[c0+kq+2]; v.w *= gt[c0+kq+3];
            }
            uint32_t h0 = pack_hi(v.x, v.y), h1 = pack_hi(v.z, v.w);
            __nv_bfloat162 hh0 = *(__nv_bfloat162*)&h0;
            __nv_bfloat162 hh1 = *(__nv_bfloat162*)&h1;
            uint32_t l0 = pack_hi(v.x - __bfloat162float(hh0.x), v.y - __bfloat162float(hh0.y));
            uint32_t l1 = pack_hi(v.z - __bfloat162float(hh1.x), v.w - __bfloat162float(hh1.y));
            int o = (r*APITCH + kq)>>1;
            Ah[o]=h0; Ah[o+1]=h1; Al[o]=l0; Al[o+1]=l1;
        }
        for (int q=tid; q<128*(KC/4); q+=256){
            int n  = q & 127;
            int kq = (q >> 7)*4;
            const float* bp = B + (size_t)(c0+kq)*NPIX + bn + n;
            float v0 = bp[0], v1 = bp[NPIX], v2 = bp[2*NPIX], v3 = bp[3*NPIX];
            uint32_t h0 = pack_hi(v0, v1), h1 = pack_hi(v2, v3);
            __nv_bfloat162 hh0 = *(__nv_bfloat162*)&h0;
            __nv_bfloat162 hh1 = *(__nv_bfloat162*)&h1;
            uint32_t l0 = pack_hi(v0 - __bfloat162float(hh0.x), v1 - __bfloat162float(hh0.y));
            uint32_t l1 = pack_hi(v2 - __bfloat162float(hh1.x), v3 - __bfloat162float(hh1.y));
            int o = (n*APITCH + kq)>>1;
            Bh[o]=h0; Bh[o+1]=h1; Bl[o]=l0; Bl[o+1]=l1;
        }
        __syncthreads();

        const uint32_t* Ab = Ah + ((wr*64 + gi)*APITCH>>1) + li4;
        const uint32_t* Lb = Al + ((wr*64 + gi)*APITCH>>1) + li4;
        const uint32_t* Bb = Bh + ((wc*32 + gi)*APITCH>>1) + li4;
        const uint32_t* Mb = Bl + ((wc*32 + gi)*APITCH>>1) + li4;

        #pragma unroll
        for (int ks=0; ks<KC/16; ks++){
            int ko = ks*8;
            uint32_t bh[4][2], af[4][4];
            #pragma unroll
            for (int ni=0; ni<4; ni++){
                bh[ni][0] = Bb[ni*8*(APITCH>>1) + ko];
                bh[ni][1] = Bb[ni*8*(APITCH>>1) + ko + 4];
            }
            #pragma unroll
            for (int mi=0; mi<4; mi++){
                const uint32_t* ap = Ab + mi*16*(APITCH>>1) + ko;
                af[mi][0]=ap[0]; af[mi][1]=ap[8*(APITCH>>1)];
                af[mi][2]=ap[4]; af[mi][3]=ap[8*(APITCH>>1)+4];
            }
            #pragma unroll
            for (int mi=0; mi<4; mi++)
                #pragma unroll
                for (int ni=0; ni<4; ni++)
                    mma16816(acc[mi][ni], af[mi][0],af[mi][1],af[mi][2],af[mi][3],
                             bh[ni][0], bh[ni][1]);
            #pragma unroll
            for (int ni=0; ni<4; ni++){
                uint32_t b0 = Mb[ni*8*(APITCH>>1) + ko];
                uint32_t b1 = Mb[ni*8*(APITCH>>1) + ko + 4];
                #pragma unroll
                for (int mi=0; mi<4; mi++)
                    mma16816(acc[mi][ni], af[mi][0],af[mi][1],af[mi][2],af[mi][3], b0, b1);
            }
            #pragma unroll
            for (int mi=0; mi<4; mi++){
                const uint32_t* ap = Lb + mi*16*(APITCH>>1) + ko;
                uint32_t a0=ap[0], a1=ap[8*(APITCH>>1)], a2=ap[4], a3=ap[8*(APITCH>>1)+4];
                #pragma unroll
                for (int ni=0; ni<4; ni++)
                    mma16816(acc[mi][ni], a0,a1,a2,a3, bh[ni][0], bh[ni][1]);
            }
        }
        __syncthreads();
    }

    #pragma unroll
    for (int ni=0; ni<4; ni++){
        int n = bn + wc*32 + ni*8 + li4*2;
        float2 sv = Sp ? *(const float2*)&Sp[n] : make_float2(1.f,1.f);
        #pragma unroll
        for (int mi=0; mi<4; mi++){
            int m0 = bm + wr*64 + mi*16 + gi;
            if (m0 < M){
                float2 p = make_float2(acc[mi][ni][0]*sv.x, acc[mi][ni][1]*sv.y);
                *(float2*)&Cout[(size_t)m0*NPIX + n] = p;
            }
            int m1 = m0 + 8;
            if (m1 < M){
                float2 p = make_float2(acc[mi][ni][2]*sv.x, acc[mi][ni][3]*sv.y);
                *(float2*)&Cout[(size_t)m1*NPIX + n] = p;
            }
        }
    }
}

// ---------------- K5: depthwise 3x3 (pad 1) + ssq partials for q,k ----------------
__global__ void k_dw(const float* __restrict__ wd){
    int bc = blockIdx.x;              // b*C4 + ch
    int ch = bc % C4;
    int b  = bc / C4;
    int y  = blockIdx.y;
    int xx = threadIdx.x;             // 128
    const float* in = g_qkv + (size_t)bc*NPIX;
    const float* w  = wd + ch*9;
    float acc = 0.f;
    #pragma unroll
    for (int dy=0; dy<3; dy++){
        int yy = y + dy - 1;
        if ((unsigned)yy < 128u){
            const float* row = in + yy*HW;
            #pragma unroll
            for (int dx=0; dx<3; dx++){
                int xc = xx + dx - 1;
                if ((unsigned)xc < 128u) acc += row[xc]*__ldg(&w[dy*3+dx]);
            }
        }
    }
    g_dw[(size_t)bc*NPIX + y*HW + xx] = acc;

    // ssq partial for q (ch<C) and k (2C<=ch<3C) channels; uniform branch per block
    int slot = (ch < C) ? ch : ((ch >= 2*C && ch < 3*C) ? C + (ch - 2*C) : -1);
    if (slot >= 0){
        float s = acc*acc;
        #pragma unroll
        for (int o=16;o;o>>=1) s += __shfl_xor_sync(~0u, s, o);
        __shared__ float w4[4];
        if ((xx&31)==0) w4[xx>>5] = s;
        __syncthreads();
        if (xx==0)
            g_ssqp[((size_t)b*C2 + slot)*HW + y] = w4[0]+w4[1]+w4[2]+w4[3];
    }
}

// ---------------- K6: combine ssq partials -> inverse norms ----------------
__global__ void k_cssq(){
    int t = blockIdx.x*256 + threadIdx.x;   // 0..3071
    if (t >= NB*C2) return;
    const float* p = g_ssqp + (size_t)t*HW;
    float s = 0.f;
    #pragma unroll 4
    for (int y=0;y<HW;y++) s += p[y];
    float inv = 1.f/fmaxf(sqrtf(s), 1e-12f);
    int b = t/C2, r = t - b*C2;
    if (r < C) g_inq[b*C + r] = inv;
    else       g_ink[b*C + r - C] = inv;
}

// ---------------- K7: partial q.k^T over a spatial segment ----------------
__global__ void k_attn_partial(){
    int bh  = blockIdx.x;             // b*HEADS + h
    int seg = blockIdx.y;
    int b = bh >> 2, hh = bh & 3;
    const float* qb = g_dw + ((size_t)b*C4 + hh*HD)*NPIX;
    const float* kb = g_dw + ((size_t)b*C4 + 2*C + hh*HD)*NPIX;
    __shared__ float qs[HD][65], ks[HD][65];
    int tid = threadIdx.x;
    int tx = tid & 15, ty = tid >> 4;
    float acc[3][3] = {};
    int p0 = seg*SEGLEN;
    for (int ck=0; ck<SEGLEN; ck+=64){
        for (int e=tid; e<HD*64; e+=256){
            int i = e >> 6, p = e & 63;
            qs[i][p] = qb[(size_t)i*NPIX + p0 + ck + p];
            ks[i][p] = kb[(size_t)i*NPIX + p0 + ck + p];
        }
        __syncthreads();
        #pragma unroll 8
        for (int p=0;p<64;p++){
            float q0=qs[ty*3+0][p], q1=qs[ty*3+1][p], q2=qs[ty*3+2][p];
            float k0=ks[tx*3+0][p], k1=ks[tx*3+1][p], k2=ks[tx*3+2][p];
            acc[0][0]+=q0*k0; acc[0][1]+=q0*k1; acc[0][2]+=q0*k2;
            acc[1][0]+=q1*k0; acc[1][1]+=q1*k1; acc[1][2]+=q1*k2;
            acc[2][0]+=q2*k0; acc[2][1]+=q2*k1; acc[2][2]+=q2*k2;
        }
        __syncthreads();
    }
    #pragma unroll
    for (int r=0;r<3;r++)
        #pragma unroll
        for (int s=0;s<3;s++)
            g_spart[((size_t)(bh*NSEG+seg)*HD + ty*3+r)*HD + tx*3+s] = acc[r][s];
}

// ---------------- K8: combine partials, scale, softmax ----------------
__global__ void k_softmax(const float* __restrict__ temp){
    int row = blockIdx.x;             // NB*HEADS*HD
    int bh = row / HD;
    int i  = row - bh*HD;
    int b = bh >> 2, hh = bh & 3;
    int j = threadIdx.x;              // 64
    float v = -1e30f;
    if (j < HD){
        float s = 0.f;
        #pragma unroll
        for (int sg=0; sg<NSEG; sg++)
            s += g_spart[((size_t)(bh*NSEG+sg)*HD + i)*HD + j];
        v = s * __ldg(&temp[hh]) * g_inq[b*C + hh*HD + i] * g_ink[b*C + hh*HD + j];
    }
    __shared__ float sh[64];
    sh[j] = v; __syncthreads();
    for (int o=32;o>0;o>>=1){ if (j<o) sh[j]=fmaxf(sh[j],sh[j+o]); __syncthreads(); }
    float m = sh[0]; __syncthreads();
    float e = (j < HD) ? expf(v - m) : 0.f;
    sh[j] = e; __syncthreads();
    for (int o=32;o>0;o>>=1){ if (j<o) sh[j]+=sh[j+o]; __syncthreads(); }
    if (j < HD) g_attn[(size_t)bh*HD*HD + i*HD + j] = e / sh[0];
}

// ---------------- K9: out = (attn @ v) * sigmoid(gate) ----------------
__global__ void k_av_gate(){
    int bh = blockIdx.x;
    int b = bh >> 2, hh = bh & 3;
    int p = blockIdx.y*128 + threadIdx.x;
    __shared__ float at[HD][HD];
    for (int e=threadIdx.x; e<HD*HD; e+=128)
        at[e/HD][e%HD] = g_attn[(size_t)bh*HD*HD + e];
    __syncthreads();
    const float* vb = g_dw + ((size_t)b*C4 + 3*C + hh*HD)*NPIX + p;
    const float* gb = g_dw + ((size_t)b*C4 + 1*C + hh*HD)*NPIX + p;
    float* ob = g_outg + ((size_t)b*C + hh*HD)*NPIX + p;
    float vcol[HD];
    #pragma unroll
    for (int j=0;j<HD;j++) vcol[j] = vb[(size_t)j*NPIX];
    for (int i=0;i<HD;i++){
        float a = 0.f;
        #pragma unroll
        for (int j=0;j<HD;j++) a += at[i][j]*vcol[j];
        float g = gb[(size_t)i*NPIX];
        ob[(size_t)i*NPIX] = a * sigmoidf_(g);
    }
}

// ---------------- host ----------------
extern "C" void kernel_launch(void* const* d_in, const int* in_sizes, int n_in,
                              void* d_out, int out_size){
    const float* x      = (const float*)d_in[0];
    const float* w_fc1  = (const float*)d_in[1];
    const float* w_fc2  = (const float*)d_in[2];
    const float* w_sp   = (const float*)d_in[3];
    const float* w_qkv  = (const float*)d_in[4];
    const float* w_dw   = (const float*)d_in[5];
    const float* w_proj = (const float*)d_in[6];
    const float* temp   = (const float*)d_in[7];
    float* out = (float*)d_out;

    float *qkv, *outg, *cg, *sg;
    cudaGetSymbolAddress((void**)&qkv,  g_qkv);
    cudaGetSymbolAddress((void**)&outg, g_outg);
    cudaGetSymbolAddress((void**)&cg,   g_cg);
    cudaGetSymbolAddress((void**)&sg,   g_sg);

    cudaFuncSetAttribute(k_hmma, cudaFuncAttributeMaxDynamicSharedMemorySize, SMEM_HMMA);

    k_stats        <<<dim3(NTILE, NB), 256>>>(x);   // one pass: channel+pixel stats
    k_chan_gate    <<<NB, 192>>>(w_fc1, w_fc2);
    k_spatial_conv <<<NB*NPIX/256, 256>>>(w_sp);

    // qkv = sg(p) * ((w_qkv * cg) @ x) on tensor cores (split-bf16, 3 passes)
    k_hmma<<<dim3(NPIX/128, 6, NB), 256, SMEM_HMMA>>>(
        w_qkv, cg, x, (long)C*NPIX, qkv, (long)C4*NPIX, sg, C4);

    k_dw<<<dim3(NB*C4, HW), 128>>>(w_dw);           // dw + ssq partials
    k_cssq<<<(NB*C2+255)/256, 256>>>();

    k_attn_partial<<<dim3(NB*HEADS, NSEG), 256>>>();
    k_softmax     <<<NB*HEADS*HD, 64>>>(temp);
    k_av_gate     <<<dim3(NB*HEADS, NPIX/128), 128>>>();

    // final projection straight into d_out
    k_hmma<<<dim3(NPIX/128, 2, NB), 256, SMEM_HMMA>>>(
        w_proj, nullptr, outg, (long)C*NPIX, out, (long)C*NPIX, nullptr, C);
}

// round 7
// speedup vs baseline: 1.5699x; 1.0901x over previous
#include <cuda_runtime.h>
#include <cuda_bf16.h>
#include <cuda_fp16.h>
#include <math.h>
#include <stdint.h>

#define NB    8
#define C     192
#define C2    384
#define C4    768
#define HEADS 4
#define HD    48
#define HW    128
#define NPIX  16384
#define GK    192
#define NSEG  16
#define SEGLEN (NPIX/NSEG)
#define NTILE 32

// ---------------- scratch (static device memory) ----------------
__device__ float g_cps[NB*NTILE*C];
__device__ float g_cpm[NB*NTILE*C];
__device__ float g_cg [NB*C];
__device__ float g_sp [NB*2*NPIX];
__device__ float g_sg [NB*NPIX];
__device__ __nv_bfloat16 g_xh[(size_t)NB*C*NPIX];   // x split hi (50MB)
__device__ __nv_bfloat16 g_xl[(size_t)NB*C*NPIX];   // x split lo
__device__ __nv_bfloat16 g_wqh[NB*C4*GK];           // gate-folded qkv weights hi
__device__ __nv_bfloat16 g_wql[NB*C4*GK];
__device__ __nv_bfloat16 g_wph[C*GK];               // proj weights hi
__device__ __nv_bfloat16 g_wpl[C*GK];
__device__ __half g_qkv[(size_t)NB*C4*NPIX];        // 201 MB
__device__ __half g_dw [(size_t)NB*C4*NPIX];        // 201 MB
__device__ float g_ssqp[(size_t)NB*C2*HW];
__device__ float g_inq [NB*C];
__device__ float g_ink [NB*C];
__device__ float g_spart[(size_t)NB*HEADS*NSEG*HD*HD];
__device__ float g_attn [(size_t)NB*HEADS*HD*HD];
__device__ __nv_bfloat16 g_oh[(size_t)NB*C*NPIX];   // gated attn out hi
__device__ __nv_bfloat16 g_ol[(size_t)NB*C*NPIX];   // gated attn out lo

__device__ __forceinline__ float sigmoidf_(float x){ return 1.f/(1.f+expf(-x)); }

__device__ __forceinline__ uint32_t su32(const void* p){
    uint32_t a;
    asm("{ .reg .u64 t; cvta.to.shared.u64 t, %1; cvt.u32.u64 %0, t; }" : "=r"(a) : "l"(p));
    return a;
}
#define CP16(dst, src) \
    asm volatile("cp.async.cg.shared.global [%0], [%1], 16;" :: "r"(dst), "l"(src))

__device__ __forceinline__ void ldm_x4(uint32_t* r, uint32_t addr){
    asm volatile("ldmatrix.sync.aligned.m8n8.x4.shared.b16 {%0,%1,%2,%3}, [%4];"
      : "=r"(r[0]),"=r"(r[1]),"=r"(r[2]),"=r"(r[3]) : "r"(addr));
}
__device__ __forceinline__ void ldm_x2t(uint32_t* r, uint32_t addr){
    asm volatile("ldmatrix.sync.aligned.m8n8.x2.trans.shared.b16 {%0,%1}, [%2];"
      : "=r"(r[0]),"=r"(r[1]) : "r"(addr));
}
__device__ __forceinline__ void mma16816(float* c, uint32_t a0, uint32_t a1,
                                         uint32_t a2, uint32_t a3,
                                         uint32_t b0, uint32_t b1){
    asm volatile(
      "mma.sync.aligned.m16n8k16.row.col.f32.bf16.bf16.f32 "
      "{%0,%1,%2,%3},{%4,%5,%6,%7},{%8,%9},{%0,%1,%2,%3};"
      : "+f"(c[0]), "+f"(c[1]), "+f"(c[2]), "+f"(c[3])
      : "r"(a0), "r"(a1), "r"(a2), "r"(a3), "r"(b0), "r"(b1));
}

// ---------------- K1: one pass over x -> channel partials + pixel stats ----------------
__global__ __launch_bounds__(256)
void k_stats(const float* __restrict__ x){
    __shared__ float sps[8*512], spm[8*512];
    int tile = blockIdx.x, b = blockIdx.y;
    int tid = threadIdx.x, w = tid>>5, lane = tid&31;
    int p0 = tile*512;
    float ps[16], pm[16];
    #pragma unroll
    for (int i=0;i<16;i++){ ps[i]=0.f; pm[i]=-1e30f; }
    for (int ci=0; ci<24; ci++){
        int c = w*24 + ci;
        const float* row = x + ((size_t)b*C + c)*NPIX + p0;
        float cs = 0.f, cm = -1e30f;
        #pragma unroll
        for (int it=0; it<16; it++){
            float v = row[it*32 + lane];
            ps[it] += v; pm[it] = fmaxf(pm[it], v);
            cs += v;     cm = fmaxf(cm, v);
        }
        #pragma unroll
        for (int o=16;o;o>>=1){
            cs += __shfl_xor_sync(~0u, cs, o);
            cm = fmaxf(cm, __shfl_xor_sync(~0u, cm, o));
        }
        if (lane==0){
            g_cps[(b*NTILE + tile)*C + c] = cs;
            g_cpm[(b*NTILE + tile)*C + c] = cm;
        }
    }
    #pragma unroll
    for (int it=0; it<16; it++){
        sps[w*512 + it*32 + lane] = ps[it];
        spm[w*512 + it*32 + lane] = pm[it];
    }
    __syncthreads();
    for (int p=tid; p<512; p+=256){
        float s = 0.f, m = -1e30f;
        #pragma unroll
        for (int ww=0; ww<8; ww++){
            s += sps[ww*512+p];
            m = fmaxf(m, spm[ww*512+p]);
        }
        g_sp[(size_t)b*2*NPIX + p0 + p]        = s*(1.f/C);
        g_sp[(size_t)b*2*NPIX + NPIX + p0 + p] = m;
    }
}

// ---------------- K2: SE channel gate MLP ----------------
__global__ void k_chan_gate(const float* __restrict__ w1, const float* __restrict__ w2){
    int b = blockIdx.x, t = threadIdx.x;
    __shared__ float pool[C2], sq[48];
    {
        float s = 0.f, m = -1e30f;
        for (int tile=0; tile<NTILE; tile++){
            s += g_cps[(b*NTILE + tile)*C + t];
            m = fmaxf(m, g_cpm[(b*NTILE + tile)*C + t]);
        }
        pool[t]   = s*(1.f/NPIX);
        pool[C+t] = m;
    }
    __syncthreads();
    if (t < 48){
        float a = 0.f;
        #pragma unroll 8
        for (int c=0;c<C2;c++) a += w1[t*C2+c]*pool[c];
        sq[t] = fmaxf(a, 0.f);
    }
    __syncthreads();
    float a = 0.f;
    #pragma unroll
    for (int s=0;s<48;s++) a += w2[t*48+s]*sq[s];
    g_cg[b*C+t] = sigmoidf_(a);
}

// ---------------- K3: 7x7 spatial conv + sigmoid ----------------
__global__ void k_spatial_conv(const float* __restrict__ ws){
    int idx = blockIdx.x*256 + threadIdx.x;
    int b = idx >> 14, p = idx & (NPIX-1);
    int y = p >> 7, xx = p & 127;
    float acc = 0.f;
    #pragma unroll
    for (int ch=0; ch<2; ch++){
        const float* base = g_sp + (size_t)b*2*NPIX + (size_t)ch*NPIX;
        #pragma unroll
        for (int dy=-3; dy<=3; dy++){
            int yy = y+dy;
            if ((unsigned)yy < 128u){
                const float* row = base + yy*HW;
                #pragma unroll
                for (int dx=-3; dx<=3; dx++){
                    int xc = xx+dx;
                    if ((unsigned)xc < 128u)
                        acc += row[xc]*__ldg(&ws[ch*49 + (dy+3)*7 + (dx+3)]);
                }
            }
        }
    }
    g_sg[(size_t)b*NPIX + p] = sigmoidf_(acc);
}

// ---------------- split fp32 -> bf16 hi/lo ----------------
__device__ __forceinline__ void split4(float4 v, __nv_bfloat16* oh, __nv_bfloat16* ol, size_t i){
    __nv_bfloat16 h0=__float2bfloat16(v.x), h1=__float2bfloat16(v.y);
    __nv_bfloat16 h2=__float2bfloat16(v.z), h3=__float2bfloat16(v.w);
    __nv_bfloat16 l0=__float2bfloat16(v.x-__bfloat162float(h0));
    __nv_bfloat16 l1=__float2bfloat16(v.y-__bfloat162float(h1));
    __nv_bfloat16 l2=__float2bfloat16(v.z-__bfloat162float(h2));
    __nv_bfloat16 l3=__float2bfloat16(v.w-__bfloat162float(h3));
    ushort4 H = make_ushort4(__bfloat16_as_ushort(h0),__bfloat16_as_ushort(h1),
                             __bfloat16_as_ushort(h2),__bfloat16_as_ushort(h3));
    ushort4 L = make_ushort4(__bfloat16_as_ushort(l0),__bfloat16_as_ushort(l1),
                             __bfloat16_as_ushort(l2),__bfloat16_as_ushort(l3));
    *(ushort4*)(oh+i) = H;
    *(ushort4*)(ol+i) = L;
}

__global__ void k_split(const float* __restrict__ src,
                        __nv_bfloat16* __restrict__ oh, __nv_bfloat16* __restrict__ ol){
    size_t i = ((size_t)blockIdx.x*256 + threadIdx.x)*4;
    split4(*(const float4*)(src+i), oh, ol, i);
}

__global__ void k_wsplit(const float* __restrict__ w,
                         __nv_bfloat16* __restrict__ oh, __nv_bfloat16* __restrict__ ol){
    // gate-folded qkv weights: out [NB][C4][GK]
    size_t i = ((size_t)blockIdx.x*256 + threadIdx.x)*4;
    int b  = (int)(i/(C4*GK));
    int rc = (int)(i - (size_t)b*C4*GK);
    int col = rc % GK;
    float4 v = *(const float4*)(w+rc);
    const float* g = g_cg + b*C;
    v.x *= g[col]; v.y *= g[col+1]; v.z *= g[col+2]; v.w *= g[col+3];
    split4(v, oh, ol, i);
}

// ================= bf16 HMMA GEMM (3-pass split), cp.async + ldmatrix =================
// smem: Ah[128][56] 14336, Al 14336, Bh[48][136] 13056, Bl 13056 = 54784
#define S_AH 0
#define S_AL 14336
#define S_BH 28672
#define S_BL 41728
#define SMEM2 54784

__global__ __launch_bounds__(256)
void k_hmma2(const __nv_bfloat16* __restrict__ Agh, const __nv_bfloat16* __restrict__ Agl,
             long sA,
             const __nv_bfloat16* __restrict__ Bgh, const __nv_bfloat16* __restrict__ Bgl,
             void* __restrict__ outp, long sC, int out_half,
             const float* __restrict__ S, int M){
    extern __shared__ __align__(16) char smem[];
    uint32_t sb = su32(smem);
    int b = blockIdx.z, bm = blockIdx.y*128, bn = blockIdx.x*128;
    const __nv_bfloat16* Ah = Agh + (size_t)b*sA;
    const __nv_bfloat16* Al = Agl + (size_t)b*sA;
    const __nv_bfloat16* Bh = Bgh + (size_t)b*C*NPIX;
    const __nv_bfloat16* Bl = Bgl + (size_t)b*C*NPIX;
    const float* Sp = S ? S + (size_t)b*NPIX : nullptr;

    int tid = threadIdx.x, wid = tid>>5, lane = tid&31;
    int wr = wid>>2, wc = wid&3;
    int gi = lane>>2, li4 = lane&3;

    float acc[4][4][4];
    #pragma unroll
    for (int i=0;i<4;i++)
        #pragma unroll
        for (int j=0;j<4;j++)
            #pragma unroll
            for (int r=0;r<4;r++) acc[i][j][r]=0.f;

    uint32_t aA  = sb + S_AH + (wr*64 + (lane&15))*112 + (lane>>4)*16;
    uint32_t aAl = sb + S_AL + (wr*64 + (lane&15))*112 + (lane>>4)*16;
    uint32_t bA  = sb + S_BH + (lane&15)*272 + wc*64;      // wc*32 n * 2B
    uint32_t bAl = sb + S_BL + (lane&15)*272 + wc*64;

    for (int c0=0; c0<GK; c0+=48){
        // stage A (128 rows x 96B) hi+lo
        for (int e=tid; e<768; e+=256){
            int r = e/6, ch = e - (e/6)*6;
            int m = bm + r; if (m >= M) m = M-1;
            size_t off = (size_t)m*GK + c0;
            CP16(sb + S_AH + r*112 + ch*16, (const char*)(Ah + off) + ch*16);
            CP16(sb + S_AL + r*112 + ch*16, (const char*)(Al + off) + ch*16);
        }
        // stage B (48 rows x 256B) hi+lo
        for (int e=tid; e<768; e+=256){
            int k = e>>4, ch = e&15;
            size_t off = (size_t)(c0+k)*NPIX + bn;
            CP16(sb + S_BH + k*272 + ch*16, (const char*)(Bh + off) + ch*16);
            CP16(sb + S_BL + k*272 + ch*16, (const char*)(Bl + off) + ch*16);
        }
        asm volatile("cp.async.commit_group;" ::: "memory");
        asm volatile("cp.async.wait_group 0;" ::: "memory");
        __syncthreads();

        #pragma unroll
        for (int ks=0; ks<3; ks++){
            uint32_t Af[4][4], Bf[4][2], Bx[4][2];
            #pragma unroll
            for (int mi=0; mi<4; mi++) ldm_x4(Af[mi], aA + mi*1792 + ks*32);
            #pragma unroll
            for (int ni=0; ni<4; ni++) ldm_x2t(Bf[ni], bA + ks*4352 + ni*16);
            #pragma unroll
            for (int mi=0; mi<4; mi++)
                #pragma unroll
                for (int ni=0; ni<4; ni++)
                    mma16816(acc[mi][ni], Af[mi][0],Af[mi][1],Af[mi][2],Af[mi][3],
                             Bf[ni][0],Bf[ni][1]);
            #pragma unroll
            for (int ni=0; ni<4; ni++) ldm_x2t(Bx[ni], bAl + ks*4352 + ni*16);
            #pragma unroll
            for (int mi=0; mi<4; mi++)
                #pragma unroll
                for (int ni=0; ni<4; ni++)
                    mma16816(acc[mi][ni], Af[mi][0],Af[mi][1],Af[mi][2],Af[mi][3],
                             Bx[ni][0],Bx[ni][1]);
            #pragma unroll
            for (int mi=0; mi<4; mi++){
                uint32_t Alf[4];
                ldm_x4(Alf, aAl + mi*1792 + ks*32);
                #pragma unroll
                for (int ni=0; ni<4; ni++)
                    mma16816(acc[mi][ni], Alf[0],Alf[1],Alf[2],Alf[3],
                             Bf[ni][0],Bf[ni][1]);
            }
        }
        __syncthreads();
    }

    // epilogue
    #pragma unroll
    for (int ni=0; ni<4; ni++){
        int n = bn + wc*32 + ni*8 + li4*2;
        float2 sv = Sp ? *(const float2*)&Sp[n] : make_float2(1.f,1.f);
        #pragma unroll
        for (int mi=0; mi<4; mi++){
            int m0 = bm + wr*64 + mi*16 + gi;
            int m1 = m0 + 8;
            if (out_half){
                __half* O = (__half*)outp + (size_t)b*sC;
                if (m0 < M)
                    *(__half2*)(O + (size_t)m0*NPIX + n) =
                        __floats2half2_rn(acc[mi][ni][0]*sv.x, acc[mi][ni][1]*sv.y);
                if (m1 < M)
                    *(__half2*)(O + (size_t)m1*NPIX + n) =
                        __floats2half2_rn(acc[mi][ni][2]*sv.x, acc[mi][ni][3]*sv.y);
            } else {
                float* O = (float*)outp + (size_t)b*sC;
                if (m0 < M){
                    float2 p = make_float2(acc[mi][ni][0]*sv.x, acc[mi][ni][1]*sv.y);
                    *(float2*)(O + (size_t)m0*NPIX + n) = p;
                }
                if (m1 < M){
                    float2 p = make_float2(acc[mi][ni][2]*sv.x, acc[mi][ni][3]*sv.y);
                    *(float2*)(O + (size_t)m1*NPIX + n) = p;
                }
            }
        }
    }
}

// ---------------- depthwise 3x3 (half in/out) + ssq partials for q,k ----------------
__global__ void k_dw(const float* __restrict__ wd){
    int bc = blockIdx.x;
    int ch = bc % C4;
    int b  = bc / C4;
    int y  = blockIdx.y;
    int xx = threadIdx.x;
    const __half* in = g_qkv + (size_t)bc*NPIX;
    const float* w  = wd + ch*9;
    float acc = 0.f;
    #pragma unroll
    for (int dy=0; dy<3; dy++){
        int yy = y + dy - 1;
        if ((unsigned)yy < 128u){
            const __half* row = in + yy*HW;
            #pragma unroll
            for (int dx=0; dx<3; dx++){
                int xc = xx + dx - 1;
                if ((unsigned)xc < 128u) acc += __half2float(row[xc])*__ldg(&w[dy*3+dx]);
            }
        }
    }
    g_dw[(size_t)bc*NPIX + y*HW + xx] = __float2half(acc);

    int slot = (ch < C) ? ch : ((ch >= 2*C && ch < 3*C) ? C + (ch - 2*C) : -1);
    if (slot >= 0){
        float s = acc*acc;
        #pragma unroll
        for (int o=16;o;o>>=1) s += __shfl_xor_sync(~0u, s, o);
        __shared__ float w4[4];
        if ((xx&31)==0) w4[xx>>5] = s;
        __syncthreads();
        if (xx==0)
            g_ssqp[((size_t)b*C2 + slot)*HW + y] = w4[0]+w4[1]+w4[2]+w4[3];
    }
}

__global__ void k_cssq(){
    int t = blockIdx.x*256 + threadIdx.x;
    if (t >= NB*C2) return;
    const float* p = g_ssqp + (size_t)t*HW;
    float s = 0.f;
    #pragma unroll 4
    for (int y=0;y<HW;y++) s += p[y];
    float inv = 1.f/fmaxf(sqrtf(s), 1e-12f);
    int b = t/C2, r = t - b*C2;
    if (r < C) g_inq[b*C + r] = inv;
    else       g_ink[b*C + r - C] = inv;
}

// ---------------- partial q.k^T over a spatial segment ----------------
__global__ void k_attn_partial(){
    int bh  = blockIdx.x;
    int seg = blockIdx.y;
    int b = bh >> 2, hh = bh & 3;
    const __half* qb = g_dw + ((size_t)b*C4 + hh*HD)*NPIX;
    const __half* kb = g_dw + ((size_t)b*C4 + 2*C + hh*HD)*NPIX;
    __shared__ float qs[HD][65], ks[HD][65];
    int tid = threadIdx.x;
    int tx = tid & 15, ty = tid >> 4;
    float acc[3][3] = {};
    int p0 = seg*SEGLEN;
    for (int ck=0; ck<SEGLEN; ck+=64){
        for (int e=tid; e<HD*64; e+=256){
            int i = e >> 6, p = e & 63;
            qs[i][p] = __half2float(qb[(size_t)i*NPIX + p0 + ck + p]);
            ks[i][p] = __half2float(kb[(size_t)i*NPIX + p0 + ck + p]);
        }
        __syncthreads();
        #pragma unroll 8
        for (int p=0;p<64;p++){
            float q0=qs[ty*3+0][p], q1=qs[ty*3+1][p], q2=qs[ty*3+2][p];
            float k0=ks[tx*3+0][p], k1=ks[tx*3+1][p], k2=ks[tx*3+2][p];
            acc[0][0]+=q0*k0; acc[0][1]+=q0*k1; acc[0][2]+=q0*k2;
            acc[1][0]+=q1*k0; acc[1][1]+=q1*k1; acc[1][2]+=q1*k2;
            acc[2][0]+=q2*k0; acc[2][1]+=q2*k1; acc[2][2]+=q2*k2;
        }
        __syncthreads();
    }
    #pragma unroll
    for (int r=0;r<3;r++)
        #pragma unroll
        for (int s=0;s<3;s++)
            g_spart[((size_t)(bh*NSEG+seg)*HD + ty*3+r)*HD + tx*3+s] = acc[r][s];
}

// ---------------- combine partials, scale, softmax ----------------
__global__ void k_softmax(const float* __restrict__ temp){
    int row = blockIdx.x;
    int bh = row / HD;
    int i  = row - bh*HD;
    int b = bh >> 2, hh = bh & 3;
    int j = threadIdx.x;
    float v = -1e30f;
    if (j < HD){
        float s = 0.f;
        #pragma unroll
        for (int sg=0; sg<NSEG; sg++)
            s += g_spart[((size_t)(bh*NSEG+sg)*HD + i)*HD + j];
        v = s * __ldg(&temp[hh]) * g_inq[b*C + hh*HD + i] * g_ink[b*C + hh*HD + j];
    }
    __shared__ float sh[64];
    sh[j] = v; __syncthreads();
    for (int o=32;o>0;o>>=1){ if (j<o) sh[j]=fmaxf(sh[j],sh[j+o]); __syncthreads(); }
    float m = sh[0]; __syncthreads();
    float e = (j < HD) ? expf(v - m) : 0.f;
    sh[j] = e; __syncthreads();
    for (int o=32;o>0;o>>=1){ if (j<o) sh[j]+=sh[j+o]; __syncthreads(); }
    if (j < HD) g_attn[(size_t)bh*HD*HD + i*HD + j] = e / sh[0];
}

// ---------------- out = (attn @ v) * sigmoid(gate), written as bf16 hi/lo ----------------
__global__ void k_av_gate(){
    int bh = blockIdx.x;
    int b = bh >> 2, hh = bh & 3;
    int p = blockIdx.y*128 + threadIdx.x;
    __shared__ float at[HD][HD];
    for (int e=threadIdx.x; e<HD*HD; e+=128)
        at[e/HD][e%HD] = g_attn[(size_t)bh*HD*HD + e];
    __syncthreads();
    const __half* vb = g_dw + ((size_t)b*C4 + 3*C + hh*HD)*NPIX + p;
    const __half* gb = g_dw + ((size_t)b*C4 + 1*C + hh*HD)*NPIX + p;
    size_t ob = ((size_t)b*C + hh*HD)*NPIX + p;
    float vcol[HD];
    #pragma unroll
    for (int j=0;j<HD;j++) vcol[j] = __half2float(vb[(size_t)j*NPIX]);
    for (int i=0;i<HD;i++){
        float a = 0.f;
        #pragma unroll
        for (int j=0;j<HD;j++) a += at[i][j]*vcol[j];
        float g = __half2float(gb[(size_t)i*NPIX]);
        float o = a * sigmoidf_(g);
        __nv_bfloat16 h = __float2bfloat16(o);
        g_oh[ob + (size_t)i*NPIX] = h;
        g_ol[ob + (size_t)i*NPIX] = __float2bfloat16(o - __bfloat162float(h));
    }
}

// ---------------- host ----------------
extern "C" void kernel_launch(void* const* d_in, const int* in_sizes, int n_in,
                              void* d_out, int out_size){
    const float* x      = (const float*)d_in[0];
    const float* w_fc1  = (const float*)d_in[1];
    const float* w_fc2  = (const float*)d_in[2];
    const float* w_sp   = (const float*)d_in[3];
    const float* w_qkv  = (const float*)d_in[4];
    const float* w_dw   = (const float*)d_in[5];
    const float* w_proj = (const float*)d_in[6];
    const float* temp   = (const float*)d_in[7];
    float* out = (float*)d_out;

    __nv_bfloat16 *xh, *xl, *wqh, *wql, *wph, *wpl, *oh, *ol;
    __half *qkv;
    float *sg;
    cudaGetSymbolAddress((void**)&xh,  g_xh);
    cudaGetSymbolAddress((void**)&xl,  g_xl);
    cudaGetSymbolAddress((void**)&wqh, g_wqh);
    cudaGetSymbolAddress((void**)&wql, g_wql);
    cudaGetSymbolAddress((void**)&wph, g_wph);
    cudaGetSymbolAddress((void**)&wpl, g_wpl);
    cudaGetSymbolAddress((void**)&oh,  g_oh);
    cudaGetSymbolAddress((void**)&ol,  g_ol);
    cudaGetSymbolAddress((void**)&qkv, g_qkv);
    cudaGetSymbolAddress((void**)&sg,  g_sg);

    cudaFuncSetAttribute(k_hmma2, cudaFuncAttributeMaxDynamicSharedMemorySize, SMEM2);

    k_stats        <<<dim3(NTILE, NB), 256>>>(x);
    k_chan_gate    <<<NB, 192>>>(w_fc1, w_fc2);
    k_spatial_conv <<<NB*NPIX/256, 256>>>(w_sp);

    k_split <<<(int)(((size_t)NB*C*NPIX/4 + 255)/256), 256>>>(x, xh, xl);
    k_wsplit<<<(NB*C4*GK/4 + 255)/256, 256>>>(w_qkv, wqh, wql); // gate-folded, per-batch
    k_split <<<(C*GK/4 + 255)/256, 256>>>(w_proj, wph, wpl);    // batch-shared

    // qkv = sg(p) * ((w_qkv*cg) @ x), half output
    k_hmma2<<<dim3(NPIX/128, 6, NB), 256, SMEM2>>>(
        wqh, wql, (long)C4*GK, xh, xl, qkv, (long)C4*NPIX, 1, sg, C4);

    k_dw<<<dim3(NB*C4, HW), 128>>>(w_dw);
    k_cssq<<<(NB*C2+255)/256, 256>>>();

    k_attn_partial<<<dim3(NB*HEADS, NSEG), 256>>>();
    k_softmax     <<<NB*HEADS*HD, 64>>>(temp);
    k_av_gate     <<<dim3(NB*HEADS, NPIX/128), 128>>>();

    // final projection (batch-shared weights, fp32 output into d_out)
    k_hmma2<<<dim3(NPIX/128, 2, NB), 256, SMEM2>>>(
        wph, wpl, 0L, oh, ol, out, (long)C*NPIX, 0, nullptr, C);
}

// round 9
// speedup vs baseline: 2.3466x; 1.4948x over previous
#include <cuda_runtime.h>
#include <cuda_fp16.h>
#include <math.h>
#include <stdint.h>

#define NB    8
#define C     192
#define C2    384
#define C4    768
#define HEADS 4
#define HD    48
#define HW    128
#define NPIX  16384
#define GK    192
#define NSEG  16
#define SEGLEN (NPIX/NSEG)
#define NTILE 32
#define WSCALE 64.0f
#define IWSCALE (1.0f/64.0f)

// ---------------- scratch (static device memory) ----------------
__device__ float g_cps[NB*NTILE*C];
__device__ float g_cpm[NB*NTILE*C];
__device__ float g_cg [NB*C];
__device__ float g_sp [NB*2*NPIX];
__device__ float g_sg [NB*NPIX];
__device__ __half g_xf [(size_t)NB*C*NPIX];   // x fp16 (50MB)
__device__ __half g_wqh[NB*C4*GK];            // gate-folded qkv weights *64, hi
__device__ __half g_wql[NB*C4*GK];            // lo
__device__ __half g_wph[C*GK];                // proj weights *64, hi
__device__ __half g_wpl[C*GK];
__device__ __half g_qkv[(size_t)NB*C4*NPIX];  // 201 MB
__device__ __half g_dw [(size_t)NB*C4*NPIX];  // 201 MB
__device__ float g_inq [NB*C];
__device__ float g_ink [NB*C];
__device__ float g_spart[(size_t)NB*HEADS*NSEG*HD*HD];
__device__ float g_attn [(size_t)NB*HEADS*HD*HD];
__device__ __half g_of [(size_t)NB*C*NPIX];   // gated attn out fp16

__device__ __forceinline__ float sigmoidf_(float x){ return 1.f/(1.f+expf(-x)); }

__device__ __forceinline__ uint32_t su32(const void* p){
    uint32_t a;
    asm("{ .reg .u64 t; cvta.to.shared.u64 t, %1; cvt.u32.u64 %0, t; }" : "=r"(a) : "l"(p));
    return a;
}
#define CP16(dst, src) \
    asm volatile("cp.async.cg.shared.global [%0], [%1], 16;" :: "r"(dst), "l"(src))

__device__ __forceinline__ void ldm_x4(uint32_t* r, uint32_t addr){
    asm volatile("ldmatrix.sync.aligned.m8n8.x4.shared.b16 {%0,%1,%2,%3}, [%4];"
      : "=r"(r[0]),"=r"(r[1]),"=r"(r[2]),"=r"(r[3]) : "r"(addr));
}
__device__ __forceinline__ void ldm_x2t(uint32_t* r, uint32_t addr){
    asm volatile("ldmatrix.sync.aligned.m8n8.x2.trans.shared.b16 {%0,%1}, [%2];"
      : "=r"(r[0]),"=r"(r[1]) : "r"(addr));
}
__device__ __forceinline__ void mma16816f(float* c, uint32_t a0, uint32_t a1,
                                          uint32_t a2, uint32_t a3,
                                          uint32_t b0, uint32_t b1){
    asm volatile(
      "mma.sync.aligned.m16n8k16.row.col.f32.f16.f16.f32 "
      "{%0,%1,%2,%3},{%4,%5,%6,%7},{%8,%9},{%0,%1,%2,%3};"
      : "+f"(c[0]), "+f"(c[1]), "+f"(c[2]), "+f"(c[3])
      : "r"(a0), "r"(a1), "r"(a2), "r"(a3), "r"(b0), "r"(b1));
}

// ---------------- K1: one pass over x -> channel partials + pixel stats ----------------
__global__ __launch_bounds__(256)
void k_stats(const float* __restrict__ x){
    __shared__ float sps[8*512], spm[8*512];
    int tile = blockIdx.x, b = blockIdx.y;
    int tid = threadIdx.x, w = tid>>5, lane = tid&31;
    int p0 = tile*512;
    float ps[16], pm[16];
    #pragma unroll
    for (int i=0;i<16;i++){ ps[i]=0.f; pm[i]=-1e30f; }
    for (int ci=0; ci<24; ci++){
        int c = w*24 + ci;
        const float* row = x + ((size_t)b*C + c)*NPIX + p0;
        float cs = 0.f, cm = -1e30f;
        #pragma unroll
        for (int it=0; it<16; it++){
            float v = row[it*32 + lane];
            ps[it] += v; pm[it] = fmaxf(pm[it], v);
            cs += v;     cm = fmaxf(cm, v);
        }
        #pragma unroll
        for (int o=16;o;o>>=1){
            cs += __shfl_xor_sync(~0u, cs, o);
            cm = fmaxf(cm, __shfl_xor_sync(~0u, cm, o));
        }
        if (lane==0){
            g_cps[(b*NTILE + tile)*C + c] = cs;
            g_cpm[(b*NTILE + tile)*C + c] = cm;
        }
    }
    #pragma unroll
    for (int it=0; it<16; it++){
        sps[w*512 + it*32 + lane] = ps[it];
        spm[w*512 + it*32 + lane] = pm[it];
    }
    __syncthreads();
    for (int p=tid; p<512; p+=256){
        float s = 0.f, m = -1e30f;
        #pragma unroll
        for (int ww=0; ww<8; ww++){
            s += sps[ww*512+p];
            m = fmaxf(m, spm[ww*512+p]);
        }
        g_sp[(size_t)b*2*NPIX + p0 + p]        = s*(1.f/C);
        g_sp[(size_t)b*2*NPIX + NPIX + p0 + p] = m;
    }
}

// ---------------- K2: SE channel gate MLP ----------------
__global__ void k_chan_gate(const float* __restrict__ w1, const float* __restrict__ w2){
    int b = blockIdx.x, t = threadIdx.x;
    __shared__ float pool[C2], sq[48];
    {
        float s = 0.f, m = -1e30f;
        for (int tile=0; tile<NTILE; tile++){
            s += g_cps[(b*NTILE + tile)*C + t];
            m = fmaxf(m, g_cpm[(b*NTILE + tile)*C + t]);
        }
        pool[t]   = s*(1.f/NPIX);
        pool[C+t] = m;
    }
    __syncthreads();
    if (t < 48){
        float a = 0.f;
        #pragma unroll 8
        for (int c=0;c<C2;c++) a += w1[t*C2+c]*pool[c];
        sq[t] = fmaxf(a, 0.f);
    }
    __syncthreads();
    float a = 0.f;
    #pragma unroll
    for (int s=0;s<48;s++) a += w2[t*48+s]*sq[s];
    g_cg[b*C+t] = sigmoidf_(a);
}

// ---------------- K3: 7x7 spatial conv + sigmoid ----------------
__global__ void k_spatial_conv(const float* __restrict__ ws){
    int idx = blockIdx.x*256 + threadIdx.x;
    int b = idx >> 14, p = idx & (NPIX-1);
    int y = p >> 7, xx = p & 127;
    float acc = 0.f;
    #pragma unroll
    for (int ch=0; ch<2; ch++){
        const float* base = g_sp + (size_t)b*2*NPIX + (size_t)ch*NPIX;
        #pragma unroll
        for (int dy=-3; dy<=3; dy++){
            int yy = y+dy;
            if ((unsigned)yy < 128u){
                const float* row = base + yy*HW;
                #pragma unroll
                for (int dx=-3; dx<=3; dx++){
                    int xc = xx+dx;
                    if ((unsigned)xc < 128u)
                        acc += row[xc]*__ldg(&ws[ch*49 + (dy+3)*7 + (dx+3)]);
                }
            }
        }
    }
    g_sg[(size_t)b*NPIX + p] = sigmoidf_(acc);
}

// ---------------- conversions ----------------
__global__ void k_xcvt(const float* __restrict__ src, __half* __restrict__ dst){
    size_t i = ((size_t)blockIdx.x*256 + threadIdx.x)*4;
    float4 v = *(const float4*)(src+i);
    __half2 a = __floats2half2_rn(v.x, v.y);
    __half2 b = __floats2half2_rn(v.z, v.w);
    *(uint2*)(dst+i) = make_uint2(*(uint32_t*)&a, *(uint32_t*)&b);
}

__device__ __forceinline__ void splitstore(float4 v, __half* oh, __half* ol, size_t i){
    __half h0=__float2half(v.x), h1=__float2half(v.y);
    __half h2=__float2half(v.z), h3=__float2half(v.w);
    __half l0=__float2half(v.x-__half2float(h0));
    __half l1=__float2half(v.y-__half2float(h1));
    __half l2=__float2half(v.z-__half2float(h2));
    __half l3=__float2half(v.w-__half2float(h3));
    *(ushort4*)(oh+i) = make_ushort4(__half_as_ushort(h0),__half_as_ushort(h1),
                                     __half_as_ushort(h2),__half_as_ushort(h3));
    *(ushort4*)(ol+i) = make_ushort4(__half_as_ushort(l0),__half_as_ushort(l1),
                                     __half_as_ushort(l2),__half_as_ushort(l3));
}

__global__ void k_wsplit16(const float* __restrict__ w,
                           __half* __restrict__ oh, __half* __restrict__ ol){
    // gate-folded qkv weights *64 -> [NB][C4][GK] fp16 hi/lo
    size_t i = ((size_t)blockIdx.x*256 + threadIdx.x)*4;
    int b  = (int)(i/(C4*GK));
    int rc = (int)(i - (size_t)b*C4*GK);
    int col = rc % GK;
    float4 v = *(const float4*)(w+rc);
    const float* g = g_cg + b*C;
    v.x *= WSCALE*g[col];   v.y *= WSCALE*g[col+1];
    v.z *= WSCALE*g[col+2]; v.w *= WSCALE*g[col+3];
    splitstore(v, oh, ol, i);
}

__global__ void k_pwsplit16(const float* __restrict__ w,
                            __half* __restrict__ oh, __half* __restrict__ ol){
    size_t i = ((size_t)blockIdx.x*256 + threadIdx.x)*4;
    float4 v = *(const float4*)(w+i);
    v.x *= WSCALE; v.y *= WSCALE; v.z *= WSCALE; v.w *= WSCALE;
    splitstore(v, oh, ol, i);
}

// ================= fp16 HMMA GEMM (2-pass: Wh*X + Wl*X), cp.async + ldmatrix =================
// smem: Ah[128][56] 14336, Al 14336, B[48][136] 13056 = 41728
#define S_AH 0
#define S_AL 14336
#define S_B  28672
#define SMEM3 41728

__global__ __launch_bounds__(256)
void k_hmma3(const __half* __restrict__ Agh, const __half* __restrict__ Agl,
             long sA,
             const __half* __restrict__ Bg,
             void* __restrict__ outp, long sC, int out_half,
             const float* __restrict__ S, int M){
    extern __shared__ __align__(16) char smem[];
    uint32_t sb = su32(smem);
    int b = blockIdx.z, bm = blockIdx.y*128, bn = blockIdx.x*128;
    const __half* Ah = Agh + (size_t)b*sA;
    const __half* Al = Agl + (size_t)b*sA;
    const __half* B  = Bg + (size_t)b*C*NPIX;
    const float* Sp = S ? S + (size_t)b*NPIX : nullptr;

    int tid = threadIdx.x, wid = tid>>5, lane = tid&31;
    int wr = wid>>2, wc = wid&3;
    int gi = lane>>2, li4 = lane&3;

    float acc[4][4][4];
    #pragma unroll
    for (int i=0;i<4;i++)
        #pragma unroll
        for (int j=0;j<4;j++)
            #pragma unroll
            for (int r=0;r<4;r++) acc[i][j][r]=0.f;

    uint32_t aA  = sb + S_AH + (wr*64 + (lane&15))*112 + (lane>>4)*16;
    uint32_t aAl = sb + S_AL + (wr*64 + (lane&15))*112 + (lane>>4)*16;
    uint32_t bA  = sb + S_B  + (lane&15)*272 + wc*64;

    for (int c0=0; c0<GK; c0+=48){
        for (int e=tid; e<768; e+=256){
            int r = e/6, ch = e - (e/6)*6;
            int m = bm + r; if (m >= M) m = M-1;
            size_t off = (size_t)m*GK + c0;
            CP16(sb + S_AH + r*112 + ch*16, (const char*)(Ah + off) + ch*16);
            CP16(sb + S_AL + r*112 + ch*16, (const char*)(Al + off) + ch*16);
        }
        for (int e=tid; e<768; e+=256){
            int k = e>>4, ch = e&15;
            size_t off = (size_t)(c0+k)*NPIX + bn;
            CP16(sb + S_B + k*272 + ch*16, (const char*)(B + off) + ch*16);
        }
        asm volatile("cp.async.commit_group;" ::: "memory");
        asm volatile("cp.async.wait_group 0;" ::: "memory");
        __syncthreads();

        #pragma unroll
        for (int ks=0; ks<3; ks++){
            uint32_t Af[4][4], Bf[4][2];
            #pragma unroll
            for (int mi=0; mi<4; mi++) ldm_x4(Af[mi], aA + mi*1792 + ks*32);
            #pragma unroll
            for (int ni=0; ni<4; ni++) ldm_x2t(Bf[ni], bA + ks*4352 + ni*16);
            #pragma unroll
            for (int mi=0; mi<4; mi++)
                #pragma unroll
                for (int ni=0; ni<4; ni++)
                    mma16816f(acc[mi][ni], Af[mi][0],Af[mi][1],Af[mi][2],Af[mi][3],
                              Bf[ni][0],Bf[ni][1]);
            #pragma unroll
            for (int mi=0; mi<4; mi++){
                uint32_t Alf[4];
                ldm_x4(Alf, aAl + mi*1792 + ks*32);
                #pragma unroll
                for (int ni=0; ni<4; ni++)
                    mma16816f(acc[mi][ni], Alf[0],Alf[1],Alf[2],Alf[3],
                              Bf[ni][0],Bf[ni][1]);
            }
        }
        __syncthreads();
    }

    // epilogue (undo *64 weight scale, apply spatial gate)
    #pragma unroll
    for (int ni=0; ni<4; ni++){
        int n = bn + wc*32 + ni*8 + li4*2;
        float2 sv;
        if (Sp){ float2 t = *(const float2*)&Sp[n]; sv = make_float2(t.x*IWSCALE, t.y*IWSCALE); }
        else sv = make_float2(IWSCALE, IWSCALE);
        #pragma unroll
        for (int mi=0; mi<4; mi++){
            int m0 = bm + wr*64 + mi*16 + gi;
            int m1 = m0 + 8;
            if (out_half){
                __half* O = (__half*)outp + (size_t)b*sC;
                if (m0 < M)
                    *(__half2*)(O + (size_t)m0*NPIX + n) =
                        __floats2half2_rn(acc[mi][ni][0]*sv.x, acc[mi][ni][1]*sv.y);
                if (m1 < M)
                    *(__half2*)(O + (size_t)m1*NPIX + n) =
                        __floats2half2_rn(acc[mi][ni][2]*sv.x, acc[mi][ni][3]*sv.y);
            } else {
                float* O = (float*)outp + (size_t)b*sC;
                if (m0 < M){
                    float2 p = make_float2(acc[mi][ni][0]*sv.x, acc[mi][ni][1]*sv.y);
                    *(float2*)(O + (size_t)m0*NPIX + n) = p;
                }
                if (m1 < M){
                    float2 p = make_float2(acc[mi][ni][2]*sv.x, acc[mi][ni][3]*sv.y);
                    *(float2*)(O + (size_t)m1*NPIX + n) = p;
                }
            }
        }
    }
}

// ---------------- depthwise 3x3, full channel image per block + inv-norm ----------------
// DWP=144 halves/row (288B, mult of 16): 8 guard | 128 data | 8 guard
#define DWP 144
__global__ __launch_bounds__(256)
void k_dw2(const float* __restrict__ wd){
    __shared__ __half img[128*DWP];
    __shared__ float wsum[8];
    int bc = blockIdx.x;              // b*C4 + ch
    int ch = bc % C4;
    int b  = bc / C4;
    int tid = threadIdx.x;
    const __half* in = g_qkv + (size_t)bc*NPIX;

    float w[9];
    #pragma unroll
    for (int k=0;k<9;k++) w[k] = __ldg(&wd[ch*9+k]);

    // zero guards (16B aligned)
    for (int r=tid; r<128; r+=256){
        *(uint4*)&img[r*DWP]       = make_uint4(0,0,0,0);
        *(uint4*)&img[r*DWP + 136] = make_uint4(0,0,0,0);
    }
    // load image (coalesced uint4 = 8 halves); data col d at img[r*DWP + 8 + d]
    for (int i=tid; i<2048; i+=256){
        int r = i>>4, c = i&15;
        *(uint4*)&img[r*DWP + 8 + c*8] = ((const uint4*)in)[i];
    }
    __syncthreads();

    __half* op = g_dw + (size_t)bc*NPIX;
    float ssq = 0.f;
    #pragma unroll
    for (int it=0; it<8; it++){
        int idx = it*256 + tid;       // 0..2047
        int r  = idx>>4;
        int x0 = (idx&15)*8;
        float acc[8] = {0.f,0.f,0.f,0.f,0.f,0.f,0.f,0.f};
        #pragma unroll
        for (int dr=-1; dr<=1; dr++){
            int rr = r + dr;
            if ((unsigned)rr < 128u){
                // f[j] = data col (x0-2+j); need cols x0-1 .. x0+8
                const __half* rp = &img[rr*DWP + x0 + 6];
                float f[12];
                #pragma unroll
                for (int j=0;j<6;j++){
                    float2 p = __half22float2(*(const __half2*)(rp + 2*j));
                    f[2*j] = p.x; f[2*j+1] = p.y;
                }
                float w0 = w[(dr+1)*3], w1 = w[(dr+1)*3+1], w2 = w[(dr+1)*3+2];
                #pragma unroll
                for (int u=0;u<8;u++)
                    acc[u] += w0*f[u+1] + w1*f[u+2] + w2*f[u+3];
            }
        }
        __align__(16) __half hv[8];
        #pragma unroll
        for (int u=0;u<8;u++){ hv[u] = __float2half(acc[u]); ssq += acc[u]*acc[u]; }
        ((uint4*)op)[idx] = *(uint4*)hv;
    }

    // inverse L2 norm for q (ch<C) and k (2C<=ch<3C) channels
    int slot = (ch < C) ? 0 : ((ch >= 2*C && ch < 3*C) ? 1 : -1);
    if (slot >= 0){
        #pragma unroll
        for (int o=16;o;o>>=1) ssq += __shfl_xor_sync(~0u, ssq, o);
        if ((tid&31)==0) wsum[tid>>5] = ssq;
        __syncthreads();
        if (tid==0){
            float s = 0.f;
            #pragma unroll
            for (int i=0;i<8;i++) s += wsum[i];
            float inv = 1.f/fmaxf(sqrtf(s), 1e-12f);
            if (slot==0) g_inq[b*C + ch]       = inv;
            else         g_ink[b*C + ch - 2*C] = inv;
        }
    }
}

// ---------------- partial q.k^T over a spatial segment ----------------
__global__ void k_attn_partial(){
    int bh  = blockIdx.x;
    int seg = blockIdx.y;
    int b = bh >> 2, hh = bh & 3;
    const __half* qb = g_dw + ((size_t)b*C4 + hh*HD)*NPIX;
    const __half* kb = g_dw + ((size_t)b*C4 + 2*C + hh*HD)*NPIX;
    __shared__ float qs[HD][65], ks[HD][65];
    int tid = threadIdx.x;
    int tx = tid & 15, ty = tid >> 4;
    float acc[3][3] = {};
    int p0 = seg*SEGLEN;
    for (int ck=0; ck<SEGLEN; ck+=64){
        for (int e=tid; e<HD*64; e+=256){
            int i = e >> 6, p = e & 63;
            qs[i][p] = __half2float(qb[(size_t)i*NPIX + p0 + ck + p]);
            ks[i][p] = __half2float(kb[(size_t)i*NPIX + p0 + ck + p]);
        }
        __syncthreads();
        #pragma unroll 8
        for (int p=0;p<64;p++){
            float q0=qs[ty*3+0][p], q1=qs[ty*3+1][p], q2=qs[ty*3+2][p];
            float k0=ks[tx*3+0][p], k1=ks[tx*3+1][p], k2=ks[tx*3+2][p];
            acc[0][0]+=q0*k0; acc[0][1]+=q0*k1; acc[0][2]+=q0*k2;
            acc[1][0]+=q1*k0; acc[1][1]+=q1*k1; acc[1][2]+=q1*k2;
            acc[2][0]+=q2*k0; acc[2][1]+=q2*k1; acc[2][2]+=q2*k2;
        }
        __syncthreads();
    }
    #pragma unroll
    for (int r=0;r<3;r++)
        #pragma unroll
        for (int s=0;s<3;s++)
            g_spart[((size_t)(bh*NSEG+seg)*HD + ty*3+r)*HD + tx*3+s] = acc[r][s];
}

// ---------------- combine partials, scale, softmax ----------------
__global__ void k_softmax(const float* __restrict__ temp){
    int row = blockIdx.x;
    int bh = row / HD;
    int i  = row - bh*HD;
    int b = bh >> 2, hh = bh & 3;
    int j = threadIdx.x;
    float v = -1e30f;
    if (j < HD){
        float s = 0.f;
        #pragma unroll
        for (int sg=0; sg<NSEG; sg++)
            s += g_spart[((size_t)(bh*NSEG+sg)*HD + i)*HD + j];
        v = s * __ldg(&temp[hh]) * g_inq[b*C + hh*HD + i] * g_ink[b*C + hh*HD + j];
    }
    __shared__ float sh[64];
    sh[j] = v; __syncthreads();
    for (int o=32;o>0;o>>=1){ if (j<o) sh[j]=fmaxf(sh[j],sh[j+o]); __syncthreads(); }
    float m = sh[0]; __syncthreads();
    float e = (j < HD) ? expf(v - m) : 0.f;
    sh[j] = e; __syncthreads();
    for (int o=32;o>0;o>>=1){ if (j<o) sh[j]+=sh[j+o]; __syncthreads(); }
    if (j < HD) g_attn[(size_t)bh*HD*HD + i*HD + j] = e / sh[0];
}

// ---------------- out = (attn @ v) * sigmoid(gate), fp16 out ----------------
__global__ void k_av_gate(){
    int bh = blockIdx.x;
    int b = bh >> 2, hh = bh & 3;
    int p = blockIdx.y*128 + threadIdx.x;
    __shared__ float at[HD][HD];
    for (int e=threadIdx.x; e<HD*HD; e+=128)
        at[e/HD][e%HD] = g_attn[(size_t)bh*HD*HD + e];
    __syncthreads();
    const __half* vb = g_dw + ((size_t)b*C4 + 3*C + hh*HD)*NPIX + p;
    const __half* gb = g_dw + ((size_t)b*C4 + 1*C + hh*HD)*NPIX + p;
    size_t ob = ((size_t)b*C + hh*HD)*NPIX + p;
    float vcol[HD];
    #pragma unroll
    for (int j=0;j<HD;j++) vcol[j] = __half2float(vb[(size_t)j*NPIX]);
    for (int i=0;i<HD;i++){
        float a = 0.f;
        #pragma unroll
        for (int j=0;j<HD;j++) a += at[i][j]*vcol[j];
        float g = __half2float(gb[(size_t)i*NPIX]);
        g_of[ob + (size_t)i*NPIX] = __float2half(a * sigmoidf_(g));
    }
}

// ---------------- host ----------------
extern "C" void kernel_launch(void* const* d_in, const int* in_sizes, int n_in,
                              void* d_out, int out_size){
    const float* x      = (const float*)d_in[0];
    const float* w_fc1  = (const float*)d_in[1];
    const float* w_fc2  = (const float*)d_in[2];
    const float* w_sp   = (const float*)d_in[3];
    const float* w_qkv  = (const float*)d_in[4];
    const float* w_dw   = (const float*)d_in[5];
    const float* w_proj = (const float*)d_in[6];
    const float* temp   = (const float*)d_in[7];
    float* out = (float*)d_out;

    __half *xf, *wqh, *wql, *wph, *wpl, *of, *qkv;
    float *sg;
    cudaGetSymbolAddress((void**)&xf,  g_xf);
    cudaGetSymbolAddress((void**)&wqh, g_wqh);
    cudaGetSymbolAddress((void**)&wql, g_wql);
    cudaGetSymbolAddress((void**)&wph, g_wph);
    cudaGetSymbolAddress((void**)&wpl, g_wpl);
    cudaGetSymbolAddress((void**)&of,  g_of);
    cudaGetSymbolAddress((void**)&qkv, g_qkv);
    cudaGetSymbolAddress((void**)&sg,  g_sg);

    cudaFuncSetAttribute(k_hmma3, cudaFuncAttributeMaxDynamicSharedMemorySize, SMEM3);

    k_stats        <<<dim3(NTILE, NB), 256>>>(x);
    k_chan_gate    <<<NB, 192>>>(w_fc1, w_fc2);
    k_spatial_conv <<<NB*NPIX/256, 256>>>(w_sp);

    k_xcvt    <<<(int)(((size_t)NB*C*NPIX/4)/256), 256>>>(x, xf);
    k_wsplit16<<<(NB*C4*GK/4)/256, 256>>>(w_qkv, wqh, wql);
    k_pwsplit16<<<(C*GK/4 + 255)/256, 256>>>(w_proj, wph, wpl);

    // qkv = sg(p) * ((w_qkv*cg) @ x), fp16 2-pass, half output
    k_hmma3<<<dim3(NPIX/128, 6, NB), 256, SMEM3>>>(
        wqh, wql, (long)C4*GK, xf, qkv, (long)C4*NPIX, 1, sg, C4);

    k_dw2<<<NB*C4, 256>>>(w_dw);     // dw + inverse norms

    k_attn_partial<<<dim3(NB*HEADS, NSEG), 256>>>();
    k_softmax     <<<NB*HEADS*HD, 64>>>(temp);
    k_av_gate     <<<dim3(NB*HEADS, NPIX/128), 128>>>();

    // final projection (batch-shared weights, fp32 output into d_out)
    k_hmma3<<<dim3(NPIX/128, 2, NB), 256, SMEM3>>>(
        wph, wpl, 0L, of, out, (long)C*NPIX, 0, nullptr, C);
}

// round 10
// speedup vs baseline: 2.9800x; 1.2699x over previous
#include <cuda_runtime.h>
#include <cuda_fp16.h>
#include <math.h>
#include <stdint.h>

#define NB    8
#define C     192
#define C2    384
#define C4    768
#define HEADS 4
#define HD    48
#define HW    128
#define NPIX  16384
#define GK    192
#define ASEG  8
#define ASEGLEN (NPIX/ASEG)
#define NTILE 32

// ---------------- scratch (static device memory) ----------------
__device__ float g_cps[NB*NTILE*C];
__device__ float g_cpm[NB*NTILE*C];
__device__ float g_cg [NB*C];
__device__ float g_sp [NB*2*NPIX];
__device__ float g_sg [NB*NPIX];
__device__ __half g_xf [(size_t)NB*C*NPIX];   // x fp16
__device__ __half g_wq [NB*C4*GK];            // gate-folded qkv weights fp16
__device__ __half g_wp [C*GK];                // proj weights fp16
__device__ __half g_qkv[(size_t)NB*C4*NPIX];  // 201 MB
__device__ __half g_dw [(size_t)NB*C4*NPIX];  // 201 MB
__device__ float g_inq [NB*C];
__device__ float g_ink [NB*C];
__device__ float g_spart[(size_t)NB*HEADS*ASEG*HD*HD];
__device__ float g_attn [(size_t)NB*HEADS*HD*HD];
__device__ __half g_of [(size_t)NB*C*NPIX];   // gated attn out fp16

__device__ __forceinline__ float sigmoidf_(float x){ return 1.f/(1.f+expf(-x)); }

__device__ __forceinline__ uint32_t su32(const void* p){
    uint32_t a;
    asm("{ .reg .u64 t; cvta.to.shared.u64 t, %1; cvt.u32.u64 %0, t; }" : "=r"(a) : "l"(p));
    return a;
}
#define CP16(dst, src) \
    asm volatile("cp.async.cg.shared.global [%0], [%1], 16;" :: "r"(dst), "l"(src))

__device__ __forceinline__ void ldm_x4(uint32_t* r, uint32_t addr){
    asm volatile("ldmatrix.sync.aligned.m8n8.x4.shared.b16 {%0,%1,%2,%3}, [%4];"
      : "=r"(r[0]),"=r"(r[1]),"=r"(r[2]),"=r"(r[3]) : "r"(addr));
}
__device__ __forceinline__ void ldm_x2(uint32_t* r, uint32_t addr){
    asm volatile("ldmatrix.sync.aligned.m8n8.x2.shared.b16 {%0,%1}, [%2];"
      : "=r"(r[0]),"=r"(r[1]) : "r"(addr));
}
__device__ __forceinline__ void ldm_x2t(uint32_t* r, uint32_t addr){
    asm volatile("ldmatrix.sync.aligned.m8n8.x2.trans.shared.b16 {%0,%1}, [%2];"
      : "=r"(r[0]),"=r"(r[1]) : "r"(addr));
}
__device__ __forceinline__ void mma16816f(float* c, uint32_t a0, uint32_t a1,
                                          uint32_t a2, uint32_t a3,
                                          uint32_t b0, uint32_t b1){
    asm volatile(
      "mma.sync.aligned.m16n8k16.row.col.f32.f16.f16.f32 "
      "{%0,%1,%2,%3},{%4,%5,%6,%7},{%8,%9},{%0,%1,%2,%3};"
      : "+f"(c[0]), "+f"(c[1]), "+f"(c[2]), "+f"(c[3])
      : "r"(a0), "r"(a1), "r"(a2), "r"(a3), "r"(b0), "r"(b1));
}

// ---------------- K1: one pass over x -> channel partials + pixel stats ----------------
__global__ __launch_bounds__(256)
void k_stats(const float* __restrict__ x){
    __shared__ float sps[8*512], spm[8*512];
    int tile = blockIdx.x, b = blockIdx.y;
    int tid = threadIdx.x, w = tid>>5, lane = tid&31;
    int p0 = tile*512;
    float ps[16], pm[16];
    #pragma unroll
    for (int i=0;i<16;i++){ ps[i]=0.f; pm[i]=-1e30f; }
    for (int ci=0; ci<24; ci++){
        int c = w*24 + ci;
        const float* row = x + ((size_t)b*C + c)*NPIX + p0;
        float cs = 0.f, cm = -1e30f;
        #pragma unroll
        for (int it=0; it<16; it++){
            float v = row[it*32 + lane];
            ps[it] += v; pm[it] = fmaxf(pm[it], v);
            cs += v;     cm = fmaxf(cm, v);
        }
        #pragma unroll
        for (int o=16;o;o>>=1){
            cs += __shfl_xor_sync(~0u, cs, o);
            cm = fmaxf(cm, __shfl_xor_sync(~0u, cm, o));
        }
        if (lane==0){
            g_cps[(b*NTILE + tile)*C + c] = cs;
            g_cpm[(b*NTILE + tile)*C + c] = cm;
        }
    }
    #pragma unroll
    for (int it=0; it<16; it++){
        sps[w*512 + it*32 + lane] = ps[it];
        spm[w*512 + it*32 + lane] = pm[it];
    }
    __syncthreads();
    for (int p=tid; p<512; p+=256){
        float s = 0.f, m = -1e30f;
        #pragma unroll
        for (int ww=0; ww<8; ww++){
            s += sps[ww*512+p];
            m = fmaxf(m, spm[ww*512+p]);
        }
        g_sp[(size_t)b*2*NPIX + p0 + p]        = s*(1.f/C);
        g_sp[(size_t)b*2*NPIX + NPIX + p0 + p] = m;
    }
}

// ---------------- K2: SE channel gate MLP ----------------
__global__ void k_chan_gate(const float* __restrict__ w1, const float* __restrict__ w2){
    int b = blockIdx.x, t = threadIdx.x;
    __shared__ float pool[C2], sq[48];
    {
        float s = 0.f, m = -1e30f;
        for (int tile=0; tile<NTILE; tile++){
            s += g_cps[(b*NTILE + tile)*C + t];
            m = fmaxf(m, g_cpm[(b*NTILE + tile)*C + t]);
        }
        pool[t]   = s*(1.f/NPIX);
        pool[C+t] = m;
    }
    __syncthreads();
    if (t < 48){
        float a = 0.f;
        #pragma unroll 8
        for (int c=0;c<C2;c++) a += w1[t*C2+c]*pool[c];
        sq[t] = fmaxf(a, 0.f);
    }
    __syncthreads();
    float a = 0.f;
    #pragma unroll
    for (int s=0;s<48;s++) a += w2[t*48+s]*sq[s];
    g_cg[b*C+t] = sigmoidf_(a);
}

// ---------------- K3: 7x7 spatial conv + sigmoid ----------------
__global__ void k_spatial_conv(const float* __restrict__ ws){
    int idx = blockIdx.x*256 + threadIdx.x;
    int b = idx >> 14, p = idx & (NPIX-1);
    int y = p >> 7, xx = p & 127;
    float acc = 0.f;
    #pragma unroll
    for (int ch=0; ch<2; ch++){
        const float* base = g_sp + (size_t)b*2*NPIX + (size_t)ch*NPIX;
        #pragma unroll
        for (int dy=-3; dy<=3; dy++){
            int yy = y+dy;
            if ((unsigned)yy < 128u){
                const float* row = base + yy*HW;
                #pragma unroll
                for (int dx=-3; dx<=3; dx++){
                    int xc = xx+dx;
                    if ((unsigned)xc < 128u)
                        acc += row[xc]*__ldg(&ws[ch*49 + (dy+3)*7 + (dx+3)]);
                }
            }
        }
    }
    g_sg[(size_t)b*NPIX + p] = sigmoidf_(acc);
}

// ---------------- conversions ----------------
__global__ void k_xcvt(const float* __restrict__ src, __half* __restrict__ dst){
    size_t i = ((size_t)blockIdx.x*256 + threadIdx.x)*4;
    float4 v = *(const float4*)(src+i);
    __half2 a = __floats2half2_rn(v.x, v.y);
    __half2 b = __floats2half2_rn(v.z, v.w);
    *(uint2*)(dst+i) = make_uint2(*(uint32_t*)&a, *(uint32_t*)&b);
}

__global__ void k_wcvt(const float* __restrict__ w, __half* __restrict__ oh){
    size_t i = ((size_t)blockIdx.x*256 + threadIdx.x)*4;   // NB*C4*GK
    int b  = (int)(i/(C4*GK));
    int rc = (int)(i - (size_t)b*C4*GK);
    int col = rc % GK;
    float4 v = *(const float4*)(w+rc);
    const float* g = g_cg + b*C;
    v.x *= g[col]; v.y *= g[col+1]; v.z *= g[col+2]; v.w *= g[col+3];
    __half2 a = __floats2half2_rn(v.x, v.y);
    __half2 bb = __floats2half2_rn(v.z, v.w);
    *(uint2*)(oh+i) = make_uint2(*(uint32_t*)&a, *(uint32_t*)&bb);
}

__global__ void k_pcvt(const float* __restrict__ w, __half* __restrict__ oh){
    size_t i = ((size_t)blockIdx.x*256 + threadIdx.x)*4;
    float4 v = *(const float4*)(w+i);
    __half2 a = __floats2half2_rn(v.x, v.y);
    __half2 b = __floats2half2_rn(v.z, v.w);
    *(uint2*)(oh+i) = make_uint2(*(uint32_t*)&a, *(uint32_t*)&b);
}

// ================= fp16 HMMA GEMM (single pass), cp.async + ldmatrix =================
// smem: A[128][56] 14336, B[48][136] 13056 = 27392
#define S_A4 0
#define S_B4 14336
#define SMEM4 27392

__global__ __launch_bounds__(256)
void k_hmma4(const __half* __restrict__ Ag, long sA,
             const __half* __restrict__ Bg,
             void* __restrict__ outp, long sC, int out_half,
             const float* __restrict__ S, int M){
    extern __shared__ __align__(16) char smem[];
    uint32_t sb = su32(smem);
    int b = blockIdx.z, bm = blockIdx.y*128, bn = blockIdx.x*128;
    const __half* A = Ag + (size_t)b*sA;
    const __half* B = Bg + (size_t)b*C*NPIX;
    const float* Sp = S ? S + (size_t)b*NPIX : nullptr;

    int tid = threadIdx.x, wid = tid>>5, lane = tid&31;
    int wr = wid>>2, wc = wid&3;
    int gi = lane>>2, li4 = lane&3;

    float acc[4][4][4];
    #pragma unroll
    for (int i=0;i<4;i++)
        #pragma unroll
        for (int j=0;j<4;j++)
            #pragma unroll
            for (int r=0;r<4;r++) acc[i][j][r]=0.f;

    uint32_t aA = sb + S_A4 + (wr*64 + (lane&15))*112 + (lane>>4)*16;
    uint32_t bA = sb + S_B4 + (lane&15)*272 + wc*64;

    for (int c0=0; c0<GK; c0+=48){
        for (int e=tid; e<768; e+=256){
            int r = e/6, ch = e - (e/6)*6;
            int m = bm + r; if (m >= M) m = M-1;
            CP16(sb + S_A4 + r*112 + ch*16, (const char*)(A + (size_t)m*GK + c0) + ch*16);
        }
        for (int e=tid; e<768; e+=256){
            int k = e>>4, ch = e&15;
            CP16(sb + S_B4 + k*272 + ch*16, (const char*)(B + (size_t)(c0+k)*NPIX + bn) + ch*16);
        }
        asm volatile("cp.async.commit_group;" ::: "memory");
        asm volatile("cp.async.wait_group 0;" ::: "memory");
        __syncthreads();

        #pragma unroll
        for (int ks=0; ks<3; ks++){
            uint32_t Af[4][4], Bf[4][2];
            #pragma unroll
            for (int mi=0; mi<4; mi++) ldm_x4(Af[mi], aA + mi*1792 + ks*32);
            #pragma unroll
            for (int ni=0; ni<4; ni++) ldm_x2t(Bf[ni], bA + ks*4352 + ni*16);
            #pragma unroll
            for (int mi=0; mi<4; mi++)
                #pragma unroll
                for (int ni=0; ni<4; ni++)
                    mma16816f(acc[mi][ni], Af[mi][0],Af[mi][1],Af[mi][2],Af[mi][3],
                              Bf[ni][0],Bf[ni][1]);
        }
        __syncthreads();
    }

    #pragma unroll
    for (int ni=0; ni<4; ni++){
        int n = bn + wc*32 + ni*8 + li4*2;
        float2 sv = Sp ? *(const float2*)&Sp[n] : make_float2(1.f,1.f);
        #pragma unroll
        for (int mi=0; mi<4; mi++){
            int m0 = bm + wr*64 + mi*16 + gi;
            int m1 = m0 + 8;
            if (out_half){
                __half* O = (__half*)outp + (size_t)b*sC;
                if (m0 < M)
                    *(__half2*)(O + (size_t)m0*NPIX + n) =
                        __floats2half2_rn(acc[mi][ni][0]*sv.x, acc[mi][ni][1]*sv.y);
                if (m1 < M)
                    *(__half2*)(O + (size_t)m1*NPIX + n) =
                        __floats2half2_rn(acc[mi][ni][2]*sv.x, acc[mi][ni][3]*sv.y);
            } else {
                float* O = (float*)outp + (size_t)b*sC;
                if (m0 < M){
                    float2 p = make_float2(acc[mi][ni][0]*sv.x, acc[mi][ni][1]*sv.y);
                    *(float2*)(O + (size_t)m0*NPIX + n) = p;
                }
                if (m1 < M){
                    float2 p = make_float2(acc[mi][ni][2]*sv.x, acc[mi][ni][3]*sv.y);
                    *(float2*)(O + (size_t)m1*NPIX + n) = p;
                }
            }
        }
    }
}

// ---------------- depthwise 3x3, full channel image per block + inv-norm ----------------
#define DWP 144
__global__ __launch_bounds__(256)
void k_dw2(const float* __restrict__ wd){
    __shared__ __half img[128*DWP];
    __shared__ float wsum[8];
    int bc = blockIdx.x;
    int ch = bc % C4;
    int b  = bc / C4;
    int tid = threadIdx.x;
    const __half* in = g_qkv + (size_t)bc*NPIX;

    float w[9];
    #pragma unroll
    for (int k=0;k<9;k++) w[k] = __ldg(&wd[ch*9+k]);

    for (int r=tid; r<128; r+=256){
        *(uint4*)&img[r*DWP]       = make_uint4(0,0,0,0);
        *(uint4*)&img[r*DWP + 136] = make_uint4(0,0,0,0);
    }
    for (int i=tid; i<2048; i+=256){
        int r = i>>4, c = i&15;
        *(uint4*)&img[r*DWP + 8 + c*8] = ((const uint4*)in)[i];
    }
    __syncthreads();

    __half* op = g_dw + (size_t)bc*NPIX;
    float ssq = 0.f;
    #pragma unroll
    for (int it=0; it<8; it++){
        int idx = it*256 + tid;
        int r  = idx>>4;
        int x0 = (idx&15)*8;
        float acc[8] = {0.f,0.f,0.f,0.f,0.f,0.f,0.f,0.f};
        #pragma unroll
        for (int dr=-1; dr<=1; dr++){
            int rr = r + dr;
            if ((unsigned)rr < 128u){
                const __half* rp = &img[rr*DWP + x0 + 6];
                float f[12];
                #pragma unroll
                for (int j=0;j<6;j++){
                    float2 p = __half22float2(*(const __half2*)(rp + 2*j));
                    f[2*j] = p.x; f[2*j+1] = p.y;
                }
                float w0 = w[(dr+1)*3], w1 = w[(dr+1)*3+1], w2 = w[(dr+1)*3+2];
                #pragma unroll
                for (int u=0;u<8;u++)
                    acc[u] += w0*f[u+1] + w1*f[u+2] + w2*f[u+3];
            }
        }
        __align__(16) __half hv[8];
        #pragma unroll
        for (int u=0;u<8;u++){ hv[u] = __float2half(acc[u]); ssq += acc[u]*acc[u]; }
        ((uint4*)op)[idx] = *(uint4*)hv;
    }

    int slot = (ch < C) ? 0 : ((ch >= 2*C && ch < 3*C) ? 1 : -1);
    if (slot >= 0){
        #pragma unroll
        for (int o=16;o;o>>=1) ssq += __shfl_xor_sync(~0u, ssq, o);
        if ((tid&31)==0) wsum[tid>>5] = ssq;
        __syncthreads();
        if (tid==0){
            float s = 0.f;
            #pragma unroll
            for (int i=0;i<8;i++) s += wsum[i];
            float inv = 1.f/fmaxf(sqrtf(s), 1e-12f);
            if (slot==0) g_inq[b*C + ch]       = inv;
            else         g_ink[b*C + ch - 2*C] = inv;
        }
    }
}

// ---------------- q.k^T partials on tensor cores ----------------
// grid (32, ASEG); 8 warps, warps 0-5 each own an n8 strip of the 48x48 gram.
__global__ __launch_bounds__(256)
void k_attn_mma(){
    __shared__ __half qs[48*72];
    __shared__ __half ks[48*72];
    int bh = blockIdx.x, seg = blockIdx.y;
    int b = bh>>2, hh = bh&3;
    const __half* qb = g_dw + ((size_t)b*C4 + hh*HD)*NPIX + seg*ASEGLEN;
    const __half* kb = g_dw + ((size_t)b*C4 + 2*C + hh*HD)*NPIX + seg*ASEGLEN;
    int tid = threadIdx.x, wid = tid>>5, lane = tid&31;
    uint32_t qsb = su32(qs), ksb = su32(ks);
    int n0 = wid*8;

    float acc[3][4];
    #pragma unroll
    for (int mi=0;mi<3;mi++)
        #pragma unroll
        for (int r=0;r<4;r++) acc[mi][r]=0.f;

    uint32_t aAddr = qsb + ((lane&15)*72 + (lane>>4)*8)*2;
    uint32_t bAddr = ksb + (((n0 + (lane&7))*72) + (((lane>>3)&1)*8))*2;

    for (int ck=0; ck<ASEGLEN/64; ck++){
        for (int e=tid; e<768; e+=256){
            int which = e>=384;
            int idx = e - which*384;
            int r = idx>>3, c8 = idx&7;
            const __half* src = (which? kb : qb) + (size_t)r*NPIX + ck*64 + c8*8;
            __half* dst = (which? ks : qs) + r*72 + c8*8;
            *(uint4*)dst = *(const uint4*)src;
        }
        __syncthreads();
        if (wid < 6){
            #pragma unroll
            for (int kst=0; kst<4; kst++){
                uint32_t Bf[2];
                ldm_x2(Bf, bAddr + kst*32);
                #pragma unroll
                for (int mi=0; mi<3; mi++){
                    uint32_t Af[4];
                    ldm_x4(Af, aAddr + mi*16*144 + kst*32);
                    mma16816f(acc[mi], Af[0],Af[1],Af[2],Af[3], Bf[0],Bf[1]);
                }
            }
        }
        __syncthreads();
    }
    if (wid < 6){
        int gi = lane>>2, li4 = lane&3;
        float* dst = g_spart + (size_t)(bh*ASEG+seg)*HD*HD;
        #pragma unroll
        for (int mi=0; mi<3; mi++){
            int r0 = mi*16 + gi;
            int cc = n0 + li4*2;
            dst[r0*HD+cc]     = acc[mi][0];
            dst[r0*HD+cc+1]   = acc[mi][1];
            dst[(r0+8)*HD+cc]   = acc[mi][2];
            dst[(r0+8)*HD+cc+1] = acc[mi][3];
        }
    }
}

// ---------------- combine partials, scale, softmax ----------------
__global__ void k_softmax(const float* __restrict__ temp){
    int row = blockIdx.x;
    int bh = row / HD;
    int i  = row - bh*HD;
    int b = bh >> 2, hh = bh & 3;
    int j = threadIdx.x;
    float v = -1e30f;
    if (j < HD){
        float s = 0.f;
        #pragma unroll
        for (int sg=0; sg<ASEG; sg++)
            s += g_spart[((size_t)(bh*ASEG+sg)*HD + i)*HD + j];
        v = s * __ldg(&temp[hh]) * g_inq[b*C + hh*HD + i] * g_ink[b*C + hh*HD + j];
    }
    __shared__ float sh[64];
    sh[j] = v; __syncthreads();
    for (int o=32;o>0;o>>=1){ if (j<o) sh[j]=fmaxf(sh[j],sh[j+o]); __syncthreads(); }
    float m = sh[0]; __syncthreads();
    float e = (j < HD) ? expf(v - m) : 0.f;
    sh[j] = e; __syncthreads();
    for (int o=32;o>0;o>>=1){ if (j<o) sh[j]+=sh[j+o]; __syncthreads(); }
    if (j < HD) g_attn[(size_t)bh*HD*HD + i*HD + j] = e / sh[0];
}

// ---------------- (attn @ v) * sigmoid(gate) on tensor cores ----------------
// grid (32, 64): per block 256 px. attn fp16 in smem (A), v [k][n] trans-ldmatrix (B).
#define AVP 264
__global__ __launch_bounds__(256)
void k_av_mma(){
    __shared__ __half at_s[48*56];
    __shared__ __half vs[48*AVP];
    int bh = blockIdx.x, pt = blockIdx.y;
    int b = bh>>2, hh = bh&3;
    int p0 = pt*256;
    int tid = threadIdx.x, wid = tid>>5, lane = tid&31;
    uint32_t atb = su32(at_s), vsb = su32(vs);

    const float* ap = g_attn + (size_t)bh*HD*HD;
    for (int e=tid; e<2304; e+=256){
        int i = e/48, j = e - (e/48)*48;
        at_s[i*56+j] = __float2half(ap[e]);
    }
    const __half* vb = g_dw + ((size_t)b*C4 + 3*C + hh*HD)*NPIX + p0;
    for (int e=tid; e<1536; e+=256){
        int r = e>>5, c = e&31;
        *(uint4*)&vs[r*AVP + c*8] = *(const uint4*)(vb + (size_t)r*NPIX + c*8);
    }
    __syncthreads();

    // hoist A fragments: 3 m-tiles x 3 k-steps
    uint32_t Af[3][3][4];
    #pragma unroll
    for (int mi=0; mi<3; mi++)
        #pragma unroll
        for (int kst=0; kst<3; kst++)
            ldm_x4(Af[mi][kst], atb + ((mi*16 + (lane&15))*56 + kst*16 + (lane>>4)*8)*2);

    const __half* gb = g_dw + ((size_t)b*C4 + C + hh*HD)*NPIX + p0;
    __half* ob = g_of + ((size_t)b*C + hh*HD)*NPIX + p0;
    int gi = lane>>2, li4 = lane&3;

    #pragma unroll
    for (int ni=0; ni<4; ni++){
        int n0 = wid*32 + ni*8;
        float acc[3][4];
        #pragma unroll
        for (int mi=0;mi<3;mi++)
            #pragma unroll
            for (int r=0;r<4;r++) acc[mi][r]=0.f;
        #pragma unroll
        for (int kst=0; kst<3; kst++){
            uint32_t Bf[2];
            ldm_x2t(Bf, vsb + ((kst*16 + (lane&15))*AVP + n0)*2);
            #pragma unroll
            for (int mi=0; mi<3; mi++)
                mma16816f(acc[mi], Af[mi][kst][0],Af[mi][kst][1],Af[mi][kst][2],Af[mi][kst][3],
                          Bf[0],Bf[1]);
        }
        #pragma unroll
        for (int mi=0; mi<3; mi++){
            int r0 = mi*16 + gi;
            int cc = n0 + li4*2;
            float2 g0 = __half22float2(*(const __half2*)(gb + (size_t)r0*NPIX + cc));
            *(__half2*)(ob + (size_t)r0*NPIX + cc) =
                __floats2half2_rn(acc[mi][0]*sigmoidf_(g0.x), acc[mi][1]*sigmoidf_(g0.y));
            float2 g1 = __half22float2(*(const __half2*)(gb + (size_t)(r0+8)*NPIX + cc));
            *(__half2*)(ob + (size_t)(r0+8)*NPIX + cc) =
                __floats2half2_rn(acc[mi][2]*sigmoidf_(g1.x), acc[mi][3]*sigmoidf_(g1.y));
        }
    }
}

// ---------------- host ----------------
extern "C" void kernel_launch(void* const* d_in, const int* in_sizes, int n_in,
                              void* d_out, int out_size){
    const float* x      = (const float*)d_in[0];
    const float* w_fc1  = (const float*)d_in[1];
    const float* w_fc2  = (const float*)d_in[2];
    const float* w_sp   = (const float*)d_in[3];
    const float* w_qkv  = (const float*)d_in[4];
    const float* w_dw   = (const float*)d_in[5];
    const float* w_proj = (const float*)d_in[6];
    const float* temp   = (const float*)d_in[7];
    float* out = (float*)d_out;

    __half *xf, *wq, *wp, *qkv;
    float *sg;
    cudaGetSymbolAddress((void**)&xf,  g_xf);
    cudaGetSymbolAddress((void**)&wq,  g_wq);
    cudaGetSymbolAddress((void**)&wp,  g_wp);
    cudaGetSymbolAddress((void**)&qkv, g_qkv);
    cudaGetSymbolAddress((void**)&sg,  g_sg);
    __half* of;
    cudaGetSymbolAddress((void**)&of,  g_of);

    cudaFuncSetAttribute(k_hmma4, cudaFuncAttributeMaxDynamicSharedMemorySize, SMEM4);

    k_stats        <<<dim3(NTILE, NB), 256>>>(x);
    k_chan_gate    <<<NB, 192>>>(w_fc1, w_fc2);
    k_spatial_conv <<<NB*NPIX/256, 256>>>(w_sp);

    k_xcvt<<<(int)(((size_t)NB*C*NPIX/4)/256), 256>>>(x, xf);
    k_wcvt<<<(NB*C4*GK/4)/256, 256>>>(w_qkv, wq);
    k_pcvt<<<(C*GK/4 + 255)/256, 256>>>(w_proj, wp);

    // qkv = sg(p) * ((w_qkv*cg) @ x), fp16 single-pass, half output
    k_hmma4<<<dim3(NPIX/128, 6, NB), 256, SMEM4>>>(
        wq, (long)C4*GK, xf, qkv, (long)C4*NPIX, 1, sg, C4);

    k_dw2<<<NB*C4, 256>>>(w_dw);     // dw + inverse norms

    k_attn_mma<<<dim3(NB*HEADS, ASEG), 256>>>();
    k_softmax  <<<NB*HEADS*HD, 64>>>(temp);
    k_av_mma   <<<dim3(NB*HEADS, NPIX/256), 256>>>();

    // final projection (batch-shared weights, fp32 output into d_out)
    k_hmma4<<<dim3(NPIX/128, 2, NB), 256, SMEM4>>>(
        wp, 0L, of, out, (long)C*NPIX, 0, nullptr, C);
}

// round 11
// speedup vs baseline: 3.5782x; 1.2007x over previous
#include <cuda_runtime.h>
#include <cuda_fp16.h>
#include <math.h>
#include <stdint.h>

#define NB    8
#define C     192
#define C2    384
#define C4    768
#define HEADS 4
#define HD    48
#define HW    128
#define NPIX  16384
#define GK    192
#define ASEG  8
#define ASEGLEN (NPIX/ASEG)
#define NTILE 32

// ---------------- scratch (static device memory) ----------------
__device__ float g_cps[NB*NTILE*C];
__device__ float g_cpm[NB*NTILE*C];
__device__ float g_cg [NB*C];
__device__ float g_sp [NB*2*NPIX];
__device__ float g_sg [NB*NPIX];
__device__ __half g_xf [(size_t)NB*C*NPIX];   // x fp16 (written by k_stats)
__device__ __half g_wq [NB*C4*GK];            // gate-folded qkv weights fp16
__device__ __half g_wp [C*GK];                // proj weights fp16
__device__ __half g_qkv[(size_t)NB*C4*NPIX];  // 201 MB
__device__ __half g_dw [(size_t)NB*C4*NPIX];  // 201 MB
__device__ float g_inq [NB*C];
__device__ float g_ink [NB*C];
__device__ float g_spart[(size_t)NB*HEADS*ASEG*HD*HD];
__device__ float g_attn [(size_t)NB*HEADS*HD*HD];
__device__ __half g_of [(size_t)NB*C*NPIX];   // gated attn out fp16

__device__ __forceinline__ float sigmoidf_(float x){ return 1.f/(1.f+expf(-x)); }

__device__ __forceinline__ uint32_t su32(const void* p){
    uint32_t a;
    asm("{ .reg .u64 t; cvta.to.shared.u64 t, %1; cvt.u32.u64 %0, t; }" : "=r"(a) : "l"(p));
    return a;
}
#define CP16(dst, src) \
    asm volatile("cp.async.cg.shared.global [%0], [%1], 16;" :: "r"(dst), "l"(src))

__device__ __forceinline__ void ldm_x4(uint32_t* r, uint32_t addr){
    asm volatile("ldmatrix.sync.aligned.m8n8.x4.shared.b16 {%0,%1,%2,%3}, [%4];"
      : "=r"(r[0]),"=r"(r[1]),"=r"(r[2]),"=r"(r[3]) : "r"(addr));
}
__device__ __forceinline__ void ldm_x2(uint32_t* r, uint32_t addr){
    asm volatile("ldmatrix.sync.aligned.m8n8.x2.shared.b16 {%0,%1}, [%2];"
      : "=r"(r[0]),"=r"(r[1]) : "r"(addr));
}
__device__ __forceinline__ void ldm_x2t(uint32_t* r, uint32_t addr){
    asm volatile("ldmatrix.sync.aligned.m8n8.x2.trans.shared.b16 {%0,%1}, [%2];"
      : "=r"(r[0]),"=r"(r[1]) : "r"(addr));
}
__device__ __forceinline__ void mma16816f(float* c, uint32_t a0, uint32_t a1,
                                          uint32_t a2, uint32_t a3,
                                          uint32_t b0, uint32_t b1){
    asm volatile(
      "mma.sync.aligned.m16n8k16.row.col.f32.f16.f16.f32 "
      "{%0,%1,%2,%3},{%4,%5,%6,%7},{%8,%9},{%0,%1,%2,%3};"
      : "+f"(c[0]), "+f"(c[1]), "+f"(c[2]), "+f"(c[3])
      : "r"(a0), "r"(a1), "r"(a2), "r"(a3), "r"(b0), "r"(b1));
}

// ---------------- K1: one pass over x -> stats + fp16 copy ----------------
__global__ __launch_bounds__(256)
void k_stats(const float* __restrict__ x, __half* __restrict__ xf){
    __shared__ float sps[8*512], spm[8*512];
    int tile = blockIdx.x, b = blockIdx.y;
    int tid = threadIdx.x, w = tid>>5, lane = tid&31;
    int p0 = tile*512;
    float ps[16], pm[16];
    #pragma unroll
    for (int i=0;i<16;i++){ ps[i]=0.f; pm[i]=-1e30f; }
    for (int ci=0; ci<24; ci++){
        int c = w*24 + ci;
        size_t rowoff = ((size_t)b*C + c)*NPIX + p0;
        const float* row = x + rowoff;
        __half* orow = xf + rowoff;
        float cs = 0.f, cm = -1e30f;
        #pragma unroll
        for (int it=0; it<16; it++){
            float v = row[it*32 + lane];
            orow[it*32 + lane] = __float2half(v);
            ps[it] += v; pm[it] = fmaxf(pm[it], v);
            cs += v;     cm = fmaxf(cm, v);
        }
        #pragma unroll
        for (int o=16;o;o>>=1){
            cs += __shfl_xor_sync(~0u, cs, o);
            cm = fmaxf(cm, __shfl_xor_sync(~0u, cm, o));
        }
        if (lane==0){
            g_cps[(b*NTILE + tile)*C + c] = cs;
            g_cpm[(b*NTILE + tile)*C + c] = cm;
        }
    }
    #pragma unroll
    for (int it=0; it<16; it++){
        sps[w*512 + it*32 + lane] = ps[it];
        spm[w*512 + it*32 + lane] = pm[it];
    }
    __syncthreads();
    for (int p=tid; p<512; p+=256){
        float s = 0.f, m = -1e30f;
        #pragma unroll
        for (int ww=0; ww<8; ww++){
            s += sps[ww*512+p];
            m = fmaxf(m, spm[ww*512+p]);
        }
        g_sp[(size_t)b*2*NPIX + p0 + p]        = s*(1.f/C);
        g_sp[(size_t)b*2*NPIX + NPIX + p0 + p] = m;
    }
}

// ---------------- K2: SE channel gate MLP ----------------
__global__ void k_chan_gate(const float* __restrict__ w1, const float* __restrict__ w2){
    int b = blockIdx.x, t = threadIdx.x;
    __shared__ float pool[C2], sq[48];
    {
        float s = 0.f, m = -1e30f;
        for (int tile=0; tile<NTILE; tile++){
            s += g_cps[(b*NTILE + tile)*C + t];
            m = fmaxf(m, g_cpm[(b*NTILE + tile)*C + t]);
        }
        pool[t]   = s*(1.f/NPIX);
        pool[C+t] = m;
    }
    __syncthreads();
    if (t < 48){
        float a = 0.f;
        #pragma unroll 8
        for (int c=0;c<C2;c++) a += w1[t*C2+c]*pool[c];
        sq[t] = fmaxf(a, 0.f);
    }
    __syncthreads();
    float a = 0.f;
    #pragma unroll
    for (int s=0;s<48;s++) a += w2[t*48+s]*sq[s];
    g_cg[b*C+t] = sigmoidf_(a);
}

// ---------------- K3: 7x7 spatial conv + sigmoid ----------------
__global__ void k_spatial_conv(const float* __restrict__ ws){
    int idx = blockIdx.x*256 + threadIdx.x;
    int b = idx >> 14, p = idx & (NPIX-1);
    int y = p >> 7, xx = p & 127;
    float acc = 0.f;
    #pragma unroll
    for (int ch=0; ch<2; ch++){
        const float* base = g_sp + (size_t)b*2*NPIX + (size_t)ch*NPIX;
        #pragma unroll
        for (int dy=-3; dy<=3; dy++){
            int yy = y+dy;
            if ((unsigned)yy < 128u){
                const float* row = base + yy*HW;
                #pragma unroll
                for (int dx=-3; dx<=3; dx++){
                    int xc = xx+dx;
                    if ((unsigned)xc < 128u)
                        acc += row[xc]*__ldg(&ws[ch*49 + (dy+3)*7 + (dx+3)]);
                }
            }
        }
    }
    g_sg[(size_t)b*NPIX + p] = sigmoidf_(acc);
}

// ---------------- weight conversions ----------------
__global__ void k_wcvt(const float* __restrict__ w, __half* __restrict__ oh){
    size_t i = ((size_t)blockIdx.x*256 + threadIdx.x)*4;   // NB*C4*GK
    int b  = (int)(i/(C4*GK));
    int rc = (int)(i - (size_t)b*C4*GK);
    int col = rc % GK;
    float4 v = *(const float4*)(w+rc);
    const float* g = g_cg + b*C;
    v.x *= g[col]; v.y *= g[col+1]; v.z *= g[col+2]; v.w *= g[col+3];
    __half2 a = __floats2half2_rn(v.x, v.y);
    __half2 bb = __floats2half2_rn(v.z, v.w);
    *(uint2*)(oh+i) = make_uint2(*(uint32_t*)&a, *(uint32_t*)&bb);
}

__global__ void k_pcvt(const float* __restrict__ w, __half* __restrict__ oh){
    size_t i = ((size_t)blockIdx.x*256 + threadIdx.x)*4;
    float4 v = *(const float4*)(w+i);
    __half2 a = __floats2half2_rn(v.x, v.y);
    __half2 b = __floats2half2_rn(v.z, v.w);
    *(uint2*)(oh+i) = make_uint2(*(uint32_t*)&a, *(uint32_t*)&b);
}

// ================= fp16 HMMA GEMM, B-panel resident in smem =================
// smem: A[128][200h=400B] 51200, B[192][272B] 52224 -> 103424 bytes
#define S_A5 0
#define S_B5 51200
#define SMEM5 103424

__global__ __launch_bounds__(256)
void k_hmma5(const __half* __restrict__ Ag, long sA,
             const __half* __restrict__ Bg,
             void* __restrict__ outp, long sC, int out_half,
             const float* __restrict__ S, int M, int Mtiles){
    extern __shared__ __align__(16) char smem[];
    uint32_t sb = su32(smem);
    int b = blockIdx.x & 7, bn = (blockIdx.x >> 3)*128;
    const __half* A = Ag + (size_t)b*sA;
    const __half* B = Bg + (size_t)b*C*NPIX;
    const float* Sp = S ? S + (size_t)b*NPIX : nullptr;

    int tid = threadIdx.x, wid = tid>>5, lane = tid&31;
    int wr = wid>>2, wc = wid&3;
    int gi = lane>>2, li4 = lane&3;

    // stage B once: 192 rows x 256B (16 chunks)
    for (int e=tid; e<3072; e+=256){
        int k = e>>4, ch = e&15;
        CP16(sb + S_B5 + k*272 + ch*16, (const char*)(B + (size_t)k*NPIX + bn) + ch*16);
    }
    asm volatile("cp.async.commit_group;" ::: "memory");

    uint32_t aA = sb + S_A5 + (wr*64 + (lane&15))*400 + (lane>>4)*16;
    uint32_t bA = sb + S_B5 + (lane&15)*272 + wc*64;

    for (int ot=0; ot<Mtiles; ot++){
        int bm = ot*128;
        // stage A tile: 128 rows x 384B (24 chunks)
        for (int e=tid; e<3072; e+=256){
            int r = e/24, ch = e - (e/24)*24;
            int m = bm + r; if (m >= M) m = M-1;
            CP16(sb + S_A5 + r*400 + ch*16, (const char*)(A + (size_t)m*GK) + ch*16);
        }
        asm volatile("cp.async.commit_group;" ::: "memory");
        asm volatile("cp.async.wait_group 0;" ::: "memory");
        __syncthreads();

        float acc[4][4][4];
        #pragma unroll
        for (int i=0;i<4;i++)
            #pragma unroll
            for (int j=0;j<4;j++)
                #pragma unroll
                for (int r=0;r<4;r++) acc[i][j][r]=0.f;

        #pragma unroll
        for (int ks=0; ks<12; ks++){
            uint32_t Af[4][4], Bf[4][2];
            #pragma unroll
            for (int mi=0; mi<4; mi++) ldm_x4(Af[mi], aA + mi*6400 + ks*32);
            #pragma unroll
            for (int ni=0; ni<4; ni++) ldm_x2t(Bf[ni], bA + ks*4352 + ni*16);
            #pragma unroll
            for (int mi=0; mi<4; mi++)
                #pragma unroll
                for (int ni=0; ni<4; ni++)
                    mma16816f(acc[mi][ni], Af[mi][0],Af[mi][1],Af[mi][2],Af[mi][3],
                              Bf[ni][0],Bf[ni][1]);
        }
        __syncthreads();   // A smem reused next m-tile

        #pragma unroll
        for (int ni=0; ni<4; ni++){
            int n = bn + wc*32 + ni*8 + li4*2;
            float2 sv = Sp ? *(const float2*)&Sp[n] : make_float2(1.f,1.f);
            #pragma unroll
            for (int mi=0; mi<4; mi++){
                int m0 = bm + wr*64 + mi*16 + gi;
                int m1 = m0 + 8;
                if (out_half){
                    __half* O = (__half*)outp + (size_t)b*sC;
                    if (m0 < M)
                        *(__half2*)(O + (size_t)m0*NPIX + n) =
                            __floats2half2_rn(acc[mi][ni][0]*sv.x, acc[mi][ni][1]*sv.y);
                    if (m1 < M)
                        *(__half2*)(O + (size_t)m1*NPIX + n) =
                            __floats2half2_rn(acc[mi][ni][2]*sv.x, acc[mi][ni][3]*sv.y);
                } else {
                    float* O = (float*)outp + (size_t)b*sC;
                    if (m0 < M){
                        float2 p = make_float2(acc[mi][ni][0]*sv.x, acc[mi][ni][1]*sv.y);
                        *(float2*)(O + (size_t)m0*NPIX + n) = p;
                    }
                    if (m1 < M){
                        float2 p = make_float2(acc[mi][ni][2]*sv.x, acc[mi][ni][3]*sv.y);
                        *(float2*)(O + (size_t)m1*NPIX + n) = p;
                    }
                }
            }
        }
    }
}

// ---------------- depthwise 3x3, full channel image per block + inv-norm ----------------
#define DWP 144
__global__ __launch_bounds__(256)
void k_dw2(const float* __restrict__ wd){
    __shared__ __half img[128*DWP];
    __shared__ float wsum[8];
    int bc = blockIdx.x;
    int ch = bc % C4;
    int b  = bc / C4;
    int tid = threadIdx.x;
    const __half* in = g_qkv + (size_t)bc*NPIX;

    float w[9];
    #pragma unroll
    for (int k=0;k<9;k++) w[k] = __ldg(&wd[ch*9+k]);

    for (int r=tid; r<128; r+=256){
        *(uint4*)&img[r*DWP]       = make_uint4(0,0,0,0);
        *(uint4*)&img[r*DWP + 136] = make_uint4(0,0,0,0);
    }
    for (int i=tid; i<2048; i+=256){
        int r = i>>4, c = i&15;
        *(uint4*)&img[r*DWP + 8 + c*8] = ((const uint4*)in)[i];
    }
    __syncthreads();

    __half* op = g_dw + (size_t)bc*NPIX;
    float ssq = 0.f;
    #pragma unroll
    for (int it=0; it<8; it++){
        int idx = it*256 + tid;
        int r  = idx>>4;
        int x0 = (idx&15)*8;
        float acc[8] = {0.f,0.f,0.f,0.f,0.f,0.f,0.f,0.f};
        #pragma unroll
        for (int dr=-1; dr<=1; dr++){
            int rr = r + dr;
            if ((unsigned)rr < 128u){
                const __half* rp = &img[rr*DWP + x0 + 6];
                float f[12];
                #pragma unroll
                for (int j=0;j<6;j++){
                    float2 p = __half22float2(*(const __half2*)(rp + 2*j));
                    f[2*j] = p.x; f[2*j+1] = p.y;
                }
                float w0 = w[(dr+1)*3], w1 = w[(dr+1)*3+1], w2 = w[(dr+1)*3+2];
                #pragma unroll
                for (int u=0;u<8;u++)
                    acc[u] += w0*f[u+1] + w1*f[u+2] + w2*f[u+3];
            }
        }
        __align__(16) __half hv[8];
        #pragma unroll
        for (int u=0;u<8;u++){ hv[u] = __float2half(acc[u]); ssq += acc[u]*acc[u]; }
        ((uint4*)op)[idx] = *(uint4*)hv;
    }

    int slot = (ch < C) ? 0 : ((ch >= 2*C && ch < 3*C) ? 1 : -1);
    if (slot >= 0){
        #pragma unroll
        for (int o=16;o;o>>=1) ssq += __shfl_xor_sync(~0u, ssq, o);
        if ((tid&31)==0) wsum[tid>>5] = ssq;
        __syncthreads();
        if (tid==0){
            float s = 0.f;
            #pragma unroll
            for (int i=0;i<8;i++) s += wsum[i];
            float inv = 1.f/fmaxf(sqrtf(s), 1e-12f);
            if (slot==0) g_inq[b*C + ch]       = inv;
            else         g_ink[b*C + ch - 2*C] = inv;
        }
    }
}

// ---------------- q.k^T partials on tensor cores ----------------
__global__ __launch_bounds__(256)
void k_attn_mma(){
    __shared__ __half qs[48*72];
    __shared__ __half ks[48*72];
    int bh = blockIdx.x, seg = blockIdx.y;
    int b = bh>>2, hh = bh&3;
    const __half* qb = g_dw + ((size_t)b*C4 + hh*HD)*NPIX + seg*ASEGLEN;
    const __half* kb = g_dw + ((size_t)b*C4 + 2*C + hh*HD)*NPIX + seg*ASEGLEN;
    int tid = threadIdx.x, wid = tid>>5, lane = tid&31;
    uint32_t qsb = su32(qs), ksb = su32(ks);
    int n0 = wid*8;

    float acc[3][4];
    #pragma unroll
    for (int mi=0;mi<3;mi++)
        #pragma unroll
        for (int r=0;r<4;r++) acc[mi][r]=0.f;

    uint32_t aAddr = qsb + ((lane&15)*72 + (lane>>4)*8)*2;
    uint32_t bAddr = ksb + (((n0 + (lane&7))*72) + (((lane>>3)&1)*8))*2;

    for (int ck=0; ck<ASEGLEN/64; ck++){
        for (int e=tid; e<768; e+=256){
            int which = e>=384;
            int idx = e - which*384;
            int r = idx>>3, c8 = idx&7;
            const __half* src = (which? kb : qb) + (size_t)r*NPIX + ck*64 + c8*8;
            __half* dst = (which? ks : qs) + r*72 + c8*8;
            *(uint4*)dst = *(const uint4*)src;
        }
        __syncthreads();
        if (wid < 6){
            #pragma unroll
            for (int kst=0; kst<4; kst++){
                uint32_t Bf[2];
                ldm_x2(Bf, bAddr + kst*32);
                #pragma unroll
                for (int mi=0; mi<3; mi++){
                    uint32_t Af[4];
                    ldm_x4(Af, aAddr + mi*16*144 + kst*32);
                    mma16816f(acc[mi], Af[0],Af[1],Af[2],Af[3], Bf[0],Bf[1]);
                }
            }
        }
        __syncthreads();
    }
    if (wid < 6){
        int gi = lane>>2, li4 = lane&3;
        float* dst = g_spart + (size_t)(bh*ASEG+seg)*HD*HD;
        #pragma unroll
        for (int mi=0; mi<3; mi++){
            int r0 = mi*16 + gi;
            int cc = n0 + li4*2;
            dst[r0*HD+cc]     = acc[mi][0];
            dst[r0*HD+cc+1]   = acc[mi][1];
            dst[(r0+8)*HD+cc]   = acc[mi][2];
            dst[(r0+8)*HD+cc+1] = acc[mi][3];
        }
    }
}

// ---------------- combine partials, scale, softmax ----------------
__global__ void k_softmax(const float* __restrict__ temp){
    int row = blockIdx.x;
    int bh = row / HD;
    int i  = row - bh*HD;
    int b = bh >> 2, hh = bh & 3;
    int j = threadIdx.x;
    float v = -1e30f;
    if (j < HD){
        float s = 0.f;
        #pragma unroll
        for (int sg=0; sg<ASEG; sg++)
            s += g_spart[((size_t)(bh*ASEG+sg)*HD + i)*HD + j];
        v = s * __ldg(&temp[hh]) * g_inq[b*C + hh*HD + i] * g_ink[b*C + hh*HD + j];
    }
    __shared__ float sh[64];
    sh[j] = v; __syncthreads();
    for (int o=32;o>0;o>>=1){ if (j<o) sh[j]=fmaxf(sh[j],sh[j+o]); __syncthreads(); }
    float m = sh[0]; __syncthreads();
    float e = (j < HD) ? expf(v - m) : 0.f;
    sh[j] = e; __syncthreads();
    for (int o=32;o>0;o>>=1){ if (j<o) sh[j]+=sh[j+o]; __syncthreads(); }
    if (j < HD) g_attn[(size_t)bh*HD*HD + i*HD + j] = e / sh[0];
}

// ---------------- (attn @ v) * sigmoid(gate) on tensor cores ----------------
#define AVP 264
__global__ __launch_bounds__(256)
void k_av_mma(){
    __shared__ __half at_s[48*56];
    __shared__ __half vs[48*AVP];
    int bh = blockIdx.x, pt = blockIdx.y;
    int b = bh>>2, hh = bh&3;
    int p0 = pt*256;
    int tid = threadIdx.x, wid = tid>>5, lane = tid&31;
    uint32_t atb = su32(at_s), vsb = su32(vs);

    const float* ap = g_attn + (size_t)bh*HD*HD;
    for (int e=tid; e<2304; e+=256){
        int i = e/48, j = e - (e/48)*48;
        at_s[i*56+j] = __float2half(ap[e]);
    }
    const __half* vb = g_dw + ((size_t)b*C4 + 3*C + hh*HD)*NPIX + p0;
    for (int e=tid; e<1536; e+=256){
        int r = e>>5, c = e&31;
        *(uint4*)&vs[r*AVP + c*8] = *(const uint4*)(vb + (size_t)r*NPIX + c*8);
    }
    __syncthreads();

    uint32_t Af[3][3][4];
    #pragma unroll
    for (int mi=0; mi<3; mi++)
        #pragma unroll
        for (int kst=0; kst<3; kst++)
            ldm_x4(Af[mi][kst], atb + ((mi*16 + (lane&15))*56 + kst*16 + (lane>>4)*8)*2);

    const __half* gb = g_dw + ((size_t)b*C4 + C + hh*HD)*NPIX + p0;
    __half* ob = g_of + ((size_t)b*C + hh*HD)*NPIX + p0;
    int gi = lane>>2, li4 = lane&3;

    #pragma unroll
    for (int ni=0; ni<4; ni++){
        int n0 = wid*32 + ni*8;
        float acc[3][4];
        #pragma unroll
        for (int mi=0;mi<3;mi++)
            #pragma unroll
            for (int r=0;r<4;r++) acc[mi][r]=0.f;
        #pragma unroll
        for (int kst=0; kst<3; kst++){
            uint32_t Bf[2];
            ldm_x2t(Bf, vsb + ((kst*16 + (lane&15))*AVP + n0)*2);
            #pragma unroll
            for (int mi=0; mi<3; mi++)
                mma16816f(acc[mi], Af[mi][kst][0],Af[mi][kst][1],Af[mi][kst][2],Af[mi][kst][3],
                          Bf[0],Bf[1]);
        }
        #pragma unroll
        for (int mi=0; mi<3; mi++){
            int r0 = mi*16 + gi;
            int cc = n0 + li4*2;
            float2 g0 = __half22float2(*(const __half2*)(gb + (size_t)r0*NPIX + cc));
            *(__half2*)(ob + (size_t)r0*NPIX + cc) =
                __floats2half2_rn(acc[mi][0]*sigmoidf_(g0.x), acc[mi][1]*sigmoidf_(g0.y));
            float2 g1 = __half22float2(*(const __half2*)(gb + (size_t)(r0+8)*NPIX + cc));
            *(__half2*)(ob + (size_t)(r0+8)*NPIX + cc) =
                __floats2half2_rn(acc[mi][2]*sigmoidf_(g1.x), acc[mi][3]*sigmoidf_(g1.y));
        }
    }
}

// ---------------- host ----------------
extern "C" void kernel_launch(void* const* d_in, const int* in_sizes, int n_in,
                              void* d_out, int out_size){
    const float* x      = (const float*)d_in[0];
    const float* w_fc1  = (const float*)d_in[1];
    const float* w_fc2  = (const float*)d_in[2];
    const float* w_sp   = (const float*)d_in[3];
    const float* w_qkv  = (const float*)d_in[4];
    const float* w_dw   = (const float*)d_in[5];
    const float* w_proj = (const float*)d_in[6];
    const float* temp   = (const float*)d_in[7];
    float* out = (float*)d_out;

    __half *xf, *wq, *wp, *qkv, *of;
    float *sg;
    cudaGetSymbolAddress((void**)&xf,  g_xf);
    cudaGetSymbolAddress((void**)&wq,  g_wq);
    cudaGetSymbolAddress((void**)&wp,  g_wp);
    cudaGetSymbolAddress((void**)&qkv, g_qkv);
    cudaGetSymbolAddress((void**)&sg,  g_sg);
    cudaGetSymbolAddress((void**)&of,  g_of);

    cudaFuncSetAttribute(k_hmma5, cudaFuncAttributeMaxDynamicSharedMemorySize, SMEM5);

    k_stats        <<<dim3(NTILE, NB), 256>>>(x, xf);   // stats + x->fp16
    k_chan_gate    <<<NB, 192>>>(w_fc1, w_fc2);
    k_spatial_conv <<<NB*NPIX/256, 256>>>(w_sp);

    k_wcvt<<<(NB*C4*GK/4)/256, 256>>>(w_qkv, wq);
    k_pcvt<<<(C*GK/4 + 255)/256, 256>>>(w_proj, wp);

    // qkv = sg(p) * ((w_qkv*cg) @ x), B-resident fp16 GEMM, half output
    k_hmma5<<<NB*(NPIX/128), 256, SMEM5>>>(
        wq, (long)C4*GK, xf, qkv, (long)C4*NPIX, 1, sg, C4, 6);

    k_dw2<<<NB*C4, 256>>>(w_dw);     // dw + inverse norms

    k_attn_mma<<<dim3(NB*HEADS, ASEG), 256>>>();
    k_softmax  <<<NB*HEADS*HD, 64>>>(temp);
    k_av_mma   <<<dim3(NB*HEADS, NPIX/256), 256>>>();

    // final projection (batch-shared weights, fp32 output into d_out)
    k_hmma5<<<NB*(NPIX/128), 256, SMEM5>>>(
        wp, 0L, of, out, (long)C*NPIX, 0, nullptr, C, 2);
}

// round 12
// speedup vs baseline: 4.2528x; 1.1886x over previous
#include <cuda_runtime.h>
#include <cuda_fp16.h>
#include <math.h>
#include <stdint.h>

#define NB    8
#define C     192
#define C2    384
#define C4    768
#define HEADS 4
#define HD    48
#define HW    128
#define NPIX  16384
#define GK    192
#define ASEG  8
#define ASEGLEN (NPIX/ASEG)
#define NTILE 64              // x-stat tiles of 256 px

// ---------------- scratch (static device memory) ----------------
__device__ float g_cps[NB*NTILE*C];
__device__ float g_cpm[NB*NTILE*C];
__device__ float g_cg [NB*C];
__device__ float g_sp [NB*2*NPIX];
__device__ float g_sg [NB*NPIX];
__device__ __half g_xf [(size_t)NB*C*NPIX];   // x fp16 (written by k_stats)
__device__ __half g_wq [NB*C4*GK];            // gate-folded qkv weights fp16
__device__ __half g_wp [C*GK];                // proj weights fp16
__device__ __half g_qkv[(size_t)NB*C4*NPIX];  // 201 MB
__device__ __half g_dw [(size_t)NB*C4*NPIX];  // 201 MB
__device__ float g_inq [NB*C];
__device__ float g_ink [NB*C];
__device__ float g_spart[(size_t)NB*HEADS*ASEG*HD*HD];
__device__ float g_attn [(size_t)NB*HEADS*HD*HD];
__device__ __half g_of [(size_t)NB*C*NPIX];   // gated attn out fp16

__device__ __forceinline__ float sigmoidf_(float x){ return 1.f/(1.f+expf(-x)); }

__device__ __forceinline__ uint32_t su32(const void* p){
    uint32_t a;
    asm("{ .reg .u64 t; cvta.to.shared.u64 t, %1; cvt.u32.u64 %0, t; }" : "=r"(a) : "l"(p));
    return a;
}
#define CP16(dst, src) \
    asm volatile("cp.async.cg.shared.global [%0], [%1], 16;" :: "r"(dst), "l"(src))

__device__ __forceinline__ void ldm_x4(uint32_t* r, uint32_t addr){
    asm volatile("ldmatrix.sync.aligned.m8n8.x4.shared.b16 {%0,%1,%2,%3}, [%4];"
      : "=r"(r[0]),"=r"(r[1]),"=r"(r[2]),"=r"(r[3]) : "r"(addr));
}
__device__ __forceinline__ void ldm_x2(uint32_t* r, uint32_t addr){
    asm volatile("ldmatrix.sync.aligned.m8n8.x2.shared.b16 {%0,%1}, [%2];"
      : "=r"(r[0]),"=r"(r[1]) : "r"(addr));
}
__device__ __forceinline__ void ldm_x2t(uint32_t* r, uint32_t addr){
    asm volatile("ldmatrix.sync.aligned.m8n8.x2.trans.shared.b16 {%0,%1}, [%2];"
      : "=r"(r[0]),"=r"(r[1]) : "r"(addr));
}
__device__ __forceinline__ void mma16816f(float* c, uint32_t a0, uint32_t a1,
                                          uint32_t a2, uint32_t a3,
                                          uint32_t b0, uint32_t b1){
    asm volatile(
      "mma.sync.aligned.m16n8k16.row.col.f32.f16.f16.f32 "
      "{%0,%1,%2,%3},{%4,%5,%6,%7},{%8,%9},{%0,%1,%2,%3};"
      : "+f"(c[0]), "+f"(c[1]), "+f"(c[2]), "+f"(c[3])
      : "r"(a0), "r"(a1), "r"(a2), "r"(a3), "r"(b0), "r"(b1));
}

// ---------------- K1: one pass over x -> stats + fp16 copy ----------------
__global__ __launch_bounds__(256)
void k_stats(const float* __restrict__ x, __half* __restrict__ xf){
    __shared__ float sps[8*256], spm[8*256];
    int tile = blockIdx.x, b = blockIdx.y;
    int tid = threadIdx.x, w = tid>>5, lane = tid&31;
    int p0 = tile*256;
    float ps[8], pm[8];
    #pragma unroll
    for (int i=0;i<8;i++){ ps[i]=0.f; pm[i]=-1e30f; }
    for (int ci=0; ci<24; ci++){
        int c = w*24 + ci;
        size_t rowoff = ((size_t)b*C + c)*NPIX + p0;
        const float* row = x + rowoff;
        __half* orow = xf + rowoff;
        float cs = 0.f, cm = -1e30f;
        #pragma unroll
        for (int it=0; it<8; it++){
            float v = row[it*32 + lane];
            orow[it*32 + lane] = __float2half(v);
            ps[it] += v; pm[it] = fmaxf(pm[it], v);
            cs += v;     cm = fmaxf(cm, v);
        }
        #pragma unroll
        for (int o=16;o;o>>=1){
            cs += __shfl_xor_sync(~0u, cs, o);
            cm = fmaxf(cm, __shfl_xor_sync(~0u, cm, o));
        }
        if (lane==0){
            g_cps[(b*NTILE + tile)*C + c] = cs;
            g_cpm[(b*NTILE + tile)*C + c] = cm;
        }
    }
    #pragma unroll
    for (int it=0; it<8; it++){
        sps[w*256 + it*32 + lane] = ps[it];
        spm[w*256 + it*32 + lane] = pm[it];
    }
    __syncthreads();
    if (tid < 256){
        int p = tid;
        float s = 0.f, m = -1e30f;
        #pragma unroll
        for (int ww=0; ww<8; ww++){
            s += sps[ww*256+p];
            m = fmaxf(m, spm[ww*256+p]);
        }
        g_sp[(size_t)b*2*NPIX + p0 + p]        = s*(1.f/C);
        g_sp[(size_t)b*2*NPIX + NPIX + p0 + p] = m;
    }
}

// ---------------- K2: SE channel gate MLP ----------------
__global__ void k_chan_gate(const float* __restrict__ w1, const float* __restrict__ w2){
    int b = blockIdx.x, t = threadIdx.x;
    __shared__ float pool[C2], sq[48];
    {
        float s = 0.f, m = -1e30f;
        for (int tile=0; tile<NTILE; tile++){
            s += g_cps[(b*NTILE + tile)*C + t];
            m = fmaxf(m, g_cpm[(b*NTILE + tile)*C + t]);
        }
        pool[t]   = s*(1.f/NPIX);
        pool[C+t] = m;
    }
    __syncthreads();
    if (t < 48){
        float a = 0.f;
        #pragma unroll 8
        for (int c=0;c<C2;c++) a += w1[t*C2+c]*pool[c];
        sq[t] = fmaxf(a, 0.f);
    }
    __syncthreads();
    float a = 0.f;
    #pragma unroll
    for (int s=0;s<48;s++) a += w2[t*48+s]*sq[s];
    g_cg[b*C+t] = sigmoidf_(a);
}

// ---------------- K3: 7x7 spatial conv + sigmoid ----------------
__global__ void k_spatial_conv(const float* __restrict__ ws){
    int idx = blockIdx.x*256 + threadIdx.x;
    int b = idx >> 14, p = idx & (NPIX-1);
    int y = p >> 7, xx = p & 127;
    float acc = 0.f;
    #pragma unroll
    for (int ch=0; ch<2; ch++){
        const float* base = g_sp + (size_t)b*2*NPIX + (size_t)ch*NPIX;
        #pragma unroll
        for (int dy=-3; dy<=3; dy++){
            int yy = y+dy;
            if ((unsigned)yy < 128u){
                const float* row = base + yy*HW;
                #pragma unroll
                for (int dx=-3; dx<=3; dx++){
                    int xc = xx+dx;
                    if ((unsigned)xc < 128u)
                        acc += row[xc]*__ldg(&ws[ch*49 + (dy+3)*7 + (dx+3)]);
                }
            }
        }
    }
    g_sg[(size_t)b*NPIX + p] = sigmoidf_(acc);
}

// ---------------- weight conversions ----------------
__global__ void k_wcvt(const float* __restrict__ w, __half* __restrict__ oh){
    size_t i = ((size_t)blockIdx.x*256 + threadIdx.x)*4;   // NB*C4*GK
    int b  = (int)(i/(C4*GK));
    int rc = (int)(i - (size_t)b*C4*GK);
    int col = rc % GK;
    float4 v = *(const float4*)(w+rc);
    const float* g = g_cg + b*C;
    v.x *= g[col]; v.y *= g[col+1]; v.z *= g[col+2]; v.w *= g[col+3];
    __half2 a = __floats2half2_rn(v.x, v.y);
    __half2 bb = __floats2half2_rn(v.z, v.w);
    *(uint2*)(oh+i) = make_uint2(*(uint32_t*)&a, *(uint32_t*)&bb);
}

__global__ void k_pcvt(const float* __restrict__ w, __half* __restrict__ oh){
    size_t i = ((size_t)blockIdx.x*256 + threadIdx.x)*4;
    float4 v = *(const float4*)(w+i);
    __half2 a = __floats2half2_rn(v.x, v.y);
    __half2 b = __floats2half2_rn(v.z, v.w);
    *(uint2*)(oh+i) = make_uint2(*(uint32_t*)&a, *(uint32_t*)&b);
}

// ================= fp16 HMMA GEMM, B-resident + pipelined A (ping-pong) =================
// smem: A 2x[64][400B] = 51200, B[192][272B] = 52224 -> 103424
#define S_A6 0
#define A6SZ 25600
#define S_B6 51200
#define SMEM6 103424

__global__ __launch_bounds__(256)
void k_hmma6(const __half* __restrict__ Ag, long sA,
             const __half* __restrict__ Bg,
             void* __restrict__ outp, long sC, int out_half,
             const float* __restrict__ S, int M, int Mtiles){
    extern __shared__ __align__(16) char smem[];
    uint32_t sb = su32(smem);
    int b = blockIdx.x & 7, bn = (blockIdx.x >> 3)*128;
    const __half* A = Ag + (size_t)b*sA;
    const __half* B = Bg + (size_t)b*C*NPIX;
    const float* Sp = S ? S + (size_t)b*NPIX : nullptr;

    int tid = threadIdx.x, wid = tid>>5, lane = tid&31;
    int wr = wid>>2, wc = wid&3;     // 2 row-groups x 4 col-groups
    int gi = lane>>2, li4 = lane&3;

    // stage B once (group)
    for (int e=tid; e<3072; e+=256){
        int k = e>>4, ch = e&15;
        CP16(sb + S_B6 + k*272 + ch*16, (const char*)(B + (size_t)k*NPIX + bn) + ch*16);
    }
    asm volatile("cp.async.commit_group;" ::: "memory");

    // stage A tile 0 (group)
    {
        for (int e=tid; e<1536; e+=256){
            int r = e/24, ch = e - (e/24)*24;
            int m = r; if (m >= M) m = M-1;
            CP16(sb + S_A6 + r*400 + ch*16, (const char*)(A + (size_t)m*GK) + ch*16);
        }
        asm volatile("cp.async.commit_group;" ::: "memory");
    }

    uint32_t aBase = sb + S_A6 + ((wr*32 + (lane&15))*400) + (lane>>4)*16;
    uint32_t bA    = sb + S_B6 + (lane&15)*272 + wc*64;

    for (int ot=0; ot<Mtiles; ot++){
        // prefetch next A tile into the other buffer
        if (ot+1 < Mtiles){
            int bm1 = (ot+1)*64;
            uint32_t dstb = sb + S_A6 + ((ot+1)&1)*A6SZ;
            for (int e=tid; e<1536; e+=256){
                int r = e/24, ch = e - (e/24)*24;
                int m = bm1 + r; if (m >= M) m = M-1;
                CP16(dstb + r*400 + ch*16, (const char*)(A + (size_t)m*GK) + ch*16);
            }
            asm volatile("cp.async.commit_group;" ::: "memory");
            asm volatile("cp.async.wait_group 1;" ::: "memory");
        } else {
            asm volatile("cp.async.wait_group 0;" ::: "memory");
        }
        __syncthreads();

        uint32_t aA = aBase + (ot&1)*A6SZ;
        float acc[2][4][4];
        #pragma unroll
        for (int i=0;i<2;i++)
            #pragma unroll
            for (int j=0;j<4;j++)
                #pragma unroll
                for (int r=0;r<4;r++) acc[i][j][r]=0.f;

        #pragma unroll
        for (int ks=0; ks<12; ks++){
            uint32_t Af[2][4], Bf[4][2];
            #pragma unroll
            for (int mi=0; mi<2; mi++) ldm_x4(Af[mi], aA + mi*6400 + ks*32);
            #pragma unroll
            for (int ni=0; ni<4; ni++) ldm_x2t(Bf[ni], bA + ks*4352 + ni*16);
            #pragma unroll
            for (int mi=0; mi<2; mi++)
                #pragma unroll
                for (int ni=0; ni<4; ni++)
                    mma16816f(acc[mi][ni], Af[mi][0],Af[mi][1],Af[mi][2],Af[mi][3],
                              Bf[ni][0],Bf[ni][1]);
        }

        int bm = ot*64;
        #pragma unroll
        for (int ni=0; ni<4; ni++){
            int n = bn + wc*32 + ni*8 + li4*2;
            float2 sv = Sp ? *(const float2*)&Sp[n] : make_float2(1.f,1.f);
            #pragma unroll
            for (int mi=0; mi<2; mi++){
                int m0 = bm + wr*32 + mi*16 + gi;
                int m1 = m0 + 8;
                if (out_half){
                    __half* O = (__half*)outp + (size_t)b*sC;
                    if (m0 < M)
                        *(__half2*)(O + (size_t)m0*NPIX + n) =
                            __floats2half2_rn(acc[mi][ni][0]*sv.x, acc[mi][ni][1]*sv.y);
                    if (m1 < M)
                        *(__half2*)(O + (size_t)m1*NPIX + n) =
                            __floats2half2_rn(acc[mi][ni][2]*sv.x, acc[mi][ni][3]*sv.y);
                } else {
                    float* O = (float*)outp + (size_t)b*sC;
                    if (m0 < M){
                        float2 p = make_float2(acc[mi][ni][0]*sv.x, acc[mi][ni][1]*sv.y);
                        *(float2*)(O + (size_t)m0*NPIX + n) = p;
                    }
                    if (m1 < M){
                        float2 p = make_float2(acc[mi][ni][2]*sv.x, acc[mi][ni][3]*sv.y);
                        *(float2*)(O + (size_t)m1*NPIX + n) = p;
                    }
                }
            }
        }
        __syncthreads();   // protect A buffer reuse (next-next prefetch)
    }
}

// ---------------- depthwise 3x3, full channel image per block + inv-norm ----------------
#define DWP 144
__global__ __launch_bounds__(256)
void k_dw2(const float* __restrict__ wd){
    __shared__ __half img[128*DWP];
    __shared__ float wsum[8];
    int bc = blockIdx.x;
    int ch = bc % C4;
    int b  = bc / C4;
    int tid = threadIdx.x;
    const __half* in = g_qkv + (size_t)bc*NPIX;

    float w[9];
    #pragma unroll
    for (int k=0;k<9;k++) w[k] = __ldg(&wd[ch*9+k]);

    for (int r=tid; r<128; r+=256){
        *(uint4*)&img[r*DWP]       = make_uint4(0,0,0,0);
        *(uint4*)&img[r*DWP + 136] = make_uint4(0,0,0,0);
    }
    for (int i=tid; i<2048; i+=256){
        int r = i>>4, c = i&15;
        *(uint4*)&img[r*DWP + 8 + c*8] = ((const uint4*)in)[i];
    }
    __syncthreads();

    __half* op = g_dw + (size_t)bc*NPIX;
    float ssq = 0.f;
    #pragma unroll
    for (int it=0; it<8; it++){
        int idx = it*256 + tid;
        int r  = idx>>4;
        int x0 = (idx&15)*8;
        float acc[8] = {0.f,0.f,0.f,0.f,0.f,0.f,0.f,0.f};
        #pragma unroll
        for (int dr=-1; dr<=1; dr++){
            int rr = r + dr;
            if ((unsigned)rr < 128u){
                const __half* rp = &img[rr*DWP + x0 + 6];
                float f[12];
                #pragma unroll
                for (int j=0;j<6;j++){
                    float2 p = __half22float2(*(const __half2*)(rp + 2*j));
                    f[2*j] = p.x; f[2*j+1] = p.y;
                }
                float w0 = w[(dr+1)*3], w1 = w[(dr+1)*3+1], w2 = w[(dr+1)*3+2];
                #pragma unroll
                for (int u=0;u<8;u++)
                    acc[u] += w0*f[u+1] + w1*f[u+2] + w2*f[u+3];
            }
        }
        __align__(16) __half hv[8];
        #pragma unroll
        for (int u=0;u<8;u++){ hv[u] = __float2half(acc[u]); ssq += acc[u]*acc[u]; }
        ((uint4*)op)[idx] = *(uint4*)hv;
    }

    int slot = (ch < C) ? 0 : ((ch >= 2*C && ch < 3*C) ? 1 : -1);
    if (slot >= 0){
        #pragma unroll
        for (int o=16;o;o>>=1) ssq += __shfl_xor_sync(~0u, ssq, o);
        if ((tid&31)==0) wsum[tid>>5] = ssq;
        __syncthreads();
        if (tid==0){
            float s = 0.f;
            #pragma unroll
            for (int i=0;i<8;i++) s += wsum[i];
            float inv = 1.f/fmaxf(sqrtf(s), 1e-12f);
            if (slot==0) g_inq[b*C + ch]       = inv;
            else         g_ink[b*C + ch - 2*C] = inv;
        }
    }
}

// ---------------- q.k^T partials on tensor cores ----------------
__global__ __launch_bounds__(256)
void k_attn_mma(){
    __shared__ __half qs[48*72];
    __shared__ __half ks[48*72];
    int bh = blockIdx.x, seg = blockIdx.y;
    int b = bh>>2, hh = bh&3;
    const __half* qb = g_dw + ((size_t)b*C4 + hh*HD)*NPIX + seg*ASEGLEN;
    const __half* kb = g_dw + ((size_t)b*C4 + 2*C + hh*HD)*NPIX + seg*ASEGLEN;
    int tid = threadIdx.x, wid = tid>>5, lane = tid&31;
    uint32_t qsb = su32(qs), ksb = su32(ks);
    int n0 = wid*8;

    float acc[3][4];
    #pragma unroll
    for (int mi=0;mi<3;mi++)
        #pragma unroll
        for (int r=0;r<4;r++) acc[mi][r]=0.f;

    uint32_t aAddr = qsb + ((lane&15)*72 + (lane>>4)*8)*2;
    uint32_t bAddr = ksb + (((n0 + (lane&7))*72) + (((lane>>3)&1)*8))*2;

    for (int ck=0; ck<ASEGLEN/64; ck++){
        for (int e=tid; e<768; e+=256){
            int which = e>=384;
            int idx = e - which*384;
            int r = idx>>3, c8 = idx&7;
            const __half* src = (which? kb : qb) + (size_t)r*NPIX + ck*64 + c8*8;
            __half* dst = (which? ks : qs) + r*72 + c8*8;
            *(uint4*)dst = *(const uint4*)src;
        }
        __syncthreads();
        if (wid < 6){
            #pragma unroll
            for (int kst=0; kst<4; kst++){
                uint32_t Bf[2];
                ldm_x2(Bf, bAddr + kst*32);
                #pragma unroll
                for (int mi=0; mi<3; mi++){
                    uint32_t Af[4];
                    ldm_x4(Af, aAddr + mi*16*144 + kst*32);
                    mma16816f(acc[mi], Af[0],Af[1],Af[2],Af[3], Bf[0],Bf[1]);
                }
            }
        }
        __syncthreads();
    }
    if (wid < 6){
        int gi = lane>>2, li4 = lane&3;
        float* dst = g_spart + (size_t)(bh*ASEG+seg)*HD*HD;
        #pragma unroll
        for (int mi=0; mi<3; mi++){
            int r0 = mi*16 + gi;
            int cc = n0 + li4*2;
            dst[r0*HD+cc]     = acc[mi][0];
            dst[r0*HD+cc+1]   = acc[mi][1];
            dst[(r0+8)*HD+cc]   = acc[mi][2];
            dst[(r0+8)*HD+cc+1] = acc[mi][3];
        }
    }
}

// ---------------- combine partials, scale, softmax ----------------
__global__ void k_softmax(const float* __restrict__ temp){
    int row = blockIdx.x;
    int bh = row / HD;
    int i  = row - bh*HD;
    int b = bh >> 2, hh = bh & 3;
    int j = threadIdx.x;
    float v = -1e30f;
    if (j < HD){
        float s = 0.f;
        #pragma unroll
        for (int sg=0; sg<ASEG; sg++)
            s += g_spart[((size_t)(bh*ASEG+sg)*HD + i)*HD + j];
        v = s * __ldg(&temp[hh]) * g_inq[b*C + hh*HD + i] * g_ink[b*C + hh*HD + j];
    }
    __shared__ float sh[64];
    sh[j] = v; __syncthreads();
    for (int o=32;o>0;o>>=1){ if (j<o) sh[j]=fmaxf(sh[j],sh[j+o]); __syncthreads(); }
    float m = sh[0]; __syncthreads();
    float e = (j < HD) ? expf(v - m) : 0.f;
    sh[j] = e; __syncthreads();
    for (int o=32;o>0;o>>=1){ if (j<o) sh[j]+=sh[j+o]; __syncthreads(); }
    if (j < HD) g_attn[(size_t)bh*HD*HD + i*HD + j] = e / sh[0];
}

// ---------------- (attn @ v) * sigmoid(gate) on tensor cores ----------------
#define AVP 264
__global__ __launch_bounds__(256)
void k_av_mma(){
    __shared__ __half at_s[48*56];
    __shared__ __half vs[48*AVP];
    int bh = blockIdx.x, pt = blockIdx.y;
    int b = bh>>2, hh = bh&3;
    int p0 = pt*256;
    int tid = threadIdx.x, wid = tid>>5, lane = tid&31;
    uint32_t atb = su32(at_s), vsb = su32(vs);

    const float* ap = g_attn + (size_t)bh*HD*HD;
    for (int e=tid; e<2304; e+=256){
        int i = e/48, j = e - (e/48)*48;
        at_s[i*56+j] = __float2half(ap[e]);
    }
    const __half* vb = g_dw + ((size_t)b*C4 + 3*C + hh*HD)*NPIX + p0;
    for (int e=tid; e<1536; e+=256){
        int r = e>>5, c = e&31;
        *(uint4*)&vs[r*AVP + c*8] = *(const uint4*)(vb + (size_t)r*NPIX + c*8);
    }
    __syncthreads();

    uint32_t Af[3][3][4];
    #pragma unroll
    for (int mi=0; mi<3; mi++)
        #pragma unroll
        for (int kst=0; kst<3; kst++)
            ldm_x4(Af[mi][kst], atb + ((mi*16 + (lane&15))*56 + kst*16 + (lane>>4)*8)*2);

    const __half* gb = g_dw + ((size_t)b*C4 + C + hh*HD)*NPIX + p0;
    __half* ob = g_of + ((size_t)b*C + hh*HD)*NPIX + p0;
    int gi = lane>>2, li4 = lane&3;

    #pragma unroll
    for (int ni=0; ni<4; ni++){
        int n0 = wid*32 + ni*8;
        float acc[3][4];
        #pragma unroll
        for (int mi=0;mi<3;mi++)
            #pragma unroll
            for (int r=0;r<4;r++) acc[mi][r]=0.f;
        #pragma unroll
        for (int kst=0; kst<3; kst++){
            uint32_t Bf[2];
            ldm_x2t(Bf, vsb + ((kst*16 + (lane&15))*AVP + n0)*2);
            #pragma unroll
            for (int mi=0; mi<3; mi++)
                mma16816f(acc[mi], Af[mi][kst][0],Af[mi][kst][1],Af[mi][kst][2],Af[mi][kst][3],
                          Bf[0],Bf[1]);
        }
        #pragma unroll
        for (int mi=0; mi<3; mi++){
            int r0 = mi*16 + gi;
            int cc = n0 + li4*2;
            float2 g0 = __half22float2(*(const __half2*)(gb + (size_t)r0*NPIX + cc));
            *(__half2*)(ob + (size_t)r0*NPIX + cc) =
                __floats2half2_rn(acc[mi][0]*sigmoidf_(g0.x), acc[mi][1]*sigmoidf_(g0.y));
            float2 g1 = __half22float2(*(const __half2*)(gb + (size_t)(r0+8)*NPIX + cc));
            *(__half2*)(ob + (size_t)(r0+8)*NPIX + cc) =
                __floats2half2_rn(acc[mi][2]*sigmoidf_(g1.x), acc[mi][3]*sigmoidf_(g1.y));
        }
    }
}

// ---------------- host ----------------
extern "C" void kernel_launch(void* const* d_in, const int* in_sizes, int n_in,
                              void* d_out, int out_size){
    const float* x      = (const float*)d_in[0];
    const float* w_fc1  = (const float*)d_in[1];
    const float* w_fc2  = (const float*)d_in[2];
    const float* w_sp   = (const float*)d_in[3];
    const float* w_qkv  = (const float*)d_in[4];
    const float* w_dw   = (const float*)d_in[5];
    const float* w_proj = (const float*)d_in[6];
    const float* temp   = (const float*)d_in[7];
    float* out = (float*)d_out;

    __half *xf, *wq, *wp, *qkv, *of;
    float *sg;
    cudaGetSymbolAddress((void**)&xf,  g_xf);
    cudaGetSymbolAddress((void**)&wq,  g_wq);
    cudaGetSymbolAddress((void**)&wp,  g_wp);
    cudaGetSymbolAddress((void**)&qkv, g_qkv);
    cudaGetSymbolAddress((void**)&sg,  g_sg);
    cudaGetSymbolAddress((void**)&of,  g_of);

    cudaFuncSetAttribute(k_hmma6, cudaFuncAttributeMaxDynamicSharedMemorySize, SMEM6);

    k_stats        <<<dim3(NTILE, NB), 256>>>(x, xf);   // stats + x->fp16
    k_chan_gate    <<<NB, 192>>>(w_fc1, w_fc2);
    k_spatial_conv <<<NB*NPIX/256, 256>>>(w_sp);

    k_wcvt<<<(NB*C4*GK/4)/256, 256>>>(w_qkv, wq);
    k_pcvt<<<(C*GK/4 + 255)/256, 256>>>(w_proj, wp);

    // qkv = sg(p) * ((w_qkv*cg) @ x), pipelined B-resident fp16 GEMM, half output
    k_hmma6<<<NB*(NPIX/128), 256, SMEM6>>>(
        wq, (long)C4*GK, xf, qkv, (long)C4*NPIX, 1, sg, C4, 12);

    k_dw2<<<NB*C4, 256>>>(w_dw);     // dw + inverse norms

    k_attn_mma<<<dim3(NB*HEADS, ASEG), 256>>>();
    k_softmax  <<<NB*HEADS*HD, 64>>>(temp);
    k_av_mma   <<<dim3(NB*HEADS, NPIX/256), 256>>>();

    // final projection (batch-shared weights, fp32 output into d_out)
    k_hmma6<<<NB*(NPIX/128), 256, SMEM6>>>(
        wp, 0L, of, out, (long)C*NPIX, 0, nullptr, C, 3);
}

// round 13
// speedup vs baseline: 4.4625x; 1.0493x over previous
#include <cuda_runtime.h>
#include <cuda_fp16.h>
#include <math.h>
#include <stdint.h>

#define NB    8
#define C     192
#define C2    384
#define C4    768
#define HEADS 4
#define HD    48
#define HW    128
#define NPIX  16384
#define GK    192
#define ASEG  8
#define ASEGLEN (NPIX/ASEG)
#define NTILE 64

// ---------------- scratch (static device memory) ----------------
__device__ float g_cps[NB*NTILE*C];
__device__ float g_cpm[NB*NTILE*C];
__device__ float g_cg [NB*C];
__device__ float g_sp [NB*2*NPIX];
__device__ float g_sg [NB*NPIX];
__device__ __half g_xf [(size_t)NB*C*NPIX];
__device__ __half g_wq [NB*C4*GK];
__device__ __half g_wp [C*GK];
__device__ __half g_qkv[(size_t)NB*C4*NPIX];
__device__ __half g_dw [(size_t)NB*C4*NPIX];
__device__ float g_inq [NB*C];
__device__ float g_ink [NB*C];
__device__ float g_spart[(size_t)NB*HEADS*ASEG*HD*HD];
__device__ float g_attn [(size_t)NB*HEADS*HD*HD];

__device__ __forceinline__ float sigmoidf_(float x){ return 1.f/(1.f+expf(-x)); }

__device__ __forceinline__ uint32_t su32(const void* p){
    uint32_t a;
    asm("{ .reg .u64 t; cvta.to.shared.u64 t, %1; cvt.u32.u64 %0, t; }" : "=r"(a) : "l"(p));
    return a;
}
#define CP16(dst, src) \
    asm volatile("cp.async.cg.shared.global [%0], [%1], 16;" :: "r"(dst), "l"(src))

__device__ __forceinline__ void ldm_x4(uint32_t* r, uint32_t addr){
    asm volatile("ldmatrix.sync.aligned.m8n8.x4.shared.b16 {%0,%1,%2,%3}, [%4];"
      : "=r"(r[0]),"=r"(r[1]),"=r"(r[2]),"=r"(r[3]) : "r"(addr));
}
__device__ __forceinline__ void ldm_x2(uint32_t* r, uint32_t addr){
    asm volatile("ldmatrix.sync.aligned.m8n8.x2.shared.b16 {%0,%1}, [%2];"
      : "=r"(r[0]),"=r"(r[1]) : "r"(addr));
}
__device__ __forceinline__ void ldm_x2t(uint32_t* r, uint32_t addr){
    asm volatile("ldmatrix.sync.aligned.m8n8.x2.trans.shared.b16 {%0,%1}, [%2];"
      : "=r"(r[0]),"=r"(r[1]) : "r"(addr));
}
__device__ __forceinline__ void mma16816f(float* c, uint32_t a0, uint32_t a1,
                                          uint32_t a2, uint32_t a3,
                                          uint32_t b0, uint32_t b1){
    asm volatile(
      "mma.sync.aligned.m16n8k16.row.col.f32.f16.f16.f32 "
      "{%0,%1,%2,%3},{%4,%5,%6,%7},{%8,%9},{%0,%1,%2,%3};"
      : "+f"(c[0]), "+f"(c[1]), "+f"(c[2]), "+f"(c[3])
      : "r"(a0), "r"(a1), "r"(a2), "r"(a3), "r"(b0), "r"(b1));
}

// ---------------- K1: one pass over x -> stats + fp16 copy ----------------
__global__ __launch_bounds__(256)
void k_stats(const float* __restrict__ x, __half* __restrict__ xf){
    __shared__ float sps[8*256], spm[8*256];
    int tile = blockIdx.x, b = blockIdx.y;
    int tid = threadIdx.x, w = tid>>5, lane = tid&31;
    int p0 = tile*256;
    float ps[8], pm[8];
    #pragma unroll
    for (int i=0;i<8;i++){ ps[i]=0.f; pm[i]=-1e30f; }
    for (int ci=0; ci<24; ci++){
        int c = w*24 + ci;
        size_t rowoff = ((size_t)b*C + c)*NPIX + p0;
        const float* row = x + rowoff;
        __half* orow = xf + rowoff;
        float cs = 0.f, cm = -1e30f;
        #pragma unroll
        for (int it=0; it<8; it++){
            float v = row[it*32 + lane];
            orow[it*32 + lane] = __float2half(v);
            ps[it] += v; pm[it] = fmaxf(pm[it], v);
            cs += v;     cm = fmaxf(cm, v);
        }
        #pragma unroll
        for (int o=16;o;o>>=1){
            cs += __shfl_xor_sync(~0u, cs, o);
            cm = fmaxf(cm, __shfl_xor_sync(~0u, cm, o));
        }
        if (lane==0){
            g_cps[(b*NTILE + tile)*C + c] = cs;
            g_cpm[(b*NTILE + tile)*C + c] = cm;
        }
    }
    #pragma unroll
    for (int it=0; it<8; it++){
        sps[w*256 + it*32 + lane] = ps[it];
        spm[w*256 + it*32 + lane] = pm[it];
    }
    __syncthreads();
    if (tid < 256){
        int p = tid;
        float s = 0.f, m = -1e30f;
        #pragma unroll
        for (int ww=0; ww<8; ww++){
            s += sps[ww*256+p];
            m = fmaxf(m, spm[ww*256+p]);
        }
        g_sp[(size_t)b*2*NPIX + p0 + p]        = s*(1.f/C);
        g_sp[(size_t)b*2*NPIX + NPIX + p0 + p] = m;
    }
}

// ---------------- K2: SE channel gate MLP ----------------
__global__ void k_chan_gate(const float* __restrict__ w1, const float* __restrict__ w2){
    int b = blockIdx.x, t = threadIdx.x;
    __shared__ float pool[C2], sq[48];
    {
        float s = 0.f, m = -1e30f;
        for (int tile=0; tile<NTILE; tile++){
            s += g_cps[(b*NTILE + tile)*C + t];
            m = fmaxf(m, g_cpm[(b*NTILE + tile)*C + t]);
        }
        pool[t]   = s*(1.f/NPIX);
        pool[C+t] = m;
    }
    __syncthreads();
    if (t < 48){
        float a = 0.f;
        #pragma unroll 8
        for (int c=0;c<C2;c++) a += w1[t*C2+c]*pool[c];
        sq[t] = fmaxf(a, 0.f);
    }
    __syncthreads();
    float a = 0.f;
    #pragma unroll
    for (int s=0;s<48;s++) a += w2[t*48+s]*sq[s];
    g_cg[b*C+t] = sigmoidf_(a);
}

// ---------------- K3: 7x7 spatial conv + sigmoid ----------------
__global__ void k_spatial_conv(const float* __restrict__ ws){
    int idx = blockIdx.x*256 + threadIdx.x;
    int b = idx >> 14, p = idx & (NPIX-1);
    int y = p >> 7, xx = p & 127;
    float acc = 0.f;
    #pragma unroll
    for (int ch=0; ch<2; ch++){
        const float* base = g_sp + (size_t)b*2*NPIX + (size_t)ch*NPIX;
        #pragma unroll
        for (int dy=-3; dy<=3; dy++){
            int yy = y+dy;
            if ((unsigned)yy < 128u){
                const float* row = base + yy*HW;
                #pragma unroll
                for (int dx=-3; dx<=3; dx++){
                    int xc = xx+dx;
                    if ((unsigned)xc < 128u)
                        acc += row[xc]*__ldg(&ws[ch*49 + (dy+3)*7 + (dx+3)]);
                }
            }
        }
    }
    g_sg[(size_t)b*NPIX + p] = sigmoidf_(acc);
}

// ---------------- weight conversions ----------------
__global__ void k_wcvt(const float* __restrict__ w, __half* __restrict__ oh){
    size_t i = ((size_t)blockIdx.x*256 + threadIdx.x)*4;
    int b  = (int)(i/(C4*GK));
    int rc = (int)(i - (size_t)b*C4*GK);
    int col = rc % GK;
    float4 v = *(const float4*)(w+rc);
    const float* g = g_cg + b*C;
    v.x *= g[col]; v.y *= g[col+1]; v.z *= g[col+2]; v.w *= g[col+3];
    __half2 a = __floats2half2_rn(v.x, v.y);
    __half2 bb = __floats2half2_rn(v.z, v.w);
    *(uint2*)(oh+i) = make_uint2(*(uint32_t*)&a, *(uint32_t*)&bb);
}

__global__ void k_pcvt(const float* __restrict__ w, __half* __restrict__ oh){
    size_t i = ((size_t)blockIdx.x*256 + threadIdx.x)*4;
    float4 v = *(const float4*)(w+i);
    __half2 a = __floats2half2_rn(v.x, v.y);
    __half2 b = __floats2half2_rn(v.z, v.w);
    *(uint2*)(oh+i) = make_uint2(*(uint32_t*)&a, *(uint32_t*)&b);
}

// ================= fp16 HMMA GEMM, B-resident + pipelined A (ping-pong) =================
#define S_A6 0
#define A6SZ 25600
#define S_B6 51200
#define SMEM6 103424

__global__ __launch_bounds__(256)
void k_hmma6(const __half* __restrict__ Ag, long sA,
             const __half* __restrict__ Bg,
             void* __restrict__ outp, long sC, int out_half,
             const float* __restrict__ S, int M, int Mtiles){
    extern __shared__ __align__(16) char smem[];
    uint32_t sb = su32(smem);
    int b = blockIdx.x & 7, bn = (blockIdx.x >> 3)*128;
    const __half* A = Ag + (size_t)b*sA;
    const __half* B = Bg + (size_t)b*C*NPIX;
    const float* Sp = S ? S + (size_t)b*NPIX : nullptr;

    int tid = threadIdx.x, wid = tid>>5, lane = tid&31;
    int wr = wid>>2, wc = wid&3;
    int gi = lane>>2, li4 = lane&3;

    for (int e=tid; e<3072; e+=256){
        int k = e>>4, ch = e&15;
        CP16(sb + S_B6 + k*272 + ch*16, (const char*)(B + (size_t)k*NPIX + bn) + ch*16);
    }
    asm volatile("cp.async.commit_group;" ::: "memory");
    {
        for (int e=tid; e<1536; e+=256){
            int r = e/24, ch = e - (e/24)*24;
            int m = r; if (m >= M) m = M-1;
            CP16(sb + S_A6 + r*400 + ch*16, (const char*)(A + (size_t)m*GK) + ch*16);
        }
        asm volatile("cp.async.commit_group;" ::: "memory");
    }

    uint32_t aBase = sb + S_A6 + ((wr*32 + (lane&15))*400) + (lane>>4)*16;
    uint32_t bA    = sb + S_B6 + (lane&15)*272 + wc*64;

    for (int ot=0; ot<Mtiles; ot++){
        if (ot+1 < Mtiles){
            int bm1 = (ot+1)*64;
            uint32_t dstb = sb + S_A6 + ((ot+1)&1)*A6SZ;
            for (int e=tid; e<1536; e+=256){
                int r = e/24, ch = e - (e/24)*24;
                int m = bm1 + r; if (m >= M) m = M-1;
                CP16(dstb + r*400 + ch*16, (const char*)(A + (size_t)m*GK) + ch*16);
            }
            asm volatile("cp.async.commit_group;" ::: "memory");
            asm volatile("cp.async.wait_group 1;" ::: "memory");
        } else {
            asm volatile("cp.async.wait_group 0;" ::: "memory");
        }
        __syncthreads();

        uint32_t aA = aBase + (ot&1)*A6SZ;
        float acc[2][4][4];
        #pragma unroll
        for (int i=0;i<2;i++)
            #pragma unroll
            for (int j=0;j<4;j++)
                #pragma unroll
                for (int r=0;r<4;r++) acc[i][j][r]=0.f;

        #pragma unroll
        for (int ks=0; ks<12; ks++){
            uint32_t Af[2][4], Bf[4][2];
            #pragma unroll
            for (int mi=0; mi<2; mi++) ldm_x4(Af[mi], aA + mi*6400 + ks*32);
            #pragma unroll
            for (int ni=0; ni<4; ni++) ldm_x2t(Bf[ni], bA + ks*4352 + ni*16);
            #pragma unroll
            for (int mi=0; mi<2; mi++)
                #pragma unroll
                for (int ni=0; ni<4; ni++)
                    mma16816f(acc[mi][ni], Af[mi][0],Af[mi][1],Af[mi][2],Af[mi][3],
                              Bf[ni][0],Bf[ni][1]);
        }

        int bm = ot*64;
        #pragma unroll
        for (int ni=0; ni<4; ni++){
            int n = bn + wc*32 + ni*8 + li4*2;
            float2 sv = Sp ? *(const float2*)&Sp[n] : make_float2(1.f,1.f);
            #pragma unroll
            for (int mi=0; mi<2; mi++){
                int m0 = bm + wr*32 + mi*16 + gi;
                int m1 = m0 + 8;
                if (out_half){
                    __half* O = (__half*)outp + (size_t)b*sC;
                    if (m0 < M)
                        *(__half2*)(O + (size_t)m0*NPIX + n) =
                            __floats2half2_rn(acc[mi][ni][0]*sv.x, acc[mi][ni][1]*sv.y);
                    if (m1 < M)
                        *(__half2*)(O + (size_t)m1*NPIX + n) =
                            __floats2half2_rn(acc[mi][ni][2]*sv.x, acc[mi][ni][3]*sv.y);
                } else {
                    float* O = (float*)outp + (size_t)b*sC;
                    if (m0 < M){
                        float2 p = make_float2(acc[mi][ni][0]*sv.x, acc[mi][ni][1]*sv.y);
                        *(float2*)(O + (size_t)m0*NPIX + n) = p;
                    }
                    if (m1 < M){
                        float2 p = make_float2(acc[mi][ni][2]*sv.x, acc[mi][ni][3]*sv.y);
                        *(float2*)(O + (size_t)m1*NPIX + n) = p;
                    }
                }
            }
        }
        __syncthreads();
    }
}

// ---------------- depthwise 3x3, full channel image per block + inv-norm ----------------
#define DWP 144
__global__ __launch_bounds__(256)
void k_dw2(const float* __restrict__ wd){
    __shared__ __half img[128*DWP];
    __shared__ float wsum[8];
    int bc = blockIdx.x;
    int ch = bc % C4;
    int b  = bc / C4;
    int tid = threadIdx.x;
    const __half* in = g_qkv + (size_t)bc*NPIX;

    float w[9];
    #pragma unroll
    for (int k=0;k<9;k++) w[k] = __ldg(&wd[ch*9+k]);

    for (int r=tid; r<128; r+=256){
        *(uint4*)&img[r*DWP]       = make_uint4(0,0,0,0);
        *(uint4*)&img[r*DWP + 136] = make_uint4(0,0,0,0);
    }
    for (int i=tid; i<2048; i+=256){
        int r = i>>4, c = i&15;
        *(uint4*)&img[r*DWP + 8 + c*8] = ((const uint4*)in)[i];
    }
    __syncthreads();

    __half* op = g_dw + (size_t)bc*NPIX;
    float ssq = 0.f;
    #pragma unroll
    for (int it=0; it<8; it++){
        int idx = it*256 + tid;
        int r  = idx>>4;
        int x0 = (idx&15)*8;
        float acc[8] = {0.f,0.f,0.f,0.f,0.f,0.f,0.f,0.f};
        #pragma unroll
        for (int dr=-1; dr<=1; dr++){
            int rr = r + dr;
            if ((unsigned)rr < 128u){
                const __half* rp = &img[rr*DWP + x0 + 6];
                float f[12];
                #pragma unroll
                for (int j=0;j<6;j++){
                    float2 p = __half22float2(*(const __half2*)(rp + 2*j));
                    f[2*j] = p.x; f[2*j+1] = p.y;
                }
                float w0 = w[(dr+1)*3], w1 = w[(dr+1)*3+1], w2 = w[(dr+1)*3+2];
                #pragma unroll
                for (int u=0;u<8;u++)
                    acc[u] += w0*f[u+1] + w1*f[u+2] + w2*f[u+3];
            }
        }
        __align__(16) __half hv[8];
        #pragma unroll
        for (int u=0;u<8;u++){ hv[u] = __float2half(acc[u]); ssq += acc[u]*acc[u]; }
        ((uint4*)op)[idx] = *(uint4*)hv;
    }

    int slot = (ch < C) ? 0 : ((ch >= 2*C && ch < 3*C) ? 1 : -1);
    if (slot >= 0){
        #pragma unroll
        for (int o=16;o;o>>=1) ssq += __shfl_xor_sync(~0u, ssq, o);
        if ((tid&31)==0) wsum[tid>>5] = ssq;
        __syncthreads();
        if (tid==0){
            float s = 0.f;
            #pragma unroll
            for (int i=0;i<8;i++) s += wsum[i];
            float inv = 1.f/fmaxf(sqrtf(s), 1e-12f);
            if (slot==0) g_inq[b*C + ch]       = inv;
            else         g_ink[b*C + ch - 2*C] = inv;
        }
    }
}

// ---------------- q.k^T partials on tensor cores ----------------
__global__ __launch_bounds__(256)
void k_attn_mma(){
    __shared__ __half qs[48*72];
    __shared__ __half ks[48*72];
    int bh = blockIdx.x, seg = blockIdx.y;
    int b = bh>>2, hh = bh&3;
    const __half* qb = g_dw + ((size_t)b*C4 + hh*HD)*NPIX + seg*ASEGLEN;
    const __half* kb = g_dw + ((size_t)b*C4 + 2*C + hh*HD)*NPIX + seg*ASEGLEN;
    int tid = threadIdx.x, wid = tid>>5, lane = tid&31;
    uint32_t qsb = su32(qs), ksb = su32(ks);
    int n0 = wid*8;

    float acc[3][4];
    #pragma unroll
    for (int mi=0;mi<3;mi++)
        #pragma unroll
        for (int r=0;r<4;r++) acc[mi][r]=0.f;

    uint32_t aAddr = qsb + ((lane&15)*72 + (lane>>4)*8)*2;
    uint32_t bAddr = ksb + (((n0 + (lane&7))*72) + (((lane>>3)&1)*8))*2;

    for (int ck=0; ck<ASEGLEN/64; ck++){
        for (int e=tid; e<768; e+=256){
            int which = e>=384;
            int idx = e - which*384;
            int r = idx>>3, c8 = idx&7;
            const __half* src = (which? kb : qb) + (size_t)r*NPIX + ck*64 + c8*8;
            __half* dst = (which? ks : qs) + r*72 + c8*8;
            *(uint4*)dst = *(const uint4*)src;
        }
        __syncthreads();
        if (wid < 6){
            #pragma unroll
            for (int kst=0; kst<4; kst++){
                uint32_t Bf[2];
                ldm_x2(Bf, bAddr + kst*32);
                #pragma unroll
                for (int mi=0; mi<3; mi++){
                    uint32_t Af[4];
                    ldm_x4(Af, aAddr + mi*16*144 + kst*32);
                    mma16816f(acc[mi], Af[0],Af[1],Af[2],Af[3], Bf[0],Bf[1]);
                }
            }
        }
        __syncthreads();
    }
    if (wid < 6){
        int gi = lane>>2, li4 = lane&3;
        float* dst = g_spart + (size_t)(bh*ASEG+seg)*HD*HD;
        #pragma unroll
        for (int mi=0; mi<3; mi++){
            int r0 = mi*16 + gi;
            int cc = n0 + li4*2;
            dst[r0*HD+cc]     = acc[mi][0];
            dst[r0*HD+cc+1]   = acc[mi][1];
            dst[(r0+8)*HD+cc]   = acc[mi][2];
            dst[(r0+8)*HD+cc+1] = acc[mi][3];
        }
    }
}

// ---------------- combine partials, scale, softmax ----------------
__global__ void k_softmax(const float* __restrict__ temp){
    int row = blockIdx.x;
    int bh = row / HD;
    int i  = row - bh*HD;
    int b = bh >> 2, hh = bh & 3;
    int j = threadIdx.x;
    float v = -1e30f;
    if (j < HD){
        float s = 0.f;
        #pragma unroll
        for (int sg=0; sg<ASEG; sg++)
            s += g_spart[((size_t)(bh*ASEG+sg)*HD + i)*HD + j];
        v = s * __ldg(&temp[hh]) * g_inq[b*C + hh*HD + i] * g_ink[b*C + hh*HD + j];
    }
    __shared__ float sh[64];
    sh[j] = v; __syncthreads();
    for (int o=32;o>0;o>>=1){ if (j<o) sh[j]=fmaxf(sh[j],sh[j+o]); __syncthreads(); }
    float m = sh[0]; __syncthreads();
    float e = (j < HD) ? expf(v - m) : 0.f;
    sh[j] = e; __syncthreads();
    for (int o=32;o>0;o>>=1){ if (j<o) sh[j]+=sh[j+o]; __syncthreads(); }
    if (j < HD) g_attn[(size_t)bh*HD*HD + i*HD + j] = e / sh[0];
}

// ================= fused (attn@v)*sigmoid(gate) + proj GEMM =================
// Phase 1: build of[192][272B] panel in smem via tensor-core av + gate.
// Phase 2: hmma6-style proj GEMM with B = the smem panel, fp32 out.
// smem: workspace 51200 (phase1: v 13056 | gate 13056 | attn 5376; phase2: A ping-pong 2x25600)
//       of panel at 51200 (52224). total 103424.
#define WS_V  0
#define WS_G  13056
#define WS_AT 26112
#define S_OF  51200
#define SMEMP 103424

__global__ __launch_bounds__(256)
void k_avproj(const __half* __restrict__ wp, float* __restrict__ outg){
    extern __shared__ __align__(16) char smem[];
    uint32_t sb = su32(smem);
    int b = blockIdx.y, pt = blockIdx.x;
    int p0 = pt*128;
    int tid = threadIdx.x, wid = tid>>5, lane = tid&31;
    int gi = lane>>2, li4 = lane&3;
    __half* of_s = (__half*)(smem + S_OF);
    __half* at_s = (__half*)(smem + WS_AT);

    // ---------- phase 1: of panel ----------
    for (int h=0; h<HEADS; h++){
        const __half* vb = g_dw + ((size_t)b*C4 + 3*C + h*HD)*NPIX + p0;
        const __half* gb = g_dw + ((size_t)b*C4 + C   + h*HD)*NPIX + p0;
        for (int e=tid; e<1536; e+=256){
            int which = e>=768;
            int idx = e - which*768;
            int r = idx>>4, ch = idx&15;
            const __half* src = (which? gb : vb) + (size_t)r*NPIX;
            CP16(sb + (which? WS_G : WS_V) + r*272 + ch*16, (const char*)src + ch*16);
        }
        asm volatile("cp.async.commit_group;" ::: "memory");
        const float* ap = g_attn + (size_t)(b*HEADS+h)*HD*HD;
        for (int e=tid; e<2304; e+=256){
            int i = e/48, j = e - (e/48)*48;
            at_s[i*56+j] = __float2half(ap[e]);
        }
        asm volatile("cp.async.wait_group 0;" ::: "memory");
        __syncthreads();

        int n0 = wid*16;
        float acc[3][2][4];
        #pragma unroll
        for (int mi=0;mi<3;mi++)
            #pragma unroll
            for (int ni=0;ni<2;ni++)
                #pragma unroll
                for (int r=0;r<4;r++) acc[mi][ni][r]=0.f;

        #pragma unroll
        for (int kst=0; kst<3; kst++){
            uint32_t Af[3][4], Bf[2][2];
            #pragma unroll
            for (int mi=0; mi<3; mi++)
                ldm_x4(Af[mi], sb + WS_AT + ((mi*16 + (lane&15))*56 + kst*16 + (lane>>4)*8)*2);
            #pragma unroll
            for (int ni=0; ni<2; ni++)
                ldm_x2t(Bf[ni], sb + WS_V + (kst*16 + (lane&15))*272 + (n0 + ni*8)*2);
            #pragma unroll
            for (int mi=0; mi<3; mi++)
                #pragma unroll
                for (int ni=0; ni<2; ni++)
                    mma16816f(acc[mi][ni], Af[mi][0],Af[mi][1],Af[mi][2],Af[mi][3],
                              Bf[ni][0],Bf[ni][1]);
        }

        const __half* gs = (const __half*)(smem + WS_G);
        #pragma unroll
        for (int mi=0; mi<3; mi++){
            #pragma unroll
            for (int ni=0; ni<2; ni++){
                int r0 = mi*16 + gi;
                int cc = n0 + ni*8 + li4*2;
                float2 g0 = __half22float2(*(const __half2*)&gs[r0*136 + cc]);
                *(__half2*)&of_s[(h*HD + r0)*136 + cc] =
                    __floats2half2_rn(acc[mi][ni][0]*sigmoidf_(g0.x),
                                      acc[mi][ni][1]*sigmoidf_(g0.y));
                float2 g1 = __half22float2(*(const __half2*)&gs[(r0+8)*136 + cc]);
                *(__half2*)&of_s[(h*HD + r0+8)*136 + cc] =
                    __floats2half2_rn(acc[mi][ni][2]*sigmoidf_(g1.x),
                                      acc[mi][ni][3]*sigmoidf_(g1.y));
            }
        }
        __syncthreads();
    }

    // ---------- phase 2: proj GEMM, B = of panel in smem ----------
    int wr = wid>>2, wc = wid&3;
    {
        for (int e=tid; e<1536; e+=256){
            int r = e/24, ch = e - (e/24)*24;
            CP16(sb + r*400 + ch*16, (const char*)(wp + (size_t)r*GK) + ch*16);
        }
        asm volatile("cp.async.commit_group;" ::: "memory");
    }
    uint32_t aBase = sb + ((wr*32 + (lane&15))*400) + (lane>>4)*16;
    uint32_t bA    = sb + S_OF + (lane&15)*272 + wc*64;

    for (int ot=0; ot<3; ot++){
        if (ot+1 < 3){
            int bm1 = (ot+1)*64;
            uint32_t dstb = sb + ((ot+1)&1)*A6SZ;
            for (int e=tid; e<1536; e+=256){
                int r = e/24, ch = e - (e/24)*24;
                CP16(dstb + r*400 + ch*16, (const char*)(wp + (size_t)(bm1+r)*GK) + ch*16);
            }
            asm volatile("cp.async.commit_group;" ::: "memory");
            asm volatile("cp.async.wait_group 1;" ::: "memory");
        } else {
            asm volatile("cp.async.wait_group 0;" ::: "memory");
        }
        __syncthreads();

        uint32_t aA = aBase + (ot&1)*A6SZ;
        float acc[2][4][4];
        #pragma unroll
        for (int i=0;i<2;i++)
            #pragma unroll
            for (int j=0;j<4;j++)
                #pragma unroll
                for (int r=0;r<4;r++) acc[i][j][r]=0.f;

        #pragma unroll
        for (int ks=0; ks<12; ks++){
            uint32_t Af[2][4], Bf[4][2];
            #pragma unroll
            for (int mi=0; mi<2; mi++) ldm_x4(Af[mi], aA + mi*6400 + ks*32);
            #pragma unroll
            for (int ni=0; ni<4; ni++) ldm_x2t(Bf[ni], bA + ks*4352 + ni*16);
            #pragma unroll
            for (int mi=0; mi<2; mi++)
                #pragma unroll
                for (int ni=0; ni<4; ni++)
                    mma16816f(acc[mi][ni], Af[mi][0],Af[mi][1],Af[mi][2],Af[mi][3],
                              Bf[ni][0],Bf[ni][1]);
        }

        int bm = ot*64;
        float* O = outg + (size_t)b*C*NPIX + p0;
        #pragma unroll
        for (int ni=0; ni<4; ni++){
            int n = wc*32 + ni*8 + li4*2;
            #pragma unroll
            for (int mi=0; mi<2; mi++){
                int m0 = bm + wr*32 + mi*16 + gi;
                *(float2*)(O + (size_t)m0*NPIX + n) =
                    make_float2(acc[mi][ni][0], acc[mi][ni][1]);
                *(float2*)(O + (size_t)(m0+8)*NPIX + n) =
                    make_float2(acc[mi][ni][2], acc[mi][ni][3]);
            }
        }
        __syncthreads();
    }
}

// ---------------- host ----------------
extern "C" void kernel_launch(void* const* d_in, const int* in_sizes, int n_in,
                              void* d_out, int out_size){
    const float* x      = (const float*)d_in[0];
    const float* w_fc1  = (const float*)d_in[1];
    const float* w_fc2  = (const float*)d_in[2];
    const float* w_sp   = (const float*)d_in[3];
    const float* w_qkv  = (const float*)d_in[4];
    const float* w_dw   = (const float*)d_in[5];
    const float* w_proj = (const float*)d_in[6];
    const float* temp   = (const float*)d_in[7];
    float* out = (float*)d_out;

    __half *xf, *wq, *wp, *qkv;
    float *sg;
    cudaGetSymbolAddress((void**)&xf,  g_xf);
    cudaGetSymbolAddress((void**)&wq,  g_wq);
    cudaGetSymbolAddress((void**)&wp,  g_wp);
    cudaGetSymbolAddress((void**)&qkv, g_qkv);
    cudaGetSymbolAddress((void**)&sg,  g_sg);

    cudaFuncSetAttribute(k_hmma6,  cudaFuncAttributeMaxDynamicSharedMemorySize, SMEM6);
    cudaFuncSetAttribute(k_avproj, cudaFuncAttributeMaxDynamicSharedMemorySize, SMEMP);

    k_stats        <<<dim3(NTILE, NB), 256>>>(x, xf);
    k_chan_gate    <<<NB, 192>>>(w_fc1, w_fc2);
    k_spatial_conv <<<NB*NPIX/256, 256>>>(w_sp);

    k_wcvt<<<(NB*C4*GK/4)/256, 256>>>(w_qkv, wq);
    k_pcvt<<<(C*GK/4 + 255)/256, 256>>>(w_proj, wp);

    // qkv = sg(p) * ((w_qkv*cg) @ x), pipelined B-resident fp16 GEMM, half output
    k_hmma6<<<NB*(NPIX/128), 256, SMEM6>>>(
        wq, (long)C4*GK, xf, qkv, (long)C4*NPIX, 1, sg, C4, 12);

    k_dw2<<<NB*C4, 256>>>(w_dw);     // dw + inverse norms

    k_attn_mma<<<dim3(NB*HEADS, ASEG), 256>>>();
    k_softmax  <<<NB*HEADS*HD, 64>>>(temp);

    // fused (attn@v)*sigmoid(gate) + final projection -> d_out
    k_avproj<<<dim3(NPIX/128, NB), 256, SMEMP>>>(wp, out);
}

// round 14
// speedup vs baseline: 4.4757x; 1.0030x over previous
#include <cuda_runtime.h>
#include <cuda_fp16.h>
#include <math.h>
#include <stdint.h>

#define NB    8
#define C     192
#define C2    384
#define C4    768
#define HEADS 4
#define HD    48
#define HW    128
#define NPIX  16384
#define GK    192
#define ASEG  8
#define ASEGLEN (NPIX/ASEG)
#define NTILE 64

// ---------------- scratch (static device memory) ----------------
__device__ float g_cps[NB*NTILE*C];
__device__ float g_cpm[NB*NTILE*C];
__device__ float g_cg [NB*C];
__device__ float g_sp [NB*2*NPIX];
__device__ float g_sg [NB*NPIX];
__device__ __half g_wq [NB*C4*GK];
__device__ __half g_wp [C*GK];
__device__ __half g_qkv[(size_t)NB*C4*NPIX];
__device__ __half g_dw [(size_t)NB*C4*NPIX];
__device__ float g_inq [NB*C];
__device__ float g_ink [NB*C];
__device__ float g_spart[(size_t)NB*HEADS*ASEG*HD*HD];
__device__ float g_attn [(size_t)NB*HEADS*HD*HD];

__device__ __forceinline__ float sigmoidf_(float x){ return 1.f/(1.f+expf(-x)); }

__device__ __forceinline__ uint32_t su32(const void* p){
    uint32_t a;
    asm("{ .reg .u64 t; cvta.to.shared.u64 t, %1; cvt.u32.u64 %0, t; }" : "=r"(a) : "l"(p));
    return a;
}
#define CP16(dst, src) \
    asm volatile("cp.async.cg.shared.global [%0], [%1], 16;" :: "r"(dst), "l"(src))

__device__ __forceinline__ void ldm_x4(uint32_t* r, uint32_t addr){
    asm volatile("ldmatrix.sync.aligned.m8n8.x4.shared.b16 {%0,%1,%2,%3}, [%4];"
      : "=r"(r[0]),"=r"(r[1]),"=r"(r[2]),"=r"(r[3]) : "r"(addr));
}
__device__ __forceinline__ void ldm_x2(uint32_t* r, uint32_t addr){
    asm volatile("ldmatrix.sync.aligned.m8n8.x2.shared.b16 {%0,%1}, [%2];"
      : "=r"(r[0]),"=r"(r[1]) : "r"(addr));
}
__device__ __forceinline__ void ldm_x2t(uint32_t* r, uint32_t addr){
    asm volatile("ldmatrix.sync.aligned.m8n8.x2.trans.shared.b16 {%0,%1}, [%2];"
      : "=r"(r[0]),"=r"(r[1]) : "r"(addr));
}
__device__ __forceinline__ void mma16816f(float* c, uint32_t a0, uint32_t a1,
                                          uint32_t a2, uint32_t a3,
                                          uint32_t b0, uint32_t b1){
    asm volatile(
      "mma.sync.aligned.m16n8k16.row.col.f32.f16.f16.f32 "
      "{%0,%1,%2,%3},{%4,%5,%6,%7},{%8,%9},{%0,%1,%2,%3};"
      : "+f"(c[0]), "+f"(c[1]), "+f"(c[2]), "+f"(c[3])
      : "r"(a0), "r"(a1), "r"(a2), "r"(a3), "r"(b0), "r"(b1));
}

// ---------------- K1: one pass over x -> channel + pixel stats ----------------
__global__ __launch_bounds__(256)
void k_stats(const float* __restrict__ x){
    __shared__ float sps[8*256], spm[8*256];
    int tile = blockIdx.x, b = blockIdx.y;
    int tid = threadIdx.x, w = tid>>5, lane = tid&31;
    int p0 = tile*256;
    float ps[8], pm[8];
    #pragma unroll
    for (int i=0;i<8;i++){ ps[i]=0.f; pm[i]=-1e30f; }
    for (int ci=0; ci<24; ci++){
        int c = w*24 + ci;
        const float* row = x + ((size_t)b*C + c)*NPIX + p0;
        float cs = 0.f, cm = -1e30f;
        #pragma unroll
        for (int it=0; it<8; it++){
            float v = row[it*32 + lane];
            ps[it] += v; pm[it] = fmaxf(pm[it], v);
            cs += v;     cm = fmaxf(cm, v);
        }
        #pragma unroll
        for (int o=16;o;o>>=1){
            cs += __shfl_xor_sync(~0u, cs, o);
            cm = fmaxf(cm, __shfl_xor_sync(~0u, cm, o));
        }
        if (lane==0){
            g_cps[(b*NTILE + tile)*C + c] = cs;
            g_cpm[(b*NTILE + tile)*C + c] = cm;
        }
    }
    #pragma unroll
    for (int it=0; it<8; it++){
        sps[w*256 + it*32 + lane] = ps[it];
        spm[w*256 + it*32 + lane] = pm[it];
    }
    __syncthreads();
    if (tid < 256){
        int p = tid;
        float s = 0.f, m = -1e30f;
        #pragma unroll
        for (int ww=0; ww<8; ww++){
            s += sps[ww*256+p];
            m = fmaxf(m, spm[ww*256+p]);
        }
        g_sp[(size_t)b*2*NPIX + p0 + p]        = s*(1.f/C);
        g_sp[(size_t)b*2*NPIX + NPIX + p0 + p] = m;
    }
}

// ---------------- K2: SE channel gate MLP ----------------
__global__ void k_chan_gate(const float* __restrict__ w1, const float* __restrict__ w2){
    int b = blockIdx.x, t = threadIdx.x;
    __shared__ float pool[C2], sq[48];
    {
        float s = 0.f, m = -1e30f;
        for (int tile=0; tile<NTILE; tile++){
            s += g_cps[(b*NTILE + tile)*C + t];
            m = fmaxf(m, g_cpm[(b*NTILE + tile)*C + t]);
        }
        pool[t]   = s*(1.f/NPIX);
        pool[C+t] = m;
    }
    __syncthreads();
    if (t < 48){
        float a = 0.f;
        #pragma unroll 8
        for (int c=0;c<C2;c++) a += w1[t*C2+c]*pool[c];
        sq[t] = fmaxf(a, 0.f);
    }
    __syncthreads();
    float a = 0.f;
    #pragma unroll
    for (int s=0;s<48;s++) a += w2[t*48+s]*sq[s];
    g_cg[b*C+t] = sigmoidf_(a);
}

// ---------------- K3: 7x7 spatial conv + sigmoid ----------------
__global__ void k_spatial_conv(const float* __restrict__ ws){
    int idx = blockIdx.x*256 + threadIdx.x;
    int b = idx >> 14, p = idx & (NPIX-1);
    int y = p >> 7, xx = p & 127;
    float acc = 0.f;
    #pragma unroll
    for (int ch=0; ch<2; ch++){
        const float* base = g_sp + (size_t)b*2*NPIX + (size_t)ch*NPIX;
        #pragma unroll
        for (int dy=-3; dy<=3; dy++){
            int yy = y+dy;
            if ((unsigned)yy < 128u){
                const float* row = base + yy*HW;
                #pragma unroll
                for (int dx=-3; dx<=3; dx++){
                    int xc = xx+dx;
                    if ((unsigned)xc < 128u)
                        acc += row[xc]*__ldg(&ws[ch*49 + (dy+3)*7 + (dx+3)]);
                }
            }
        }
    }
    g_sg[(size_t)b*NPIX + p] = sigmoidf_(acc);
}

// ---------------- weight conversions ----------------
__global__ void k_wcvt(const float* __restrict__ w, __half* __restrict__ oh){
    size_t i = ((size_t)blockIdx.x*256 + threadIdx.x)*4;
    int b  = (int)(i/(C4*GK));
    int rc = (int)(i - (size_t)b*C4*GK);
    int col = rc % GK;
    float4 v = *(const float4*)(w+rc);
    const float* g = g_cg + b*C;
    v.x *= g[col]; v.y *= g[col+1]; v.z *= g[col+2]; v.w *= g[col+3];
    __half2 a = __floats2half2_rn(v.x, v.y);
    __half2 bb = __floats2half2_rn(v.z, v.w);
    *(uint2*)(oh+i) = make_uint2(*(uint32_t*)&a, *(uint32_t*)&bb);
}

__global__ void k_pcvt(const float* __restrict__ w, __half* __restrict__ oh){
    size_t i = ((size_t)blockIdx.x*256 + threadIdx.x)*4;
    float4 v = *(const float4*)(w+i);
    __half2 a = __floats2half2_rn(v.x, v.y);
    __half2 b = __floats2half2_rn(v.z, v.w);
    *(uint2*)(oh+i) = make_uint2(*(uint32_t*)&a, *(uint32_t*)&b);
}

// ================= qkv GEMM: fp32-B staged+converted, A ping-pong cp.async =================
// smem: A 2x[64][400B] = 51200, B[192][272B] fp16 = 52224 -> 103424
#define S_A6 0
#define A6SZ 25600
#define S_B6 51200
#define SMEM6 103424

__global__ __launch_bounds__(256)
void k_hmma6(const __half* __restrict__ Ag, long sA,
             const float* __restrict__ Bg,       // fp32 x, converted at staging
             __half* __restrict__ outp, long sC,
             const float* __restrict__ S, int M, int Mtiles){
    extern __shared__ __align__(16) char smem[];
    uint32_t sb = su32(smem);
    int b = blockIdx.x & 7, bn = (blockIdx.x >> 3)*128;
    const __half* A = Ag + (size_t)b*sA;
    const float* B = Bg + (size_t)b*C*NPIX;
    const float* Sp = S + (size_t)b*NPIX;

    int tid = threadIdx.x, wid = tid>>5, lane = tid&31;
    int wr = wid>>2, wc = wid&3;
    int gi = lane>>2, li4 = lane&3;

    // stage A tile 0 via cp.async (group 0)
    for (int e=tid; e<1536; e+=256){
        int r = e/24, ch = e - (e/24)*24;
        CP16(sb + S_A6 + r*400 + ch*16, (const char*)(A + (size_t)r*GK) + ch*16);
    }
    asm volatile("cp.async.commit_group;" ::: "memory");

    // stage B panel once: fp32 load -> fp16 smem
    for (int e=tid; e<6144; e+=256){
        int k = e>>5, c4 = e&31;
        float4 v = *(const float4*)(B + (size_t)k*NPIX + bn + c4*4);
        __half2 h0 = __floats2half2_rn(v.x, v.y);
        __half2 h1 = __floats2half2_rn(v.z, v.w);
        *(uint2*)(smem + S_B6 + k*272 + c4*8) = make_uint2(*(uint32_t*)&h0, *(uint32_t*)&h1);
    }

    uint32_t aBase = sb + S_A6 + ((wr*32 + (lane&15))*400) + (lane>>4)*16;
    uint32_t bA    = sb + S_B6 + (lane&15)*272 + wc*64;

    for (int ot=0; ot<Mtiles; ot++){
        if (ot+1 < Mtiles){
            int bm1 = (ot+1)*64;
            uint32_t dstb = sb + S_A6 + ((ot+1)&1)*A6SZ;
            for (int e=tid; e<1536; e+=256){
                int r = e/24, ch = e - (e/24)*24;
                CP16(dstb + r*400 + ch*16, (const char*)(A + (size_t)(bm1+r)*GK) + ch*16);
            }
            asm volatile("cp.async.commit_group;" ::: "memory");
            asm volatile("cp.async.wait_group 1;" ::: "memory");
        } else {
            asm volatile("cp.async.wait_group 0;" ::: "memory");
        }
        __syncthreads();   // A tile ready + B STS visible

        uint32_t aA = aBase + (ot&1)*A6SZ;
        float acc[2][4][4];
        #pragma unroll
        for (int i=0;i<2;i++)
            #pragma unroll
            for (int j=0;j<4;j++)
                #pragma unroll
                for (int r=0;r<4;r++) acc[i][j][r]=0.f;

        #pragma unroll
        for (int ks=0; ks<12; ks++){
            uint32_t Af[2][4], Bf[4][2];
            #pragma unroll
            for (int mi=0; mi<2; mi++) ldm_x4(Af[mi], aA + mi*6400 + ks*32);
            #pragma unroll
            for (int ni=0; ni<4; ni++) ldm_x2t(Bf[ni], bA + ks*4352 + ni*16);
            #pragma unroll
            for (int mi=0; mi<2; mi++)
                #pragma unroll
                for (int ni=0; ni<4; ni++)
                    mma16816f(acc[mi][ni], Af[mi][0],Af[mi][1],Af[mi][2],Af[mi][3],
                              Bf[ni][0],Bf[ni][1]);
        }

        int bm = ot*64;
        __half* O = outp + (size_t)b*sC;
        #pragma unroll
        for (int ni=0; ni<4; ni++){
            int n = bn + wc*32 + ni*8 + li4*2;
            float2 sv = *(const float2*)&Sp[n];
            #pragma unroll
            for (int mi=0; mi<2; mi++){
                int m0 = bm + wr*32 + mi*16 + gi;
                *(__half2*)(O + (size_t)m0*NPIX + n) =
                    __floats2half2_rn(acc[mi][ni][0]*sv.x, acc[mi][ni][1]*sv.y);
                *(__half2*)(O + (size_t)(m0+8)*NPIX + n) =
                    __floats2half2_rn(acc[mi][ni][2]*sv.x, acc[mi][ni][3]*sv.y);
            }
        }
        __syncthreads();
    }
}

// ---------------- depthwise 3x3, full channel image per block + inv-norm ----------------
#define DWP 144
__global__ __launch_bounds__(256)
void k_dw2(const float* __restrict__ wd){
    __shared__ __half img[128*DWP];
    __shared__ float wsum[8];
    int bc = blockIdx.x;
    int ch = bc % C4;
    int b  = bc / C4;
    int tid = threadIdx.x;
    const __half* in = g_qkv + (size_t)bc*NPIX;

    float w[9];
    #pragma unroll
    for (int k=0;k<9;k++) w[k] = __ldg(&wd[ch*9+k]);

    for (int r=tid; r<128; r+=256){
        *(uint4*)&img[r*DWP]       = make_uint4(0,0,0,0);
        *(uint4*)&img[r*DWP + 136] = make_uint4(0,0,0,0);
    }
    for (int i=tid; i<2048; i+=256){
        int r = i>>4, c = i&15;
        *(uint4*)&img[r*DWP + 8 + c*8] = ((const uint4*)in)[i];
    }
    __syncthreads();

    __half* op = g_dw + (size_t)bc*NPIX;
    float ssq = 0.f;
    #pragma unroll
    for (int it=0; it<8; it++){
        int idx = it*256 + tid;
        int r  = idx>>4;
        int x0 = (idx&15)*8;
        float acc[8] = {0.f,0.f,0.f,0.f,0.f,0.f,0.f,0.f};
        #pragma unroll
        for (int dr=-1; dr<=1; dr++){
            int rr = r + dr;
            if ((unsigned)rr < 128u){
                const __half* rp = &img[rr*DWP + x0 + 6];
                float f[12];
                #pragma unroll
                for (int j=0;j<6;j++){
                    float2 p = __half22float2(*(const __half2*)(rp + 2*j));
                    f[2*j] = p.x; f[2*j+1] = p.y;
                }
                float w0 = w[(dr+1)*3], w1 = w[(dr+1)*3+1], w2 = w[(dr+1)*3+2];
                #pragma unroll
                for (int u=0;u<8;u++)
                    acc[u] += w0*f[u+1] + w1*f[u+2] + w2*f[u+3];
            }
        }
        __align__(16) __half hv[8];
        #pragma unroll
        for (int u=0;u<8;u++){ hv[u] = __float2half(acc[u]); ssq += acc[u]*acc[u]; }
        ((uint4*)op)[idx] = *(uint4*)hv;
    }

    int slot = (ch < C) ? 0 : ((ch >= 2*C && ch < 3*C) ? 1 : -1);
    if (slot >= 0){
        #pragma unroll
        for (int o=16;o;o>>=1) ssq += __shfl_xor_sync(~0u, ssq, o);
        if ((tid&31)==0) wsum[tid>>5] = ssq;
        __syncthreads();
        if (tid==0){
            float s = 0.f;
            #pragma unroll
            for (int i=0;i<8;i++) s += wsum[i];
            float inv = 1.f/fmaxf(sqrtf(s), 1e-12f);
            if (slot==0) g_inq[b*C + ch]       = inv;
            else         g_ink[b*C + ch - 2*C] = inv;
        }
    }
}

// ---------------- q.k^T partials on tensor cores ----------------
__global__ __launch_bounds__(256)
void k_attn_mma(){
    __shared__ __half qs[48*72];
    __shared__ __half ks[48*72];
    int bh = blockIdx.x, seg = blockIdx.y;
    int b = bh>>2, hh = bh&3;
    const __half* qb = g_dw + ((size_t)b*C4 + hh*HD)*NPIX + seg*ASEGLEN;
    const __half* kb = g_dw + ((size_t)b*C4 + 2*C + hh*HD)*NPIX + seg*ASEGLEN;
    int tid = threadIdx.x, wid = tid>>5, lane = tid&31;
    uint32_t qsb = su32(qs), ksb = su32(ks);
    int n0 = wid*8;

    float acc[3][4];
    #pragma unroll
    for (int mi=0;mi<3;mi++)
        #pragma unroll
        for (int r=0;r<4;r++) acc[mi][r]=0.f;

    uint32_t aAddr = qsb + ((lane&15)*72 + (lane>>4)*8)*2;
    uint32_t bAddr = ksb + (((n0 + (lane&7))*72) + (((lane>>3)&1)*8))*2;

    for (int ck=0; ck<ASEGLEN/64; ck++){
        for (int e=tid; e<768; e+=256){
            int which = e>=384;
            int idx = e - which*384;
            int r = idx>>3, c8 = idx&7;
            const __half* src = (which? kb : qb) + (size_t)r*NPIX + ck*64 + c8*8;
            __half* dst = (which? ks : qs) + r*72 + c8*8;
            *(uint4*)dst = *(const uint4*)src;
        }
        __syncthreads();
        if (wid < 6){
            #pragma unroll
            for (int kst=0; kst<4; kst++){
                uint32_t Bf[2];
                ldm_x2(Bf, bAddr + kst*32);
                #pragma unroll
                for (int mi=0; mi<3; mi++){
                    uint32_t Af[4];
                    ldm_x4(Af, aAddr + mi*16*144 + kst*32);
                    mma16816f(acc[mi], Af[0],Af[1],Af[2],Af[3], Bf[0],Bf[1]);
                }
            }
        }
        __syncthreads();
    }
    if (wid < 6){
        int gi = lane>>2, li4 = lane&3;
        float* dst = g_spart + (size_t)(bh*ASEG+seg)*HD*HD;
        #pragma unroll
        for (int mi=0; mi<3; mi++){
            int r0 = mi*16 + gi;
            int cc = n0 + li4*2;
            dst[r0*HD+cc]     = acc[mi][0];
            dst[r0*HD+cc+1]   = acc[mi][1];
            dst[(r0+8)*HD+cc]   = acc[mi][2];
            dst[(r0+8)*HD+cc+1] = acc[mi][3];
        }
    }
}

// ---------------- combine partials, scale, softmax ----------------
__global__ void k_softmax(const float* __restrict__ temp){
    int row = blockIdx.x;
    int bh = row / HD;
    int i  = row - bh*HD;
    int b = bh >> 2, hh = bh & 3;
    int j = threadIdx.x;
    float v = -1e30f;
    if (j < HD){
        float s = 0.f;
        #pragma unroll
        for (int sg=0; sg<ASEG; sg++)
            s += g_spart[((size_t)(bh*ASEG+sg)*HD + i)*HD + j];
        v = s * __ldg(&temp[hh]) * g_inq[b*C + hh*HD + i] * g_ink[b*C + hh*HD + j];
    }
    __shared__ float sh[64];
    sh[j] = v; __syncthreads();
    for (int o=32;o>0;o>>=1){ if (j<o) sh[j]=fmaxf(sh[j],sh[j+o]); __syncthreads(); }
    float m = sh[0]; __syncthreads();
    float e = (j < HD) ? expf(v - m) : 0.f;
    sh[j] = e; __syncthreads();
    for (int o=32;o>0;o>>=1){ if (j<o) sh[j]+=sh[j+o]; __syncthreads(); }
    if (j < HD) g_attn[(size_t)bh*HD*HD + i*HD + j] = e / sh[0];
}

// ================= fused (attn@v)*sigmoid(gate) + proj GEMM =================
#define WS_V  0
#define WS_G  13056
#define WS_AT 26112
#define S_OF  51200
#define SMEMP 103424

__global__ __launch_bounds__(256)
void k_avproj(const __half* __restrict__ wp, float* __restrict__ outg){
    extern __shared__ __align__(16) char smem[];
    uint32_t sb = su32(smem);
    int b = blockIdx.y, pt = blockIdx.x;
    int p0 = pt*128;
    int tid = threadIdx.x, wid = tid>>5, lane = tid&31;
    int gi = lane>>2, li4 = lane&3;
    __half* of_s = (__half*)(smem + S_OF);
    __half* at_s = (__half*)(smem + WS_AT);

    // ---------- phase 1: of panel ----------
    for (int h=0; h<HEADS; h++){
        const __half* vb = g_dw + ((size_t)b*C4 + 3*C + h*HD)*NPIX + p0;
        const __half* gb = g_dw + ((size_t)b*C4 + C   + h*HD)*NPIX + p0;
        for (int e=tid; e<1536; e+=256){
            int which = e>=768;
            int idx = e - which*768;
            int r = idx>>4, ch = idx&15;
            const __half* src = (which? gb : vb) + (size_t)r*NPIX;
            CP16(sb + (which? WS_G : WS_V) + r*272 + ch*16, (const char*)src + ch*16);
        }
        asm volatile("cp.async.commit_group;" ::: "memory");
        const float* ap = g_attn + (size_t)(b*HEADS+h)*HD*HD;
        for (int e=tid; e<2304; e+=256){
            int i = e/48, j = e - (e/48)*48;
            at_s[i*56+j] = __float2half(ap[e]);
        }
        asm volatile("cp.async.wait_group 0;" ::: "memory");
        __syncthreads();

        int n0 = wid*16;
        float acc[3][2][4];
        #pragma unroll
        for (int mi=0;mi<3;mi++)
            #pragma unroll
            for (int ni=0;ni<2;ni++)
                #pragma unroll
                for (int r=0;r<4;r++) acc[mi][ni][r]=0.f;

        #pragma unroll
        for (int kst=0; kst<3; kst++){
            uint32_t Af[3][4], Bf[2][2];
            #pragma unroll
            for (int mi=0; mi<3; mi++)
                ldm_x4(Af[mi], sb + WS_AT + ((mi*16 + (lane&15))*56 + kst*16 + (lane>>4)*8)*2);
            #pragma unroll
            for (int ni=0; ni<2; ni++)
                ldm_x2t(Bf[ni], sb + WS_V + (kst*16 + (lane&15))*272 + (n0 + ni*8)*2);
            #pragma unroll
            for (int mi=0; mi<3; mi++)
                #pragma unroll
                for (int ni=0; ni<2; ni++)
                    mma16816f(acc[mi][ni], Af[mi][0],Af[mi][1],Af[mi][2],Af[mi][3],
                              Bf[ni][0],Bf[ni][1]);
        }

        const __half* gs = (const __half*)(smem + WS_G);
        #pragma unroll
        for (int mi=0; mi<3; mi++){
            #pragma unroll
            for (int ni=0; ni<2; ni++){
                int r0 = mi*16 + gi;
                int cc = n0 + ni*8 + li4*2;
                float2 g0 = __half22float2(*(const __half2*)&gs[r0*136 + cc]);
                *(__half2*)&of_s[(h*HD + r0)*136 + cc] =
                    __floats2half2_rn(acc[mi][ni][0]*sigmoidf_(g0.x),
                                      acc[mi][ni][1]*sigmoidf_(g0.y));
                float2 g1 = __half22float2(*(const __half2*)&gs[(r0+8)*136 + cc]);
                *(__half2*)&of_s[(h*HD + r0+8)*136 + cc] =
                    __floats2half2_rn(acc[mi][ni][2]*sigmoidf_(g1.x),
                                      acc[mi][ni][3]*sigmoidf_(g1.y));
            }
        }
        __syncthreads();
    }

    // ---------- phase 2: proj GEMM, B = of panel in smem ----------
    int wr = wid>>2, wc = wid&3;
    {
        for (int e=tid; e<1536; e+=256){
            int r = e/24, ch = e - (e/24)*24;
            CP16(sb + r*400 + ch*16, (const char*)(wp + (size_t)r*GK) + ch*16);
        }
        asm volatile("cp.async.commit_group;" ::: "memory");
    }
    uint32_t aBase = sb + ((wr*32 + (lane&15))*400) + (lane>>4)*16;
    uint32_t bA    = sb + S_OF + (lane&15)*272 + wc*64;

    for (int ot=0; ot<3; ot++){
        if (ot+1 < 3){
            int bm1 = (ot+1)*64;
            uint32_t dstb = sb + ((ot+1)&1)*A6SZ;
            for (int e=tid; e<1536; e+=256){
                int r = e/24, ch = e - (e/24)*24;
                CP16(dstb + r*400 + ch*16, (const char*)(wp + (size_t)(bm1+r)*GK) + ch*16);
            }
            asm volatile("cp.async.commit_group;" ::: "memory");
            asm volatile("cp.async.wait_group 1;" ::: "memory");
        } else {
            asm volatile("cp.async.wait_group 0;" ::: "memory");
        }
        __syncthreads();

        uint32_t aA = aBase + (ot&1)*A6SZ;
        float acc[2][4][4];
        #pragma unroll
        for (int i=0;i<2;i++)
            #pragma unroll
            for (int j=0;j<4;j++)
                #pragma unroll
                for (int r=0;r<4;r++) acc[i][j][r]=0.f;

        #pragma unroll
        for (int ks=0; ks<12; ks++){
            uint32_t Af[2][4], Bf[4][2];
            #pragma unroll
            for (int mi=0; mi<2; mi++) ldm_x4(Af[mi], aA + mi*6400 + ks*32);
            #pragma unroll
            for (int ni=0; ni<4; ni++) ldm_x2t(Bf[ni], bA + ks*4352 + ni*16);
            #pragma unroll
            for (int mi=0; mi<2; mi++)
                #pragma unroll
                for (int ni=0; ni<4; ni++)
                    mma16816f(acc[mi][ni], Af[mi][0],Af[mi][1],Af[mi][2],Af[mi][3],
                              Bf[ni][0],Bf[ni][1]);
        }

        int bm = ot*64;
        float* O = outg + (size_t)b*C*NPIX + p0;
        #pragma unroll
        for (int ni=0; ni<4; ni++){
            int n = wc*32 + ni*8 + li4*2;
            #pragma unroll
            for (int mi=0; mi<2; mi++){
                int m0 = bm + wr*32 + mi*16 + gi;
                *(float2*)(O + (size_t)m0*NPIX + n) =
                    make_float2(acc[mi][ni][0], acc[mi][ni][1]);
                *(float2*)(O + (size_t)(m0+8)*NPIX + n) =
                    make_float2(acc[mi][ni][2], acc[mi][ni][3]);
            }
        }
        __syncthreads();
    }
}

// ---------------- host ----------------
extern "C" void kernel_launch(void* const* d_in, const int* in_sizes, int n_in,
                              void* d_out, int out_size){
    const float* x      = (const float*)d_in[0];
    const float* w_fc1  = (const float*)d_in[1];
    const float* w_fc2  = (const float*)d_in[2];
    const float* w_sp   = (const float*)d_in[3];
    const float* w_qkv  = (const float*)d_in[4];
    const float* w_dw   = (const float*)d_in[5];
    const float* w_proj = (const float*)d_in[6];
    const float* temp   = (const float*)d_in[7];
    float* out = (float*)d_out;

    __half *wq, *wp, *qkv;
    float *sg;
    cudaGetSymbolAddress((void**)&wq,  g_wq);
    cudaGetSymbolAddress((void**)&wp,  g_wp);
    cudaGetSymbolAddress((void**)&qkv, g_qkv);
    cudaGetSymbolAddress((void**)&sg,  g_sg);

    cudaFuncSetAttribute(k_hmma6,  cudaFuncAttributeMaxDynamicSharedMemorySize, SMEM6);
    cudaFuncSetAttribute(k_avproj, cudaFuncAttributeMaxDynamicSharedMemorySize, SMEMP);

    k_stats        <<<dim3(NTILE, NB), 256>>>(x);
    k_chan_gate    <<<NB, 192>>>(w_fc1, w_fc2);
    k_spatial_conv <<<NB*NPIX/256, 256>>>(w_sp);

    k_wcvt<<<(NB*C4*GK/4)/256, 256>>>(w_qkv, wq);
    k_pcvt<<<(C*GK/4 + 255)/256, 256>>>(w_proj, wp);

    // qkv = sg(p) * ((w_qkv*cg) @ x): fp32-B converted at staging, half out
    k_hmma6<<<NB*(NPIX/128), 256, SMEM6>>>(
        wq, (long)C4*GK, x, qkv, (long)C4*NPIX, sg, C4, 12);

    k_dw2<<<NB*C4, 256>>>(w_dw);     // dw + inverse norms

    k_attn_mma<<<dim3(NB*HEADS, ASEG), 256>>>();
    k_softmax  <<<NB*HEADS*HD, 64>>>(temp);

    // fused (attn@v)*sigmoid(gate) + final projection -> d_out
    k_avproj<<<dim3(NPIX/128, NB), 256, SMEMP>>>(wp, out);
}